// round 7
// baseline (speedup 1.0000x reference)
#include <cuda_runtime.h>
#include <cuda_bf16.h>
#include <math.h>
#include <limits.h>
#include <stdint.h>

// ---------------- problem constants ----------------
#define BB 256
#define NN 300
#define IN_DIM 1280
#define DIM 256
#define HEADS 4
#define DH 64
#define MF 266            // NB_FEAT
#define MP 320            // padded feature dim (logical)
#define MPP 384           // feature dim padded to 128-multiple (B-operand rows)
#define NP 320            // padded sequence dim per head
#define FFH 1024
#define ROWS_TOT (BB*NN)  // 76800
#define RH (ROWS_TOT*HEADS) // 307200
#define BH (BB*HEADS)       // 1024
#define RPB (NN*HEADS)      // rows per batch in dd view = 1200

#define LN_EPS 1e-5f
#define KEPS 1e-4f
#define RATIO 0.061314066f
#define NORM 0.35355339059327373f

// ---------------- scratch ----------------
__device__ float          g_h   [ROWS_TOT*DIM];
__device__ __nv_bfloat16  g_yb  [ROWS_TOT*DIM];
__device__ __nv_bfloat16  g_qb  [ROWS_TOT*DIM];
__device__ __nv_bfloat16  g_kb  [ROWS_TOT*DIM];
__device__ __nv_bfloat16  g_vb  [ROWS_TOT*DIM];
__device__ __nv_bfloat16  g_ob  [ROWS_TOT*DIM];
__device__ __nv_bfloat16  g_ffhb[ROWS_TOT*FFH];
__device__ __nv_bfloat16  g_xb  [ROWS_TOT*IN_DIM];
__device__ float          g_ddq [(size_t)RH*MP];
__device__ float          g_ddk [(size_t)RH*MP];
__device__ __nv_bfloat16  g_qpB [(size_t)BH*NN*MP];
__device__ __nv_bfloat16  g_kpT [(size_t)BH*MPP*NP];
__device__ __nv_bfloat16  g_vT  [(size_t)BH*128*NP];
__device__ __nv_bfloat16  g_ctxT[(size_t)BH*128*MP];
__device__ float          g_outA[(size_t)BH*NN*128];
__device__ int            g_kmax[BH];
__device__ float          g_pool[BB*DIM];
__device__ float          g_z   [BB*DIM];
__device__ float          g_z1  [BB*128];
__device__ __nv_bfloat16  g_pTb [MPP*64];
__device__ __nv_bfloat16  g_wInT[DIM*IN_DIM];
__device__ __nv_bfloat16  g_wqkvT[2][3*DIM*DIM];
__device__ __nv_bfloat16  g_woT [2][DIM*DIM];
__device__ __nv_bfloat16  g_w1T [2][FFH*DIM];
__device__ __nv_bfloat16  g_w2T [2][DIM*FFH];

// ---------------- helpers ----------------
__device__ __forceinline__ int f2o(float f) {
    int i = __float_as_int(f);
    return i >= 0 ? i : (i ^ 0x7FFFFFFF);
}
__device__ __forceinline__ float o2f(int i) {
    return __int_as_float(i >= 0 ? i : (i ^ 0x7FFFFFFF));
}
__device__ __forceinline__ float tanh_fast(float a) {
    float t = __expf(-2.0f * fabsf(a));
    float r = (1.0f - t) / (1.0f + t);
    return copysignf(r, a);
}
__device__ __forceinline__ float gelu_tanh(float x) {
    float x3 = x * x * x;
    return 0.5f * x * (1.0f + tanh_fast(0.7978845608028654f * (x + 0.044715f * x3)));
}
__device__ __forceinline__ float blockReduceSum256(float v) {
    __shared__ float sh[8];
    __syncthreads();
    int lane = threadIdx.x & 31, w = threadIdx.x >> 5;
    #pragma unroll
    for (int o = 16; o; o >>= 1) v += __shfl_xor_sync(0xFFFFFFFFu, v, o);
    if (lane == 0) sh[w] = v;
    __syncthreads();
    if (threadIdx.x == 0) {
        float s = 0.f;
        #pragma unroll
        for (int i = 0; i < 8; i++) s += sh[i];
        sh[0] = s;
    }
    __syncthreads();
    return sh[0];
}
__device__ __forceinline__ uint32_t smem_u32(const void* p) {
    uint32_t a;
    asm("{ .reg .u64 t; cvta.to.shared.u64 t, %1; cvt.u32.u64 %0, t; }" : "=r"(a) : "l"(p));
    return a;
}

#define SWZ(off) ((off) ^ (((off) >> 3) & 0x70))

__device__ __forceinline__ void ldmatrix4(uint32_t* r, uint32_t addr) {
    asm volatile("ldmatrix.sync.aligned.m8n8.x4.shared.b16 {%0,%1,%2,%3}, [%4];"
        : "=r"(r[0]), "=r"(r[1]), "=r"(r[2]), "=r"(r[3]) : "r"(addr));
}
__device__ __forceinline__ void mma16816(float* c, const uint32_t* a, uint32_t b0, uint32_t b1) {
    asm volatile(
        "mma.sync.aligned.m16n8k16.row.col.f32.bf16.bf16.f32 "
        "{%0,%1,%2,%3}, {%4,%5,%6,%7}, {%8,%9}, {%0,%1,%2,%3};"
        : "+f"(c[0]), "+f"(c[1]), "+f"(c[2]), "+f"(c[3])
        : "r"(a[0]), "r"(a[1]), "r"(a[2]), "r"(a[3]), "r"(b0), "r"(b1));
}
__device__ __forceinline__ void cp_async16(uint32_t smem, const void* g) {
    asm volatile("cp.async.cg.shared.global [%0], [%1], 16;" :: "r"(smem), "l"(g));
}
__device__ __forceinline__ void cp_commit() {
    asm volatile("cp.async.commit_group;" ::: "memory");
}
__device__ __forceinline__ void cp_wait2() {
    asm volatile("cp.async.wait_group 2;" ::: "memory");
}

// 128x128 tile: A stage 16KB + B stage 16KB = 32KB; 3 stages = 96KB
#define TG_STAGE 32768
#define TG_SMEM_BYTES (3*TG_STAGE)

// ---------------- bf16 HMMA GEMM (128x128 tile, 3-stage pipeline) ----------------
// C = act(A[M,K] @ Bt[.,K]^T + bias) (+res). M%128==0, K%64==0.
// ldc = N (row stride); stores guarded by cidx < Nvalid.
// Bt must be readable for rows [0, gridDim.x*128).
// QKV split: if Cb2 != null, bf16 stores route by cidx>>8 into {Cb, Cb2, Cb3}, ld 256.
__global__ void __launch_bounds__(256) tgemm_kernel(
    const __nv_bfloat16* __restrict__ A, const __nv_bfloat16* __restrict__ Bt,
    const float* __restrict__ bias, const float* __restrict__ res,
    float* __restrict__ Cf, __nv_bfloat16* __restrict__ Cb,
    __nv_bfloat16* __restrict__ Cb2, __nv_bfloat16* __restrict__ Cb3,
    int M, int N, int Nvalid, int K, int act, int* __restrict__ kmaxOut)
{
    extern __shared__ __nv_bfloat16 sm[];
    const uint32_t base = smem_u32(sm);
    __shared__ int smax[8];

    const int tid = threadIdx.x;
    const int wid = tid >> 5, lane = tid & 31;
    const int wm = wid & 3, wn = wid >> 2;          // 4 (M) x 2 (N) warps
    const int row0 = blockIdx.y * 128, col0 = blockIdx.x * 128;
    const int tileid = lane >> 3, rit = lane & 7;
    const int gid = lane >> 2, tig = lane & 3;

    if (kmaxOut && tid < 8) smax[tid] = INT_MIN;

    float acc[2][8][4];
    #pragma unroll
    for (int mt = 0; mt < 2; mt++)
        #pragma unroll
        for (int j = 0; j < 8; j++)
            #pragma unroll
            for (int r = 0; r < 4; r++) acc[mt][j][r] = 0.f;

    const int nch = K >> 6;
    const __nv_bfloat16* Arow = A + (size_t)row0 * K;
    const __nv_bfloat16* Brow = Bt + (size_t)col0 * K;

    #pragma unroll
    for (int s = 0; s < 3; s++) {
        if (s < nch) {
            const int k0 = s << 6;
            const uint32_t aS = base + s * TG_STAGE;
            const uint32_t bS = aS + 16384;
            #pragma unroll
            for (int i = 0; i < 4; i++) {
                int lin = tid + i * 256;
                int r = lin >> 3, c8 = lin & 7;
                cp_async16(aS + SWZ(r * 128 + c8 * 16), Arow + (size_t)r * K + k0 + c8 * 8);
            }
            #pragma unroll
            for (int i = 0; i < 4; i++) {
                int lin = tid + i * 256;
                int r = lin >> 3, c8 = lin & 7;
                cp_async16(bS + SWZ(r * 128 + c8 * 16), Brow + (size_t)r * K + k0 + c8 * 8);
            }
        }
        cp_commit();
    }

    int stg = 0;
    for (int c = 0; c < nch; c++) {
        cp_wait2();
        __syncthreads();
        const uint32_t aB = base + stg * TG_STAGE;
        const uint32_t bB = aB + 16384;
        #pragma unroll
        for (int kk = 0; kk < 4; kk++) {
            uint32_t af[2][4];
            #pragma unroll
            for (int mt = 0; mt < 2; mt++) {
                int off = (wm * 32 + mt * 16 + (tileid & 1) * 8 + rit) * 128
                          + kk * 32 + (tileid >> 1) * 16;
                ldmatrix4(af[mt], aB + SWZ(off));
            }
            uint32_t bf[4][4];
            #pragma unroll
            for (int nt = 0; nt < 4; nt++) {
                int off = (wn * 64 + nt * 16 + (tileid & 1) * 8 + rit) * 128
                          + kk * 32 + (tileid >> 1) * 16;
                ldmatrix4(bf[nt], bB + SWZ(off));
            }
            #pragma unroll
            for (int mt = 0; mt < 2; mt++)
                #pragma unroll
                for (int j = 0; j < 8; j++) {
                    int nt = j >> 1, sel = j & 1;
                    mma16816(acc[mt][j], af[mt], bf[nt][sel], bf[nt][2 + sel]);
                }
        }
        __syncthreads();
        if (c + 3 < nch) {
            const int k0 = (c + 3) << 6;
            const uint32_t aS = base + stg * TG_STAGE;
            const uint32_t bS = aS + 16384;
            #pragma unroll
            for (int i = 0; i < 4; i++) {
                int lin = tid + i * 256;
                int r = lin >> 3, c8 = lin & 7;
                cp_async16(aS + SWZ(r * 128 + c8 * 16), Arow + (size_t)r * K + k0 + c8 * 8);
            }
            #pragma unroll
            for (int i = 0; i < 4; i++) {
                int lin = tid + i * 256;
                int r = lin >> 3, c8 = lin & 7;
                cp_async16(bS + SWZ(r * 128 + c8 * 16), Brow + (size_t)r * K + k0 + c8 * 8);
            }
        }
        cp_commit();
        stg = (stg + 1) == 3 ? 0 : stg + 1;
    }

    // epilogue
    float kmv[2] = {-1e30f, -1e30f};
    const int b0 = row0 / RPB;
    #pragma unroll
    for (int mt = 0; mt < 2; mt++) {
        #pragma unroll
        for (int j = 0; j < 8; j++) {
            #pragma unroll
            for (int half = 0; half < 2; half++) {
                int r = row0 + wm * 32 + mt * 16 + gid + half * 8;
                int cidx = col0 + wn * 64 + j * 8 + tig * 2;
                if (cidx >= Nvalid) continue;
                float v0 = acc[mt][j][half * 2 + 0];
                float v1 = acc[mt][j][half * 2 + 1];
                if (kmaxOut) {
                    int bs = (r / RPB == b0) ? 0 : 1;
                    float m = -1e30f;
                    if (cidx < MF) m = v0;
                    if (cidx + 1 < MF) m = fmaxf(m, v1);
                    kmv[bs] = fmaxf(kmv[bs], m);
                }
                if (bias) { v0 += bias[cidx]; v1 += bias[cidx + 1]; }
                if (act == 1) { v0 = gelu_tanh(v0); v1 = gelu_tanh(v1); }
                if (res) {
                    float2 r2 = *(const float2*)(res + (size_t)r * N + cidx);
                    v0 += r2.x; v1 += r2.y;
                }
                if (Cf) *(float2*)(Cf + (size_t)r * N + cidx) = make_float2(v0, v1);
                if (Cb2) {
                    int sel = cidx >> 8;
                    __nv_bfloat16* p = sel == 0 ? Cb : (sel == 1 ? Cb2 : Cb3);
                    *(__nv_bfloat162*)(p + (size_t)r * 256 + (cidx & 255)) = __floats2bfloat162_rn(v0, v1);
                } else if (Cb) {
                    *(__nv_bfloat162*)(Cb + (size_t)r * N + cidx) = __floats2bfloat162_rn(v0, v1);
                }
            }
        }
    }
    if (kmaxOut) {
        int h = gid & 3;
        if (kmv[0] > -1e29f) atomicMax(&smax[h], f2o(kmv[0]));
        if (kmv[1] > -1e29f) atomicMax(&smax[4 + h], f2o(kmv[1]));
        __syncthreads();
        if (tid < 8) {
            int bsel = tid >> 2, hh = tid & 3;
            int bb = b0 + bsel;
            if (smax[tid] != INT_MIN && bb < BB)
                atomicMax(&kmaxOut[bb * HEADS + hh], smax[tid]);
        }
    }
}

// ---------------- batched bf16 HMMA GEMM (128x128 tile) ----------------
__global__ void __launch_bounds__(256) btgemm_kernel(
    const __nv_bfloat16* __restrict__ A, size_t aBS, int aClamp,
    const __nv_bfloat16* __restrict__ Bt, size_t bBS,
    float* __restrict__ Cf, __nv_bfloat16* __restrict__ Cb, size_t cBS,
    int ldc, int Nvalid, int K, int mValid)
{
    extern __shared__ __nv_bfloat16 sm[];
    const uint32_t base = smem_u32(sm);

    const int tid = threadIdx.x;
    const int wid = tid >> 5, lane = tid & 31;
    const int wm = wid & 3, wn = wid >> 2;
    const int row0 = blockIdx.y * 128, col0 = blockIdx.x * 128;
    const int tileid = lane >> 3, rit = lane & 7;
    const int gid = lane >> 2, tig = lane & 3;
    const int bh = blockIdx.z;

    const __nv_bfloat16* Ab = A + (size_t)bh * aBS;
    const __nv_bfloat16* Bb = Bt + (size_t)bh * bBS + (size_t)col0 * K;

    float acc[2][8][4];
    #pragma unroll
    for (int mt = 0; mt < 2; mt++)
        #pragma unroll
        for (int j = 0; j < 8; j++)
            #pragma unroll
            for (int r = 0; r < 4; r++) acc[mt][j][r] = 0.f;

    const int nch = K >> 6;
    #pragma unroll
    for (int s = 0; s < 3; s++) {
        if (s < nch) {
            const int k0 = s << 6;
            const uint32_t aS = base + s * TG_STAGE;
            const uint32_t bS = aS + 16384;
            #pragma unroll
            for (int i = 0; i < 4; i++) {
                int lin = tid + i * 256;
                int r = lin >> 3, c8 = lin & 7;
                int rg = min(row0 + r, aClamp);
                cp_async16(aS + SWZ(r * 128 + c8 * 16), Ab + (size_t)rg * K + k0 + c8 * 8);
            }
            #pragma unroll
            for (int i = 0; i < 4; i++) {
                int lin = tid + i * 256;
                int r = lin >> 3, c8 = lin & 7;
                cp_async16(bS + SWZ(r * 128 + c8 * 16), Bb + (size_t)r * K + k0 + c8 * 8);
            }
        }
        cp_commit();
    }

    int stg = 0;
    for (int c = 0; c < nch; c++) {
        cp_wait2();
        __syncthreads();
        const uint32_t aB = base + stg * TG_STAGE;
        const uint32_t bB = aB + 16384;
        #pragma unroll
        for (int kk = 0; kk < 4; kk++) {
            uint32_t af[2][4];
            #pragma unroll
            for (int mt = 0; mt < 2; mt++) {
                int off = (wm * 32 + mt * 16 + (tileid & 1) * 8 + rit) * 128
                          + kk * 32 + (tileid >> 1) * 16;
                ldmatrix4(af[mt], aB + SWZ(off));
            }
            uint32_t bf[4][4];
            #pragma unroll
            for (int nt = 0; nt < 4; nt++) {
                int off = (wn * 64 + nt * 16 + (tileid & 1) * 8 + rit) * 128
                          + kk * 32 + (tileid >> 1) * 16;
                ldmatrix4(bf[nt], bB + SWZ(off));
            }
            #pragma unroll
            for (int mt = 0; mt < 2; mt++)
                #pragma unroll
                for (int j = 0; j < 8; j++) {
                    int nt = j >> 1, sel = j & 1;
                    mma16816(acc[mt][j], af[mt], bf[nt][sel], bf[nt][2 + sel]);
                }
        }
        __syncthreads();
        if (c + 3 < nch) {
            const int k0 = (c + 3) << 6;
            const uint32_t aS = base + stg * TG_STAGE;
            const uint32_t bS = aS + 16384;
            #pragma unroll
            for (int i = 0; i < 4; i++) {
                int lin = tid + i * 256;
                int r = lin >> 3, c8 = lin & 7;
                int rg = min(row0 + r, aClamp);
                cp_async16(aS + SWZ(r * 128 + c8 * 16), Ab + (size_t)rg * K + k0 + c8 * 8);
            }
            #pragma unroll
            for (int i = 0; i < 4; i++) {
                int lin = tid + i * 256;
                int r = lin >> 3, c8 = lin & 7;
                cp_async16(bS + SWZ(r * 128 + c8 * 16), Bb + (size_t)r * K + k0 + c8 * 8);
            }
        }
        cp_commit();
        stg = (stg + 1) == 3 ? 0 : stg + 1;
    }

    float* Cfb = Cf ? Cf + (size_t)bh * cBS : nullptr;
    __nv_bfloat16* Cbb = Cb ? Cb + (size_t)bh * cBS : nullptr;
    #pragma unroll
    for (int mt = 0; mt < 2; mt++) {
        #pragma unroll
        for (int j = 0; j < 8; j++) {
            #pragma unroll
            for (int half = 0; half < 2; half++) {
                int r = row0 + wm * 32 + mt * 16 + gid + half * 8;
                if (r >= mValid) continue;
                int cidx = col0 + wn * 64 + j * 8 + tig * 2;
                if (cidx >= Nvalid) continue;
                float v0 = acc[mt][j][half * 2 + 0];
                float v1 = acc[mt][j][half * 2 + 1];
                if (Cfb) *(float2*)(Cfb + (size_t)r * ldc + cidx) = make_float2(v0, v1);
                if (Cbb) *(__nv_bfloat162*)(Cbb + (size_t)r * ldc + cidx) = __floats2bfloat162_rn(v0, v1);
            }
        }
    }
}

// ---------------- prep kernels ----------------
__global__ void f2b_kernel(const float* __restrict__ a, __nv_bfloat16* __restrict__ b, size_t n) {
    size_t i = (size_t)blockIdx.x * blockDim.x + threadIdx.x;
    if (i < n) b[i] = __float2bfloat16(a[i]);
}

__global__ void wtrans_kernel(const float* __restrict__ W, __nv_bfloat16* __restrict__ Wt,
                              int K, int N) {
    __shared__ float t[32][33];
    int k0 = blockIdx.y * 32, n0 = blockIdx.x * 32;
    int tx = threadIdx.x, ty = threadIdx.y;
    #pragma unroll
    for (int i = 0; i < 32; i += 8)
        t[ty + i][tx] = W[(size_t)(k0 + ty + i) * N + n0 + tx];
    __syncthreads();
    #pragma unroll
    for (int i = 0; i < 32; i += 8)
        Wt[(size_t)(n0 + ty + i) * K + k0 + tx] = __float2bfloat16(t[tx][ty + i]);
}

__global__ void projb_kernel(const float* __restrict__ proj, __nv_bfloat16* __restrict__ pTb) {
    int i = blockIdx.x * 256 + threadIdx.x;
    if (i >= MPP * 64) return;
    int m = i >> 6, d = i & 63;
    pTb[i] = __float2bfloat16((m < MF) ? proj[m * 64 + d] * NORM : 0.f);
}

// ---------------- layernorm ----------------
__global__ void ln_bf16_kernel(const float* __restrict__ x, const float* __restrict__ g,
                               const float* __restrict__ b, __nv_bfloat16* __restrict__ y)
{
    int row = blockIdx.x;
    int t = threadIdx.x;
    float v = x[(size_t)row * DIM + t];
    float mu = blockReduceSum256(v) * (1.0f / DIM);
    float d = v - mu;
    float var = blockReduceSum256(d * d) * (1.0f / DIM);
    y[(size_t)row * DIM + t] = __float2bfloat16(d * rsqrtf(var + LN_EPS) * g[t] + b[t]);
}

__global__ void ln_f32_kernel(const float* __restrict__ x, const float* __restrict__ g,
                              const float* __restrict__ b, float* __restrict__ y)
{
    int row = blockIdx.x;
    int t = threadIdx.x;
    float v = x[(size_t)row * DIM + t];
    float mu = blockReduceSum256(v) * (1.0f / DIM);
    float d = v - mu;
    float var = blockReduceSum256(d * d) * (1.0f / DIM);
    y[(size_t)row * DIM + t] = d * rsqrtf(var + LN_EPS) * g[t] + b[t];
}

// ---------------- FAVOR+ passes ----------------
__global__ void qexp_kernel(const __nv_bfloat16* __restrict__ qbuf, const float* __restrict__ dd,
                            __nv_bfloat16* __restrict__ qpB)
{
    int w = (blockIdx.x * 256 + threadIdx.x) >> 5;
    int lane = threadIdx.x & 31;
    if (w >= RH) return;
    const __nv_bfloat16* qr = qbuf + (size_t)w * 64;
    float a = __bfloat162float(qr[lane]), b2 = __bfloat162float(qr[lane + 32]);
    float s = a * a + b2 * b2;
    #pragma unroll
    for (int o = 16; o; o >>= 1) s += __shfl_xor_sync(0xFFFFFFFFu, s, o);
    float diag = 0.0625f * s;
    const float* row = dd + (size_t)w * MP;
    float vv[9], mx = -1e30f;
    #pragma unroll
    for (int i = 0; i < 9; i++) {
        int m = lane + 32 * i;
        vv[i] = (m < MF) ? row[m] : -1e30f;
        mx = fmaxf(mx, vv[i]);
    }
    #pragma unroll
    for (int o = 16; o; o >>= 1) mx = fmaxf(mx, __shfl_xor_sync(0xFFFFFFFFu, mx, o));

    int b = w / RPB;
    int rem = w - b * RPB;
    int n = rem >> 2, h = rem & 3;
    __nv_bfloat16* orow = qpB + ((size_t)(b * HEADS + h) * NN + n) * MP;
    #pragma unroll
    for (int i = 0; i < 9; i++) {
        int m = lane + 32 * i;
        if (m < MF) orow[m] = __float2bfloat16(RATIO * (__expf(vv[i] - diag - mx) + KEPS));
        else orow[m] = __float2bfloat16(0.f);
    }
    orow[lane + 288] = __float2bfloat16(0.f);
}

__global__ void kmax_init_kernel(int* __restrict__ kmax) {
    int i = blockIdx.x * blockDim.x + threadIdx.x;
    if (i < BH) kmax[i] = INT_MIN;
}

// kexp + transpose: kpT rows padded to MPP
__global__ void __launch_bounds__(256) kexpT_kernel(
    const __nv_bfloat16* __restrict__ kbuf, const float* __restrict__ dd,
    const int* __restrict__ kmax, __nv_bfloat16* __restrict__ kpT)
{
    __shared__ float s[32][325];
    __shared__ float diag[32];
    int bh = blockIdx.x, b = bh >> 2, h = bh & 3;
    int n0 = blockIdx.y * 32;
    int tid = threadIdx.x;
    int wid = tid >> 5, lane = tid & 31;

    #pragma unroll
    for (int ii = 0; ii < 4; ii++) {
        int n_l = wid * 4 + ii;
        int n_g = n0 + n_l;
        float sum = 0.f;
        if (n_g < NN) {
            const __nv_bfloat16* kr = kbuf + ((size_t)(b * NN + n_g)) * DIM + h * 64;
            float a = __bfloat162float(kr[lane]), b2 = __bfloat162float(kr[lane + 32]);
            sum = a * a + b2 * b2;
        }
        #pragma unroll
        for (int o = 16; o; o >>= 1) sum += __shfl_xor_sync(0xFFFFFFFFu, sum, o);
        if (lane == 0) diag[n_l] = 0.0625f * sum;
    }

    #pragma unroll
    for (int it = 0; it < 4; it++) {
        int n_l = (tid >> 5) + 8 * it;
        int n_g = n0 + n_l;
        const float* row = dd + ((size_t)((b * NN + min(n_g, NN - 1)) * HEADS) + h) * MP;
        bool ok = n_g < NN;
        #pragma unroll
        for (int j = 0; j < 10; j++) {
            int m = lane + 32 * j;
            s[n_l][m] = ok ? row[m] : 0.f;
        }
    }
    __syncthreads();

    float stab = o2f(kmax[bh]);
    int n_g = n0 + lane;
    bool nok = n_g < NN;
    float dg = diag[lane];
    __nv_bfloat16* base = kpT + (size_t)bh * MPP * NP + n0 + lane;
    for (int m = wid; m < MPP; m += 8) {
        float val = 0.f;
        if (m < MF && nok)
            val = RATIO * (__expf(s[lane][m] - dg - stab) + KEPS);
        base[(size_t)m * NP] = __float2bfloat16(val);
    }
}

// v transpose (bf16 in): vAugT[bh][d][n], d=64 row = ones
__global__ void __launch_bounds__(256) vtrans_kernel(
    const __nv_bfloat16* __restrict__ v, __nv_bfloat16* __restrict__ vT)
{
    __shared__ float t[32][65];
    int bh = blockIdx.x, b = bh >> 2, h = bh & 3;
    int tid = threadIdx.x;
    int lane = tid & 31;
    __nv_bfloat16* vb = vT + (size_t)bh * 128 * NP;

    for (int it = 0; it < 10; it++) {
        int n0 = it * 32;
        int d = tid & 63;
        #pragma unroll
        for (int sub = 0; sub < 8; sub++) {
            int n_l = (tid >> 6) + 4 * sub;
            int n_g = n0 + n_l;
            t[n_l][d] = (n_g < NN) ?
                __bfloat162float(v[((size_t)(b * NN + n_g)) * DIM + h * 64 + d]) : 0.f;
        }
        __syncthreads();
        int dcol = tid >> 5;
        #pragma unroll
        for (int j = 0; j < 8; j++) {
            int d2 = dcol + 8 * j;
            vb[(size_t)d2 * NP + n0 + lane] = __float2bfloat16(t[lane][d2]);
        }
        __syncthreads();
    }
    for (int idx = tid; idx < 64 * NP; idx += 256) {
        int d = 64 + idx / NP, n = idx % NP;
        float val = (d == 64 && n < NN) ? 1.f : 0.f;
        vb[(size_t)d * NP + n] = __float2bfloat16(val);
    }
}

__global__ void divout_kernel(const float* __restrict__ outA, __nv_bfloat16* __restrict__ ob)
{
    int bh = blockIdx.x, b = bh >> 2, h = bh & 3;
    const float* base = outA + (size_t)bh * NN * 128;
    for (int idx = threadIdx.x; idx < NN * 64; idx += 256) {
        int n = idx >> 6, d = idx & 63;
        float num = base[(size_t)n * 128 + d];
        float den = base[(size_t)n * 128 + 64];
        ob[((size_t)(b * NN + n)) * DIM + h * 64 + d] = __float2bfloat16(num / den);
    }
}

// ---------------- pooling & head ----------------
__global__ void pool_kernel(const float* __restrict__ h, float* __restrict__ pooled)
{
    int b = blockIdx.x, c = threadIdx.x;
    const float* p = h + (size_t)b * NN * DIM + c;
    float s0 = 0.f, s1 = 0.f, s2 = 0.f, s3 = 0.f;
    for (int n = 0; n < NN; n += 4) {
        s0 += p[(size_t)(n + 0) * DIM];
        s1 += p[(size_t)(n + 1) * DIM];
        s2 += p[(size_t)(n + 2) * DIM];
        s3 += p[(size_t)(n + 3) * DIM];
    }
    pooled[b * DIM + c] = ((s0 + s1) + (s2 + s3)) * (1.0f / NN);
}

__global__ void head1_kernel(const float* __restrict__ z, const float* __restrict__ w,
                             const float* __restrict__ bias, float* __restrict__ z1)
{
    __shared__ float zs[DIM];
    int b = blockIdx.x, j = threadIdx.x;
    for (int c = j; c < DIM; c += 128) zs[c] = z[b * DIM + c];
    __syncthreads();
    float s0 = 0.f, s1 = 0.f, s2 = 0.f, s3 = 0.f;
    #pragma unroll 1
    for (int c = 0; c < DIM; c += 4) {
        s0 = fmaf(zs[c + 0], w[(c + 0) * 128 + j], s0);
        s1 = fmaf(zs[c + 1], w[(c + 1) * 128 + j], s1);
        s2 = fmaf(zs[c + 2], w[(c + 2) * 128 + j], s2);
        s3 = fmaf(zs[c + 3], w[(c + 3) * 128 + j], s3);
    }
    z1[b * 128 + j] = fmaxf(((s0 + s1) + (s2 + s3)) + bias[j], 0.f);
}

__global__ void head2_kernel(const float* __restrict__ z1, const float* __restrict__ w,
                             const float* __restrict__ bias, float* __restrict__ out)
{
    __shared__ float sh[4];
    int b = blockIdx.x, j = threadIdx.x;
    float s = z1[b * 128 + j] * w[j];
    #pragma unroll
    for (int o = 16; o; o >>= 1) s += __shfl_xor_sync(0xFFFFFFFFu, s, o);
    if ((j & 31) == 0) sh[j >> 5] = s;
    __syncthreads();
    if (j == 0) {
        float t = sh[0] + sh[1] + sh[2] + sh[3] + bias[0];
        out[b] = 1.0f / (1.0f + __expf(-t));
    }
}

// ---------------- host ----------------
template <typename T> static T* symaddr(const void* sym) {
    void* p = nullptr;
    cudaGetSymbolAddress(&p, sym);
    return (T*)p;
}

extern "C" void kernel_launch(void* const* d_in, const int* in_sizes, int n_in,
                              void* d_out, int out_size)
{
    const float* x     = (const float*)d_in[0];
    const float* w_in  = (const float*)d_in[1];
    const float* b_in  = (const float*)d_in[2];
    const float* proj  = (const float*)d_in[3];
    const float* ln1_g = (const float*)d_in[4];
    const float* ln1_b = (const float*)d_in[5];
    const float* wq    = (const float*)d_in[6];
    const float* wk    = (const float*)d_in[7];
    const float* wv    = (const float*)d_in[8];
    const float* wo    = (const float*)d_in[9];
    const float* bo    = (const float*)d_in[10];
    const float* ln2_g = (const float*)d_in[11];
    const float* ln2_b = (const float*)d_in[12];
    const float* w1    = (const float*)d_in[13];
    const float* b1    = (const float*)d_in[14];
    const float* w2    = (const float*)d_in[15];
    const float* b2    = (const float*)d_in[16];
    const float* hln_g = (const float*)d_in[17];
    const float* hln_b = (const float*)d_in[18];
    const float* wh1   = (const float*)d_in[19];
    const float* bh1   = (const float*)d_in[20];
    const float* wh2   = (const float*)d_in[21];
    const float* bh2   = (const float*)d_in[22];
    float* out = (float*)d_out;

    float* h    = symaddr<float>(g_h);
    __nv_bfloat16* yb   = symaddr<__nv_bfloat16>(g_yb);
    __nv_bfloat16* qb   = symaddr<__nv_bfloat16>(g_qb);
    __nv_bfloat16* kb   = symaddr<__nv_bfloat16>(g_kb);
    __nv_bfloat16* vb   = symaddr<__nv_bfloat16>(g_vb);
    __nv_bfloat16* ob   = symaddr<__nv_bfloat16>(g_ob);
    __nv_bfloat16* ffhb = symaddr<__nv_bfloat16>(g_ffhb);
    __nv_bfloat16* xb   = symaddr<__nv_bfloat16>(g_xb);
    float* ddq  = symaddr<float>(g_ddq);
    float* ddk  = symaddr<float>(g_ddk);
    __nv_bfloat16* qpB  = symaddr<__nv_bfloat16>(g_qpB);
    __nv_bfloat16* kpT  = symaddr<__nv_bfloat16>(g_kpT);
    __nv_bfloat16* vT   = symaddr<__nv_bfloat16>(g_vT);
    __nv_bfloat16* ctxT = symaddr<__nv_bfloat16>(g_ctxT);
    float* outA = symaddr<float>(g_outA);
    int*   kmx  = symaddr<int>(g_kmax);
    float* pool = symaddr<float>(g_pool);
    float* z    = symaddr<float>(g_z);
    float* z1   = symaddr<float>(g_z1);
    __nv_bfloat16* pTb  = symaddr<__nv_bfloat16>(g_pTb);
    __nv_bfloat16* wInT = symaddr<__nv_bfloat16>(g_wInT);
    __nv_bfloat16* wqkvT = symaddr<__nv_bfloat16>(g_wqkvT);
    __nv_bfloat16* woT  = symaddr<__nv_bfloat16>(g_woT);
    __nv_bfloat16* w1T  = symaddr<__nv_bfloat16>(g_w1T);
    __nv_bfloat16* w2T  = symaddr<__nv_bfloat16>(g_w2T);

    static bool attr_set = false;
    if (!attr_set) {
        cudaFuncSetAttribute(tgemm_kernel, cudaFuncAttributeMaxDynamicSharedMemorySize, TG_SMEM_BYTES);
        cudaFuncSetAttribute(btgemm_kernel, cudaFuncAttributeMaxDynamicSharedMemorySize, TG_SMEM_BYTES);
        attr_set = true;
    }

    dim3 blk256(256);
    dim3 t256(2, ROWS_TOT / 128);       // N=256
    dim3 t768(6, ROWS_TOT / 128);       // N=768 fused QKV
    dim3 t1024(8, ROWS_TOT / 128);      // N=1024
    dim3 tdd(3, RH / 128);              // N=320 (padded grid to 384)
    dim3 gCtx(3, 1, BH);                // ctxT: 384-col grid, Nvalid=320
    dim3 gAtt(1, 3, BH);                // attnout: N=128, M=300

    // ---- prep ----
    f2b_kernel<<<(int)((ROWS_TOT * (size_t)IN_DIM + 255) / 256), 256>>>(x, xb, (size_t)ROWS_TOT * IN_DIM);
    wtrans_kernel<<<dim3(DIM / 32, IN_DIM / 32), dim3(32, 8)>>>(w_in, wInT, IN_DIM, DIM);
    for (int l = 0; l < 2; l++) {
        __nv_bfloat16* wqkv = wqkvT + (size_t)l * 3 * DIM * DIM;
        wtrans_kernel<<<dim3(DIM / 32, DIM / 32), dim3(32, 8)>>>(wq + (size_t)l * DIM * DIM, wqkv, DIM, DIM);
        wtrans_kernel<<<dim3(DIM / 32, DIM / 32), dim3(32, 8)>>>(wk + (size_t)l * DIM * DIM, wqkv + DIM * DIM, DIM, DIM);
        wtrans_kernel<<<dim3(DIM / 32, DIM / 32), dim3(32, 8)>>>(wv + (size_t)l * DIM * DIM, wqkv + 2 * DIM * DIM, DIM, DIM);
        wtrans_kernel<<<dim3(DIM / 32, DIM / 32), dim3(32, 8)>>>(wo + (size_t)l * DIM * DIM, woT + (size_t)l * DIM * DIM, DIM, DIM);
        wtrans_kernel<<<dim3(FFH / 32, DIM / 32), dim3(32, 8)>>>(w1 + (size_t)l * DIM * FFH, w1T + (size_t)l * DIM * FFH, DIM, FFH);
        wtrans_kernel<<<dim3(DIM / 32, FFH / 32), dim3(32, 8)>>>(w2 + (size_t)l * FFH * DIM, w2T + (size_t)l * FFH * DIM, FFH, DIM);
    }

    tgemm_kernel<<<t256, blk256, TG_SMEM_BYTES>>>(xb, wInT, b_in, nullptr, h, nullptr, nullptr, nullptr,
                                                  ROWS_TOT, DIM, DIM, IN_DIM, 0, nullptr);

    for (int l = 0; l < 2; l++) {
        // --- attention ---
        ln_bf16_kernel<<<ROWS_TOT, 256>>>(h, ln1_g + l * DIM, ln1_b + l * DIM, yb);
        // fused QKV: N=768, split epilogue into qb/kb/vb
        tgemm_kernel<<<t768, blk256, TG_SMEM_BYTES>>>(yb, wqkvT + (size_t)l * 3 * DIM * DIM,
                                                      nullptr, nullptr, nullptr, qb, kb, vb,
                                                      ROWS_TOT, 768, 768, DIM, 0, nullptr);

        projb_kernel<<<(MPP * 64 + 255) / 256, 256>>>(proj + (size_t)l * MF * DH, pTb);
        kmax_init_kernel<<<1, 1024>>>(kmx);
        tgemm_kernel<<<tdd, blk256, TG_SMEM_BYTES>>>(qb, pTb, nullptr, nullptr, ddq, nullptr, nullptr, nullptr,
                                                     RH, MP, MP, 64, 0, nullptr);
        tgemm_kernel<<<tdd, blk256, TG_SMEM_BYTES>>>(kb, pTb, nullptr, nullptr, ddk, nullptr, nullptr, nullptr,
                                                     RH, MP, MP, 64, 0, kmx);

        qexp_kernel<<<RH / 8, 256>>>(qb, ddq, qpB);
        kexpT_kernel<<<dim3(BH, 10), 256>>>(kb, ddk, kmx, kpT);
        vtrans_kernel<<<BH, 256>>>(vb, vT);

        btgemm_kernel<<<gCtx, blk256, TG_SMEM_BYTES>>>(
            vT, (size_t)128 * NP, 127, kpT, (size_t)MPP * NP,
            nullptr, ctxT, (size_t)128 * MP, MP, MP, NP, 128);
        btgemm_kernel<<<gAtt, blk256, TG_SMEM_BYTES>>>(
            qpB, (size_t)NN * MP, NN - 1, ctxT, (size_t)128 * MP,
            outA, nullptr, (size_t)NN * 128, 128, 128, MP, NN);

        divout_kernel<<<BH, 256>>>(outA, ob);

        tgemm_kernel<<<t256, blk256, TG_SMEM_BYTES>>>(ob, woT + (size_t)l * DIM * DIM, bo + l * DIM, h,
                                                      h, nullptr, nullptr, nullptr,
                                                      ROWS_TOT, DIM, DIM, DIM, 0, nullptr);

        // --- FFN ---
        ln_bf16_kernel<<<ROWS_TOT, 256>>>(h, ln2_g + l * DIM, ln2_b + l * DIM, yb);
        tgemm_kernel<<<t1024, blk256, TG_SMEM_BYTES>>>(yb, w1T + (size_t)l * DIM * FFH, b1 + l * FFH, nullptr,
                                                       nullptr, ffhb, nullptr, nullptr,
                                                       ROWS_TOT, FFH, FFH, DIM, 1, nullptr);
        tgemm_kernel<<<t256, blk256, TG_SMEM_BYTES>>>(ffhb, w2T + (size_t)l * FFH * DIM, b2 + l * DIM, h,
                                                      h, nullptr, nullptr, nullptr,
                                                      ROWS_TOT, DIM, DIM, FFH, 0, nullptr);
    }

    pool_kernel<<<BB, 256>>>(h, pool);
    ln_f32_kernel<<<BB, 256>>>(pool, hln_g, hln_b, z);
    head1_kernel<<<BB, 128>>>(z, wh1, bh1, z1);
    head2_kernel<<<BB, 128>>>(z1, wh2, bh2, out);
}

// round 8
// speedup vs baseline: 1.0732x; 1.0732x over previous
#include <cuda_runtime.h>
#include <cuda_bf16.h>
#include <math.h>
#include <limits.h>
#include <stdint.h>

// ---------------- problem constants ----------------
#define BB 256
#define NN 300
#define IN_DIM 1280
#define DIM 256
#define HEADS 4
#define DH 64
#define MF 266            // NB_FEAT
#define MP 320            // padded feature dim
#define NP 320            // padded sequence dim per head
#define FFH 1024
#define ROWS_TOT (BB*NN)  // 76800
#define RH (ROWS_TOT*HEADS) // 307200
#define BH (BB*HEADS)       // 1024
#define RPB (NN*HEADS)      // rows per batch in dd view = 1200

#define LN_EPS 1e-5f
#define KEPS 1e-4f
#define RATIO 0.061314066f
#define NORM 0.35355339059327373f

// ---------------- scratch ----------------
__device__ float          g_h   [ROWS_TOT*DIM];
__device__ __nv_bfloat16  g_yb  [ROWS_TOT*DIM];
__device__ __nv_bfloat16  g_qb  [ROWS_TOT*DIM];
__device__ __nv_bfloat16  g_kb  [ROWS_TOT*DIM];
__device__ __nv_bfloat16  g_vb  [ROWS_TOT*DIM];
__device__ __nv_bfloat16  g_ob  [ROWS_TOT*DIM];
__device__ __nv_bfloat16  g_ffhb[ROWS_TOT*FFH];
__device__ __nv_bfloat16  g_xb  [ROWS_TOT*IN_DIM];
__device__ float          g_ddq [(size_t)RH*MP];
__device__ float          g_ddk [(size_t)RH*MP];
__device__ __nv_bfloat16  g_qpB [(size_t)BH*NN*MP];
__device__ __nv_bfloat16  g_kpT [(size_t)BH*MP*NP];
__device__ __nv_bfloat16  g_vT  [(size_t)BH*128*NP];
__device__ __nv_bfloat16  g_ctxT[(size_t)BH*128*MP];
__device__ float          g_outA[(size_t)BH*NN*128];
__device__ int            g_kmax[BH];
__device__ float          g_pool[BB*DIM];
__device__ float          g_z   [BB*DIM];
__device__ float          g_z1  [BB*128];
__device__ __nv_bfloat16  g_pTb [MP*64];
__device__ __nv_bfloat16  g_wInT[DIM*IN_DIM];
__device__ __nv_bfloat16  g_wqkvT[2][3*DIM*DIM];
__device__ __nv_bfloat16  g_woT [2][DIM*DIM];
__device__ __nv_bfloat16  g_w1T [2][FFH*DIM];
__device__ __nv_bfloat16  g_w2T [2][DIM*FFH];

// ---------------- helpers ----------------
__device__ __forceinline__ int f2o(float f) {
    int i = __float_as_int(f);
    return i >= 0 ? i : (i ^ 0x7FFFFFFF);
}
__device__ __forceinline__ float o2f(int i) {
    return __int_as_float(i >= 0 ? i : (i ^ 0x7FFFFFFF));
}
__device__ __forceinline__ float tanh_fast(float a) {
    float t = __expf(-2.0f * fabsf(a));
    float r = (1.0f - t) / (1.0f + t);
    return copysignf(r, a);
}
__device__ __forceinline__ float gelu_tanh(float x) {
    float x3 = x * x * x;
    return 0.5f * x * (1.0f + tanh_fast(0.7978845608028654f * (x + 0.044715f * x3)));
}
__device__ __forceinline__ float blockReduceSum256(float v) {
    __shared__ float sh[8];
    __syncthreads();
    int lane = threadIdx.x & 31, w = threadIdx.x >> 5;
    #pragma unroll
    for (int o = 16; o; o >>= 1) v += __shfl_xor_sync(0xFFFFFFFFu, v, o);
    if (lane == 0) sh[w] = v;
    __syncthreads();
    if (threadIdx.x == 0) {
        float s = 0.f;
        #pragma unroll
        for (int i = 0; i < 8; i++) s += sh[i];
        sh[0] = s;
    }
    __syncthreads();
    return sh[0];
}
__device__ __forceinline__ uint32_t smem_u32(const void* p) {
    uint32_t a;
    asm("{ .reg .u64 t; cvta.to.shared.u64 t, %1; cvt.u32.u64 %0, t; }" : "=r"(a) : "l"(p));
    return a;
}

#define SWZ(off) ((off) ^ (((off) >> 3) & 0x70))

__device__ __forceinline__ void ldmatrix4(uint32_t* r, uint32_t addr) {
    asm volatile("ldmatrix.sync.aligned.m8n8.x4.shared.b16 {%0,%1,%2,%3}, [%4];"
        : "=r"(r[0]), "=r"(r[1]), "=r"(r[2]), "=r"(r[3]) : "r"(addr));
}
__device__ __forceinline__ void mma16816(float* c, const uint32_t* a, uint32_t b0, uint32_t b1) {
    asm volatile(
        "mma.sync.aligned.m16n8k16.row.col.f32.bf16.bf16.f32 "
        "{%0,%1,%2,%3}, {%4,%5,%6,%7}, {%8,%9}, {%0,%1,%2,%3};"
        : "+f"(c[0]), "+f"(c[1]), "+f"(c[2]), "+f"(c[3])
        : "r"(a[0]), "r"(a[1]), "r"(a[2]), "r"(a[3]), "r"(b0), "r"(b1));
}
__device__ __forceinline__ void cp_async16(uint32_t smem, const void* g) {
    asm volatile("cp.async.cg.shared.global [%0], [%1], 16;" :: "r"(smem), "l"(g));
}
__device__ __forceinline__ void cp_commit() {
    asm volatile("cp.async.commit_group;" ::: "memory");
}
__device__ __forceinline__ void cp_wait2() {
    asm volatile("cp.async.wait_group 2;" ::: "memory");
}

// stage stride: A 16384 + B 8192 = 24576; 3 stages = 73728
#define TG_STAGE 24576
#define TG_SMEM_BYTES (3*TG_STAGE)

// ---------------- bf16 HMMA GEMM (128x64 tile, 3-stage pipeline) ----------------
// C = act(A[M,K] @ Bt[N,K]^T + bias) (+res). M%128==0, N%64==0, K%64==0.
// If Cb2 != null: bf16 stores route by cidx>>8 into {Cb, Cb2, Cb3}, row stride 256 (QKV split).
__global__ void __launch_bounds__(256) tgemm_kernel(
    const __nv_bfloat16* __restrict__ A, const __nv_bfloat16* __restrict__ Bt,
    const float* __restrict__ bias, const float* __restrict__ res,
    float* __restrict__ Cf, __nv_bfloat16* __restrict__ Cb,
    __nv_bfloat16* __restrict__ Cb2, __nv_bfloat16* __restrict__ Cb3,
    int M, int N, int K, int act, int* __restrict__ kmaxOut)
{
    extern __shared__ __nv_bfloat16 sm[];
    const uint32_t base = smem_u32(sm);
    __shared__ int smax[8];

    const int tid = threadIdx.x;
    const int wid = tid >> 5, lane = tid & 31;
    const int wm = wid & 3, wn = wid >> 2;
    const int row0 = blockIdx.y * 128, col0 = blockIdx.x * 64;
    const int tileid = lane >> 3, rit = lane & 7;
    const int gid = lane >> 2, tig = lane & 3;

    if (kmaxOut && tid < 8) smax[tid] = INT_MIN;

    float acc[2][4][4];
    #pragma unroll
    for (int mt = 0; mt < 2; mt++)
        #pragma unroll
        for (int j = 0; j < 4; j++)
            #pragma unroll
            for (int r = 0; r < 4; r++) acc[mt][j][r] = 0.f;

    const int nch = K >> 6;
    const __nv_bfloat16* Arow = A + (size_t)row0 * K;
    const __nv_bfloat16* Brow = Bt + (size_t)col0 * K;

    #pragma unroll
    for (int s = 0; s < 3; s++) {
        if (s < nch) {
            const int k0 = s << 6;
            const uint32_t aS = base + s * TG_STAGE;
            const uint32_t bS = aS + 16384;
            #pragma unroll
            for (int i = 0; i < 4; i++) {
                int lin = tid + i * 256;
                int r = lin >> 3, c8 = lin & 7;
                cp_async16(aS + SWZ(r * 128 + c8 * 16), Arow + (size_t)r * K + k0 + c8 * 8);
            }
            #pragma unroll
            for (int i = 0; i < 2; i++) {
                int lin = tid + i * 256;
                int r = lin >> 3, c8 = lin & 7;
                cp_async16(bS + SWZ(r * 128 + c8 * 16), Brow + (size_t)r * K + k0 + c8 * 8);
            }
        }
        cp_commit();
    }

    int stg = 0;
    for (int c = 0; c < nch; c++) {
        cp_wait2();
        __syncthreads();
        const uint32_t aB = base + stg * TG_STAGE;
        const uint32_t bB = aB + 16384;
        #pragma unroll
        for (int kk = 0; kk < 4; kk++) {
            uint32_t af[2][4];
            #pragma unroll
            for (int mt = 0; mt < 2; mt++) {
                int off = (wm * 32 + mt * 16 + (tileid & 1) * 8 + rit) * 128
                          + kk * 32 + (tileid >> 1) * 16;
                ldmatrix4(af[mt], aB + SWZ(off));
            }
            uint32_t bf[2][4];
            #pragma unroll
            for (int nt = 0; nt < 2; nt++) {
                int off = (wn * 32 + nt * 16 + (tileid & 1) * 8 + rit) * 128
                          + kk * 32 + (tileid >> 1) * 16;
                ldmatrix4(bf[nt], bB + SWZ(off));
            }
            #pragma unroll
            for (int mt = 0; mt < 2; mt++)
                #pragma unroll
                for (int j = 0; j < 4; j++) {
                    int nt = j >> 1, sel = j & 1;
                    mma16816(acc[mt][j], af[mt], bf[nt][sel], bf[nt][2 + sel]);
                }
        }
        __syncthreads();
        if (c + 3 < nch) {
            const int k0 = (c + 3) << 6;
            const uint32_t aS = base + stg * TG_STAGE;
            const uint32_t bS = aS + 16384;
            #pragma unroll
            for (int i = 0; i < 4; i++) {
                int lin = tid + i * 256;
                int r = lin >> 3, c8 = lin & 7;
                cp_async16(aS + SWZ(r * 128 + c8 * 16), Arow + (size_t)r * K + k0 + c8 * 8);
            }
            #pragma unroll
            for (int i = 0; i < 2; i++) {
                int lin = tid + i * 256;
                int r = lin >> 3, c8 = lin & 7;
                cp_async16(bS + SWZ(r * 128 + c8 * 16), Brow + (size_t)r * K + k0 + c8 * 8);
            }
        }
        cp_commit();
        stg = (stg + 1) == 3 ? 0 : stg + 1;
    }

    // epilogue
    float kmv[2] = {-1e30f, -1e30f};
    const int b0 = row0 / RPB;
    #pragma unroll
    for (int mt = 0; mt < 2; mt++) {
        #pragma unroll
        for (int j = 0; j < 4; j++) {
            #pragma unroll
            for (int half = 0; half < 2; half++) {
                int r = row0 + wm * 32 + mt * 16 + gid + half * 8;
                int cidx = col0 + wn * 32 + j * 8 + tig * 2;
                float v0 = acc[mt][j][half * 2 + 0];
                float v1 = acc[mt][j][half * 2 + 1];
                if (kmaxOut) {
                    int bs = (r / RPB == b0) ? 0 : 1;
                    float m = -1e30f;
                    if (cidx < MF) m = v0;
                    if (cidx + 1 < MF) m = fmaxf(m, v1);
                    kmv[bs] = fmaxf(kmv[bs], m);
                }
                if (bias) { v0 += bias[cidx]; v1 += bias[cidx + 1]; }
                if (act == 1) { v0 = gelu_tanh(v0); v1 = gelu_tanh(v1); }
                if (res) {
                    float2 r2 = *(const float2*)(res + (size_t)r * N + cidx);
                    v0 += r2.x; v1 += r2.y;
                }
                if (Cf) *(float2*)(Cf + (size_t)r * N + cidx) = make_float2(v0, v1);
                if (Cb2) {
                    int sel = cidx >> 8;
                    __nv_bfloat16* p = sel == 0 ? Cb : (sel == 1 ? Cb2 : Cb3);
                    *(__nv_bfloat162*)(p + (size_t)r * 256 + (cidx & 255)) = __floats2bfloat162_rn(v0, v1);
                } else if (Cb) {
                    *(__nv_bfloat162*)(Cb + (size_t)r * N + cidx) = __floats2bfloat162_rn(v0, v1);
                }
            }
        }
    }
    if (kmaxOut) {
        int h = (row0 + wm * 32 + gid) & 3;
        if (kmv[0] > -1e29f) atomicMax(&smax[h], f2o(kmv[0]));
        if (kmv[1] > -1e29f) atomicMax(&smax[4 + h], f2o(kmv[1]));
        __syncthreads();
        if (tid < 8) {
            int bsel = tid >> 2, hh = tid & 3;
            int bb = b0 + bsel;
            if (smax[tid] != INT_MIN && bb < BB)
                atomicMax(&kmaxOut[bb * HEADS + hh], smax[tid]);
        }
    }
}

// ---------------- batched bf16 HMMA GEMM (128x64 tile, pipelined) ----------------
__global__ void __launch_bounds__(256) btgemm_kernel(
    const __nv_bfloat16* __restrict__ A, size_t aBS, int aClamp,
    const __nv_bfloat16* __restrict__ Bt, size_t bBS,
    float* __restrict__ Cf, __nv_bfloat16* __restrict__ Cb, size_t cBS,
    int ldc, int K, int mValid)
{
    extern __shared__ __nv_bfloat16 sm[];
    const uint32_t base = smem_u32(sm);

    const int tid = threadIdx.x;
    const int wid = tid >> 5, lane = tid & 31;
    const int wm = wid & 3, wn = wid >> 2;
    const int row0 = blockIdx.y * 128, col0 = blockIdx.x * 64;
    const int tileid = lane >> 3, rit = lane & 7;
    const int gid = lane >> 2, tig = lane & 3;
    const int bh = blockIdx.z;

    const __nv_bfloat16* Ab = A + (size_t)bh * aBS;
    const __nv_bfloat16* Bb = Bt + (size_t)bh * bBS + (size_t)col0 * K;

    float acc[2][4][4];
    #pragma unroll
    for (int mt = 0; mt < 2; mt++)
        #pragma unroll
        for (int j = 0; j < 4; j++)
            #pragma unroll
            for (int r = 0; r < 4; r++) acc[mt][j][r] = 0.f;

    const int nch = K >> 6;
    #pragma unroll
    for (int s = 0; s < 3; s++) {
        if (s < nch) {
            const int k0 = s << 6;
            const uint32_t aS = base + s * TG_STAGE;
            const uint32_t bS = aS + 16384;
            #pragma unroll
            for (int i = 0; i < 4; i++) {
                int lin = tid + i * 256;
                int r = lin >> 3, c8 = lin & 7;
                int rg = min(row0 + r, aClamp);
                cp_async16(aS + SWZ(r * 128 + c8 * 16), Ab + (size_t)rg * K + k0 + c8 * 8);
            }
            #pragma unroll
            for (int i = 0; i < 2; i++) {
                int lin = tid + i * 256;
                int r = lin >> 3, c8 = lin & 7;
                cp_async16(bS + SWZ(r * 128 + c8 * 16), Bb + (size_t)r * K + k0 + c8 * 8);
            }
        }
        cp_commit();
    }

    int stg = 0;
    for (int c = 0; c < nch; c++) {
        cp_wait2();
        __syncthreads();
        const uint32_t aB = base + stg * TG_STAGE;
        const uint32_t bB = aB + 16384;
        #pragma unroll
        for (int kk = 0; kk < 4; kk++) {
            uint32_t af[2][4];
            #pragma unroll
            for (int mt = 0; mt < 2; mt++) {
                int off = (wm * 32 + mt * 16 + (tileid & 1) * 8 + rit) * 128
                          + kk * 32 + (tileid >> 1) * 16;
                ldmatrix4(af[mt], aB + SWZ(off));
            }
            uint32_t bf[2][4];
            #pragma unroll
            for (int nt = 0; nt < 2; nt++) {
                int off = (wn * 32 + nt * 16 + (tileid & 1) * 8 + rit) * 128
                          + kk * 32 + (tileid >> 1) * 16;
                ldmatrix4(bf[nt], bB + SWZ(off));
            }
            #pragma unroll
            for (int mt = 0; mt < 2; mt++)
                #pragma unroll
                for (int j = 0; j < 4; j++) {
                    int nt = j >> 1, sel = j & 1;
                    mma16816(acc[mt][j], af[mt], bf[nt][sel], bf[nt][2 + sel]);
                }
        }
        __syncthreads();
        if (c + 3 < nch) {
            const int k0 = (c + 3) << 6;
            const uint32_t aS = base + stg * TG_STAGE;
            const uint32_t bS = aS + 16384;
            #pragma unroll
            for (int i = 0; i < 4; i++) {
                int lin = tid + i * 256;
                int r = lin >> 3, c8 = lin & 7;
                int rg = min(row0 + r, aClamp);
                cp_async16(aS + SWZ(r * 128 + c8 * 16), Ab + (size_t)rg * K + k0 + c8 * 8);
            }
            #pragma unroll
            for (int i = 0; i < 2; i++) {
                int lin = tid + i * 256;
                int r = lin >> 3, c8 = lin & 7;
                cp_async16(bS + SWZ(r * 128 + c8 * 16), Bb + (size_t)r * K + k0 + c8 * 8);
            }
        }
        cp_commit();
        stg = (stg + 1) == 3 ? 0 : stg + 1;
    }

    float* Cfb = Cf ? Cf + (size_t)bh * cBS : nullptr;
    __nv_bfloat16* Cbb = Cb ? Cb + (size_t)bh * cBS : nullptr;
    #pragma unroll
    for (int mt = 0; mt < 2; mt++) {
        #pragma unroll
        for (int j = 0; j < 4; j++) {
            #pragma unroll
            for (int half = 0; half < 2; half++) {
                int r = row0 + wm * 32 + mt * 16 + gid + half * 8;
                if (r >= mValid) continue;
                int cidx = col0 + wn * 32 + j * 8 + tig * 2;
                float v0 = acc[mt][j][half * 2 + 0];
                float v1 = acc[mt][j][half * 2 + 1];
                if (Cfb) *(float2*)(Cfb + (size_t)r * ldc + cidx) = make_float2(v0, v1);
                if (Cbb) *(__nv_bfloat162*)(Cbb + (size_t)r * ldc + cidx) = __floats2bfloat162_rn(v0, v1);
            }
        }
    }
}

// ---------------- prep kernels ----------------
__global__ void f2b_kernel(const float* __restrict__ a, __nv_bfloat16* __restrict__ b, size_t n) {
    size_t i = (size_t)blockIdx.x * blockDim.x + threadIdx.x;
    if (i < n) b[i] = __float2bfloat16(a[i]);
}

__global__ void wtrans_kernel(const float* __restrict__ W, __nv_bfloat16* __restrict__ Wt,
                              int K, int N) {
    __shared__ float t[32][33];
    int k0 = blockIdx.y * 32, n0 = blockIdx.x * 32;
    int tx = threadIdx.x, ty = threadIdx.y;
    #pragma unroll
    for (int i = 0; i < 32; i += 8)
        t[ty + i][tx] = W[(size_t)(k0 + ty + i) * N + n0 + tx];
    __syncthreads();
    #pragma unroll
    for (int i = 0; i < 32; i += 8)
        Wt[(size_t)(n0 + ty + i) * K + k0 + tx] = __float2bfloat16(t[tx][ty + i]);
}

__global__ void projb_kernel(const float* __restrict__ proj, __nv_bfloat16* __restrict__ pTb) {
    int i = blockIdx.x * 256 + threadIdx.x;
    if (i >= MP * 64) return;
    int m = i >> 6, d = i & 63;
    pTb[i] = __float2bfloat16((m < MF) ? proj[m * 64 + d] * NORM : 0.f);
}

// ---------------- layernorm ----------------
__global__ void ln_bf16_kernel(const float* __restrict__ x, const float* __restrict__ g,
                               const float* __restrict__ b, __nv_bfloat16* __restrict__ y)
{
    int row = blockIdx.x;
    int t = threadIdx.x;
    float v = x[(size_t)row * DIM + t];
    float mu = blockReduceSum256(v) * (1.0f / DIM);
    float d = v - mu;
    float var = blockReduceSum256(d * d) * (1.0f / DIM);
    y[(size_t)row * DIM + t] = __float2bfloat16(d * rsqrtf(var + LN_EPS) * g[t] + b[t]);
}

__global__ void ln_f32_kernel(const float* __restrict__ x, const float* __restrict__ g,
                              const float* __restrict__ b, float* __restrict__ y)
{
    int row = blockIdx.x;
    int t = threadIdx.x;
    float v = x[(size_t)row * DIM + t];
    float mu = blockReduceSum256(v) * (1.0f / DIM);
    float d = v - mu;
    float var = blockReduceSum256(d * d) * (1.0f / DIM);
    y[(size_t)row * DIM + t] = d * rsqrtf(var + LN_EPS) * g[t] + b[t];
}

// ---------------- FAVOR+ passes ----------------
__global__ void qexp_kernel(const __nv_bfloat16* __restrict__ qbuf, const float* __restrict__ dd,
                            __nv_bfloat16* __restrict__ qpB)
{
    int w = (blockIdx.x * 256 + threadIdx.x) >> 5;
    int lane = threadIdx.x & 31;
    if (w >= RH) return;
    const __nv_bfloat16* qr = qbuf + (size_t)w * 64;
    float a = __bfloat162float(qr[lane]), b2 = __bfloat162float(qr[lane + 32]);
    float s = a * a + b2 * b2;
    #pragma unroll
    for (int o = 16; o; o >>= 1) s += __shfl_xor_sync(0xFFFFFFFFu, s, o);
    float diag = 0.0625f * s;
    const float* row = dd + (size_t)w * MP;
    float vv[9], mx = -1e30f;
    #pragma unroll
    for (int i = 0; i < 9; i++) {
        int m = lane + 32 * i;
        vv[i] = (m < MF) ? row[m] : -1e30f;
        mx = fmaxf(mx, vv[i]);
    }
    #pragma unroll
    for (int o = 16; o; o >>= 1) mx = fmaxf(mx, __shfl_xor_sync(0xFFFFFFFFu, mx, o));

    int b = w / RPB;
    int rem = w - b * RPB;
    int n = rem >> 2, h = rem & 3;
    __nv_bfloat16* orow = qpB + ((size_t)(b * HEADS + h) * NN + n) * MP;
    #pragma unroll
    for (int i = 0; i < 9; i++) {
        int m = lane + 32 * i;
        if (m < MF) orow[m] = __float2bfloat16(RATIO * (__expf(vv[i] - diag - mx) + KEPS));
        else orow[m] = __float2bfloat16(0.f);
    }
    orow[lane + 288] = __float2bfloat16(0.f);
}

__global__ void kmax_init_kernel(int* __restrict__ kmax) {
    int i = blockIdx.x * blockDim.x + threadIdx.x;
    if (i < BH) kmax[i] = INT_MIN;
}

// kexp + transpose
__global__ void __launch_bounds__(256) kexpT_kernel(
    const __nv_bfloat16* __restrict__ kbuf, const float* __restrict__ dd,
    const int* __restrict__ kmax, __nv_bfloat16* __restrict__ kpT)
{
    __shared__ float s[32][325];
    __shared__ float diag[32];
    int bh = blockIdx.x, b = bh >> 2, h = bh & 3;
    int n0 = blockIdx.y * 32;
    int tid = threadIdx.x;
    int wid = tid >> 5, lane = tid & 31;

    #pragma unroll
    for (int ii = 0; ii < 4; ii++) {
        int n_l = wid * 4 + ii;
        int n_g = n0 + n_l;
        float sum = 0.f;
        if (n_g < NN) {
            const __nv_bfloat16* kr = kbuf + ((size_t)(b * NN + n_g)) * DIM + h * 64;
            float a = __bfloat162float(kr[lane]), b2 = __bfloat162float(kr[lane + 32]);
            sum = a * a + b2 * b2;
        }
        #pragma unroll
        for (int o = 16; o; o >>= 1) sum += __shfl_xor_sync(0xFFFFFFFFu, sum, o);
        if (lane == 0) diag[n_l] = 0.0625f * sum;
    }

    #pragma unroll
    for (int it = 0; it < 4; it++) {
        int n_l = (tid >> 5) + 8 * it;
        int n_g = n0 + n_l;
        const float* row = dd + ((size_t)((b * NN + min(n_g, NN - 1)) * HEADS) + h) * MP;
        bool ok = n_g < NN;
        #pragma unroll
        for (int j = 0; j < 10; j++) {
            int m = lane + 32 * j;
            s[n_l][m] = ok ? row[m] : 0.f;
        }
    }
    __syncthreads();

    float stab = o2f(kmax[bh]);
    int n_g = n0 + lane;
    bool nok = n_g < NN;
    float dg = diag[lane];
    __nv_bfloat16* base = kpT + (size_t)bh * MP * NP + n0 + lane;
    for (int m = wid; m < MP; m += 8) {
        float val = 0.f;
        if (m < MF && nok)
            val = RATIO * (__expf(s[lane][m] - dg - stab) + KEPS);
        base[(size_t)m * NP] = __float2bfloat16(val);
    }
}

// v transpose (bf16 in): vAugT[bh][d][n], d=64 row = ones
__global__ void __launch_bounds__(256) vtrans_kernel(
    const __nv_bfloat16* __restrict__ v, __nv_bfloat16* __restrict__ vT)
{
    __shared__ float t[32][65];
    int bh = blockIdx.x, b = bh >> 2, h = bh & 3;
    int tid = threadIdx.x;
    int lane = tid & 31;
    __nv_bfloat16* vb = vT + (size_t)bh * 128 * NP;

    for (int it = 0; it < 10; it++) {
        int n0 = it * 32;
        int d = tid & 63;
        #pragma unroll
        for (int sub = 0; sub < 8; sub++) {
            int n_l = (tid >> 6) + 4 * sub;
            int n_g = n0 + n_l;
            t[n_l][d] = (n_g < NN) ?
                __bfloat162float(v[((size_t)(b * NN + n_g)) * DIM + h * 64 + d]) : 0.f;
        }
        __syncthreads();
        int dcol = tid >> 5;
        #pragma unroll
        for (int j = 0; j < 8; j++) {
            int d2 = dcol + 8 * j;
            vb[(size_t)d2 * NP + n0 + lane] = __float2bfloat16(t[lane][d2]);
        }
        __syncthreads();
    }
    for (int idx = tid; idx < 64 * NP; idx += 256) {
        int d = 64 + idx / NP, n = idx % NP;
        float val = (d == 64 && n < NN) ? 1.f : 0.f;
        vb[(size_t)d * NP + n] = __float2bfloat16(val);
    }
}

__global__ void divout_kernel(const float* __restrict__ outA, __nv_bfloat16* __restrict__ ob)
{
    int bh = blockIdx.x, b = bh >> 2, h = bh & 3;
    const float* base = outA + (size_t)bh * NN * 128;
    for (int idx = threadIdx.x; idx < NN * 64; idx += 256) {
        int n = idx >> 6, d = idx & 63;
        float num = base[(size_t)n * 128 + d];
        float den = base[(size_t)n * 128 + 64];
        ob[((size_t)(b * NN + n)) * DIM + h * 64 + d] = __float2bfloat16(num / den);
    }
}

// ---------------- pooling & head ----------------
__global__ void pool_kernel(const float* __restrict__ h, float* __restrict__ pooled)
{
    int b = blockIdx.x, c = threadIdx.x;
    const float* p = h + (size_t)b * NN * DIM + c;
    float s0 = 0.f, s1 = 0.f, s2 = 0.f, s3 = 0.f;
    for (int n = 0; n < NN; n += 4) {
        s0 += p[(size_t)(n + 0) * DIM];
        s1 += p[(size_t)(n + 1) * DIM];
        s2 += p[(size_t)(n + 2) * DIM];
        s3 += p[(size_t)(n + 3) * DIM];
    }
    pooled[b * DIM + c] = ((s0 + s1) + (s2 + s3)) * (1.0f / NN);
}

__global__ void head1_kernel(const float* __restrict__ z, const float* __restrict__ w,
                             const float* __restrict__ bias, float* __restrict__ z1)
{
    __shared__ float zs[DIM];
    int b = blockIdx.x, j = threadIdx.x;
    for (int c = j; c < DIM; c += 128) zs[c] = z[b * DIM + c];
    __syncthreads();
    float s0 = 0.f, s1 = 0.f, s2 = 0.f, s3 = 0.f;
    #pragma unroll 1
    for (int c = 0; c < DIM; c += 4) {
        s0 = fmaf(zs[c + 0], w[(c + 0) * 128 + j], s0);
        s1 = fmaf(zs[c + 1], w[(c + 1) * 128 + j], s1);
        s2 = fmaf(zs[c + 2], w[(c + 2) * 128 + j], s2);
        s3 = fmaf(zs[c + 3], w[(c + 3) * 128 + j], s3);
    }
    z1[b * 128 + j] = fmaxf(((s0 + s1) + (s2 + s3)) + bias[j], 0.f);
}

__global__ void head2_kernel(const float* __restrict__ z1, const float* __restrict__ w,
                             const float* __restrict__ bias, float* __restrict__ out)
{
    __shared__ float sh[4];
    int b = blockIdx.x, j = threadIdx.x;
    float s = z1[b * 128 + j] * w[j];
    #pragma unroll
    for (int o = 16; o; o >>= 1) s += __shfl_xor_sync(0xFFFFFFFFu, s, o);
    if ((j & 31) == 0) sh[j >> 5] = s;
    __syncthreads();
    if (j == 0) {
        float t = sh[0] + sh[1] + sh[2] + sh[3] + bias[0];
        out[b] = 1.0f / (1.0f + __expf(-t));
    }
}

// ---------------- host ----------------
template <typename T> static T* symaddr(const void* sym) {
    void* p = nullptr;
    cudaGetSymbolAddress(&p, sym);
    return (T*)p;
}

extern "C" void kernel_launch(void* const* d_in, const int* in_sizes, int n_in,
                              void* d_out, int out_size)
{
    const float* x     = (const float*)d_in[0];
    const float* w_in  = (const float*)d_in[1];
    const float* b_in  = (const float*)d_in[2];
    const float* proj  = (const float*)d_in[3];
    const float* ln1_g = (const float*)d_in[4];
    const float* ln1_b = (const float*)d_in[5];
    const float* wq    = (const float*)d_in[6];
    const float* wk    = (const float*)d_in[7];
    const float* wv    = (const float*)d_in[8];
    const float* wo    = (const float*)d_in[9];
    const float* bo    = (const float*)d_in[10];
    const float* ln2_g = (const float*)d_in[11];
    const float* ln2_b = (const float*)d_in[12];
    const float* w1    = (const float*)d_in[13];
    const float* b1    = (const float*)d_in[14];
    const float* w2    = (const float*)d_in[15];
    const float* b2    = (const float*)d_in[16];
    const float* hln_g = (const float*)d_in[17];
    const float* hln_b = (const float*)d_in[18];
    const float* wh1   = (const float*)d_in[19];
    const float* bh1   = (const float*)d_in[20];
    const float* wh2   = (const float*)d_in[21];
    const float* bh2   = (const float*)d_in[22];
    float* out = (float*)d_out;

    float* h    = symaddr<float>(g_h);
    __nv_bfloat16* yb   = symaddr<__nv_bfloat16>(g_yb);
    __nv_bfloat16* qb   = symaddr<__nv_bfloat16>(g_qb);
    __nv_bfloat16* kb   = symaddr<__nv_bfloat16>(g_kb);
    __nv_bfloat16* vb   = symaddr<__nv_bfloat16>(g_vb);
    __nv_bfloat16* ob   = symaddr<__nv_bfloat16>(g_ob);
    __nv_bfloat16* ffhb = symaddr<__nv_bfloat16>(g_ffhb);
    __nv_bfloat16* xb   = symaddr<__nv_bfloat16>(g_xb);
    float* ddq  = symaddr<float>(g_ddq);
    float* ddk  = symaddr<float>(g_ddk);
    __nv_bfloat16* qpB  = symaddr<__nv_bfloat16>(g_qpB);
    __nv_bfloat16* kpT  = symaddr<__nv_bfloat16>(g_kpT);
    __nv_bfloat16* vT   = symaddr<__nv_bfloat16>(g_vT);
    __nv_bfloat16* ctxT = symaddr<__nv_bfloat16>(g_ctxT);
    float* outA = symaddr<float>(g_outA);
    int*   kmx  = symaddr<int>(g_kmax);
    float* pool = symaddr<float>(g_pool);
    float* z    = symaddr<float>(g_z);
    float* z1   = symaddr<float>(g_z1);
    __nv_bfloat16* pTb  = symaddr<__nv_bfloat16>(g_pTb);
    __nv_bfloat16* wInT = symaddr<__nv_bfloat16>(g_wInT);
    __nv_bfloat16* wqkvT = symaddr<__nv_bfloat16>(g_wqkvT);
    __nv_bfloat16* woT  = symaddr<__nv_bfloat16>(g_woT);
    __nv_bfloat16* w1T  = symaddr<__nv_bfloat16>(g_w1T);
    __nv_bfloat16* w2T  = symaddr<__nv_bfloat16>(g_w2T);

    static bool attr_set = false;
    if (!attr_set) {
        cudaFuncSetAttribute(tgemm_kernel, cudaFuncAttributeMaxDynamicSharedMemorySize, TG_SMEM_BYTES);
        cudaFuncSetAttribute(btgemm_kernel, cudaFuncAttributeMaxDynamicSharedMemorySize, TG_SMEM_BYTES);
        attr_set = true;
    }

    dim3 blk256(256);
    dim3 t256(4, ROWS_TOT / 128);       // N=256
    dim3 t768(12, ROWS_TOT / 128);      // N=768 fused QKV
    dim3 t1024(16, ROWS_TOT / 128);     // N=1024
    dim3 tdd(5, RH / 128);              // N=320
    dim3 gCtx(5, 1, BH);
    dim3 gAtt(2, 3, BH);

    // ---- prep ----
    f2b_kernel<<<(int)((ROWS_TOT * (size_t)IN_DIM + 255) / 256), 256>>>(x, xb, (size_t)ROWS_TOT * IN_DIM);
    wtrans_kernel<<<dim3(DIM / 32, IN_DIM / 32), dim3(32, 8)>>>(w_in, wInT, IN_DIM, DIM);
    for (int l = 0; l < 2; l++) {
        __nv_bfloat16* wqkv = wqkvT + (size_t)l * 3 * DIM * DIM;
        wtrans_kernel<<<dim3(DIM / 32, DIM / 32), dim3(32, 8)>>>(wq + (size_t)l * DIM * DIM, wqkv, DIM, DIM);
        wtrans_kernel<<<dim3(DIM / 32, DIM / 32), dim3(32, 8)>>>(wk + (size_t)l * DIM * DIM, wqkv + DIM * DIM, DIM, DIM);
        wtrans_kernel<<<dim3(DIM / 32, DIM / 32), dim3(32, 8)>>>(wv + (size_t)l * DIM * DIM, wqkv + 2 * DIM * DIM, DIM, DIM);
        wtrans_kernel<<<dim3(DIM / 32, DIM / 32), dim3(32, 8)>>>(wo + (size_t)l * DIM * DIM, woT + (size_t)l * DIM * DIM, DIM, DIM);
        wtrans_kernel<<<dim3(FFH / 32, DIM / 32), dim3(32, 8)>>>(w1 + (size_t)l * DIM * FFH, w1T + (size_t)l * DIM * FFH, DIM, FFH);
        wtrans_kernel<<<dim3(DIM / 32, FFH / 32), dim3(32, 8)>>>(w2 + (size_t)l * FFH * DIM, w2T + (size_t)l * FFH * DIM, FFH, DIM);
    }

    tgemm_kernel<<<t256, blk256, TG_SMEM_BYTES>>>(xb, wInT, b_in, nullptr, h, nullptr, nullptr, nullptr,
                                                  ROWS_TOT, DIM, IN_DIM, 0, nullptr);

    for (int l = 0; l < 2; l++) {
        // --- attention ---
        ln_bf16_kernel<<<ROWS_TOT, 256>>>(h, ln1_g + l * DIM, ln1_b + l * DIM, yb);
        // fused QKV: N=768, epilogue splits into qb/kb/vb
        tgemm_kernel<<<t768, blk256, TG_SMEM_BYTES>>>(yb, wqkvT + (size_t)l * 3 * DIM * DIM,
                                                      nullptr, nullptr, nullptr, qb, kb, vb,
                                                      ROWS_TOT, 768, DIM, 0, nullptr);

        projb_kernel<<<(MP * 64 + 255) / 256, 256>>>(proj + (size_t)l * MF * DH, pTb);
        kmax_init_kernel<<<1, 1024>>>(kmx);
        tgemm_kernel<<<tdd, blk256, TG_SMEM_BYTES>>>(qb, pTb, nullptr, nullptr, ddq, nullptr, nullptr, nullptr,
                                                     RH, MP, 64, 0, nullptr);
        tgemm_kernel<<<tdd, blk256, TG_SMEM_BYTES>>>(kb, pTb, nullptr, nullptr, ddk, nullptr, nullptr, nullptr,
                                                     RH, MP, 64, 0, kmx);

        qexp_kernel<<<RH / 8, 256>>>(qb, ddq, qpB);
        kexpT_kernel<<<dim3(BH, 10), 256>>>(kb, ddk, kmx, kpT);
        vtrans_kernel<<<BH, 256>>>(vb, vT);

        btgemm_kernel<<<gCtx, blk256, TG_SMEM_BYTES>>>(
            vT, (size_t)128 * NP, 127, kpT, (size_t)MP * NP,
            nullptr, ctxT, (size_t)128 * MP, MP, NP, 128);
        btgemm_kernel<<<gAtt, blk256, TG_SMEM_BYTES>>>(
            qpB, (size_t)NN * MP, NN - 1, ctxT, (size_t)128 * MP,
            outA, nullptr, (size_t)NN * 128, 128, MP, NN);

        divout_kernel<<<BH, 256>>>(outA, ob);

        tgemm_kernel<<<t256, blk256, TG_SMEM_BYTES>>>(ob, woT + (size_t)l * DIM * DIM, bo + l * DIM, h,
                                                      h, nullptr, nullptr, nullptr,
                                                      ROWS_TOT, DIM, DIM, 0, nullptr);

        // --- FFN ---
        ln_bf16_kernel<<<ROWS_TOT, 256>>>(h, ln2_g + l * DIM, ln2_b + l * DIM, yb);
        tgemm_kernel<<<t1024, blk256, TG_SMEM_BYTES>>>(yb, w1T + (size_t)l * DIM * FFH, b1 + l * FFH, nullptr,
                                                       nullptr, ffhb, nullptr, nullptr,
                                                       ROWS_TOT, FFH, DIM, 1, nullptr);
        tgemm_kernel<<<t256, blk256, TG_SMEM_BYTES>>>(ffhb, w2T + (size_t)l * FFH * DIM, b2 + l * DIM, h,
                                                      h, nullptr, nullptr, nullptr,
                                                      ROWS_TOT, DIM, FFH, 0, nullptr);
    }

    pool_kernel<<<BB, 256>>>(h, pool);
    ln_f32_kernel<<<BB, 256>>>(pool, hln_g, hln_b, z);
    head1_kernel<<<BB, 128>>>(z, wh1, bh1, z1);
    head2_kernel<<<BB, 128>>>(z1, wh2, bh2, out);
}

// round 12
// speedup vs baseline: 1.2030x; 1.1210x over previous
#include <cuda_runtime.h>
#include <cuda_bf16.h>
#include <math.h>
#include <limits.h>
#include <stdint.h>

// ---------------- problem constants ----------------
#define BB 256
#define NN 300
#define IN_DIM 1280
#define DIM 256
#define HEADS 4
#define DH 64
#define MF 266            // NB_FEAT
#define MP 320            // padded feature dim
#define NP 320            // padded sequence dim per head
#define FFH 1024
#define ROWS_TOT (BB*NN)  // 76800
#define RH (ROWS_TOT*HEADS) // 307200
#define BH (BB*HEADS)       // 1024
#define RPB (NN*HEADS)      // rows per batch in dd view = 1200

#define LN_EPS 1e-5f
#define KEPS 1e-4f
#define RATIO 0.061314066f
#define NORM 0.35355339059327373f

// ---------------- scratch ----------------
__device__ float          g_h   [ROWS_TOT*DIM];
__device__ __nv_bfloat16  g_yb  [ROWS_TOT*DIM];
__device__ __nv_bfloat16  g_qb  [ROWS_TOT*DIM];
__device__ __nv_bfloat16  g_kb  [ROWS_TOT*DIM];
__device__ __nv_bfloat16  g_vb  [ROWS_TOT*DIM];
__device__ __nv_bfloat16  g_ob  [ROWS_TOT*DIM];
__device__ __nv_bfloat16  g_ffhb[ROWS_TOT*FFH];
__device__ __nv_bfloat16  g_xb  [ROWS_TOT*IN_DIM];
__device__ float          g_ddq [(size_t)RH*MP];
__device__ float          g_ddk [(size_t)RH*MP];
__device__ __nv_bfloat16  g_qpB [(size_t)BH*NN*MP];
__device__ __nv_bfloat16  g_kpT [(size_t)BH*MP*NP];
__device__ __nv_bfloat16  g_vT  [(size_t)BH*128*NP];
__device__ __nv_bfloat16  g_ctxT[(size_t)BH*128*MP];
__device__ float          g_outA[(size_t)BH*NN*128];
__device__ int            g_kmax[BH];
__device__ float          g_pool[BB*DIM];
__device__ float          g_z   [BB*DIM];
__device__ float          g_z1  [BB*128];
__device__ __nv_bfloat16  g_pTb [MP*64];
__device__ __nv_bfloat16  g_wInT[DIM*IN_DIM];
__device__ __nv_bfloat16  g_wqT [2][DIM*DIM];
__device__ __nv_bfloat16  g_wkT [2][DIM*DIM];
__device__ __nv_bfloat16  g_wvT [2][DIM*DIM];
__device__ __nv_bfloat16  g_woT [2][DIM*DIM];
__device__ __nv_bfloat16  g_w1T [2][FFH*DIM];
__device__ __nv_bfloat16  g_w2T [2][DIM*FFH];

// ---------------- helpers ----------------
__device__ __forceinline__ int f2o(float f) {
    int i = __float_as_int(f);
    return i >= 0 ? i : (i ^ 0x7FFFFFFF);
}
__device__ __forceinline__ float o2f(int i) {
    return __int_as_float(i >= 0 ? i : (i ^ 0x7FFFFFFF));
}
__device__ __forceinline__ float tanh_fast(float a) {
    float t = __expf(-2.0f * fabsf(a));
    float r = (1.0f - t) / (1.0f + t);
    return copysignf(r, a);
}
__device__ __forceinline__ float gelu_tanh(float x) {
    float x3 = x * x * x;
    return 0.5f * x * (1.0f + tanh_fast(0.7978845608028654f * (x + 0.044715f * x3)));
}
__device__ __forceinline__ float blockReduceSum256(float v) {
    __shared__ float sh[8];
    __syncthreads();
    int lane = threadIdx.x & 31, w = threadIdx.x >> 5;
    #pragma unroll
    for (int o = 16; o; o >>= 1) v += __shfl_xor_sync(0xFFFFFFFFu, v, o);
    if (lane == 0) sh[w] = v;
    __syncthreads();
    if (threadIdx.x == 0) {
        float s = 0.f;
        #pragma unroll
        for (int i = 0; i < 8; i++) s += sh[i];
        sh[0] = s;
    }
    __syncthreads();
    return sh[0];
}
__device__ __forceinline__ uint32_t smem_u32(const void* p) {
    uint32_t a;
    asm("{ .reg .u64 t; cvta.to.shared.u64 t, %1; cvt.u32.u64 %0, t; }" : "=r"(a) : "l"(p));
    return a;
}

#define SWZ(off) ((off) ^ (((off) >> 3) & 0x70))

__device__ __forceinline__ void ldmatrix4(uint32_t* r, uint32_t addr) {
    asm volatile("ldmatrix.sync.aligned.m8n8.x4.shared.b16 {%0,%1,%2,%3}, [%4];"
        : "=r"(r[0]), "=r"(r[1]), "=r"(r[2]), "=r"(r[3]) : "r"(addr));
}
__device__ __forceinline__ void mma16816(float* c, const uint32_t* a, uint32_t b0, uint32_t b1) {
    asm volatile(
        "mma.sync.aligned.m16n8k16.row.col.f32.bf16.bf16.f32 "
        "{%0,%1,%2,%3}, {%4,%5,%6,%7}, {%8,%9}, {%0,%1,%2,%3};"
        : "+f"(c[0]), "+f"(c[1]), "+f"(c[2]), "+f"(c[3])
        : "r"(a[0]), "r"(a[1]), "r"(a[2]), "r"(a[3]), "r"(b0), "r"(b1));
}
__device__ __forceinline__ void cp_async16(uint32_t smem, const void* g) {
    asm volatile("cp.async.cg.shared.global [%0], [%1], 16;" :: "r"(smem), "l"(g));
}
__device__ __forceinline__ void cp_commit() {
    asm volatile("cp.async.commit_group;" ::: "memory");
}
__device__ __forceinline__ void cp_wait2() {
    asm volatile("cp.async.wait_group 2;" ::: "memory");
}

// stage stride: A 16384 + B 8192 = 24576; 3 stages = 73728
#define TG_STAGE 24576
#define TG_SMEM_BYTES (3*TG_STAGE)

// ---------------- bf16 HMMA GEMM (128x64 tile, 3-stage pipeline) ----------------
// C = act(A[M,K] @ Bt[N,K]^T + bias) (+res). M%128==0, N%64==0, K%64==0.
__global__ void __launch_bounds__(256, 2) tgemm_kernel(
    const __nv_bfloat16* __restrict__ A, const __nv_bfloat16* __restrict__ Bt,
    const float* __restrict__ bias, const float* __restrict__ res,
    float* __restrict__ Cf, __nv_bfloat16* __restrict__ Cb,
    int M, int N, int K, int act, int* __restrict__ kmaxOut)
{
    extern __shared__ __nv_bfloat16 sm[];
    const uint32_t base = smem_u32(sm);
    __shared__ int smax[8];

    const int tid = threadIdx.x;
    const int wid = tid >> 5, lane = tid & 31;
    const int wm = wid & 3, wn = wid >> 2;
    const int row0 = blockIdx.y * 128, col0 = blockIdx.x * 64;
    const int tileid = lane >> 3, rit = lane & 7;
    const int gid = lane >> 2, tig = lane & 3;

    if (kmaxOut && tid < 8) smax[tid] = INT_MIN;

    float acc[2][4][4];
    #pragma unroll
    for (int mt = 0; mt < 2; mt++)
        #pragma unroll
        for (int j = 0; j < 4; j++)
            #pragma unroll
            for (int r = 0; r < 4; r++) acc[mt][j][r] = 0.f;

    const int nch = K >> 6;
    const __nv_bfloat16* Arow = A + (size_t)row0 * K;
    const __nv_bfloat16* Brow = Bt + (size_t)col0 * K;

    #pragma unroll
    for (int s = 0; s < 3; s++) {
        if (s < nch) {
            const int k0 = s << 6;
            const uint32_t aS = base + s * TG_STAGE;
            const uint32_t bS = aS + 16384;
            #pragma unroll
            for (int i = 0; i < 4; i++) {
                int lin = tid + i * 256;
                int r = lin >> 3, c8 = lin & 7;
                cp_async16(aS + SWZ(r * 128 + c8 * 16), Arow + (size_t)r * K + k0 + c8 * 8);
            }
            #pragma unroll
            for (int i = 0; i < 2; i++) {
                int lin = tid + i * 256;
                int r = lin >> 3, c8 = lin & 7;
                cp_async16(bS + SWZ(r * 128 + c8 * 16), Brow + (size_t)r * K + k0 + c8 * 8);
            }
        }
        cp_commit();
    }

    int stg = 0;
    for (int c = 0; c < nch; c++) {
        cp_wait2();
        __syncthreads();
        const uint32_t aB = base + stg * TG_STAGE;
        const uint32_t bB = aB + 16384;
        #pragma unroll
        for (int kk = 0; kk < 4; kk++) {
            uint32_t af[2][4];
            #pragma unroll
            for (int mt = 0; mt < 2; mt++) {
                int off = (wm * 32 + mt * 16 + (tileid & 1) * 8 + rit) * 128
                          + kk * 32 + (tileid >> 1) * 16;
                ldmatrix4(af[mt], aB + SWZ(off));
            }
            uint32_t bf[2][4];
            #pragma unroll
            for (int nt = 0; nt < 2; nt++) {
                int off = (wn * 32 + nt * 16 + (tileid & 1) * 8 + rit) * 128
                          + kk * 32 + (tileid >> 1) * 16;
                ldmatrix4(bf[nt], bB + SWZ(off));
            }
            #pragma unroll
            for (int mt = 0; mt < 2; mt++)
                #pragma unroll
                for (int j = 0; j < 4; j++) {
                    int nt = j >> 1, sel = j & 1;
                    mma16816(acc[mt][j], af[mt], bf[nt][sel], bf[nt][2 + sel]);
                }
        }
        __syncthreads();
        if (c + 3 < nch) {
            const int k0 = (c + 3) << 6;
            const uint32_t aS = base + stg * TG_STAGE;
            const uint32_t bS = aS + 16384;
            #pragma unroll
            for (int i = 0; i < 4; i++) {
                int lin = tid + i * 256;
                int r = lin >> 3, c8 = lin & 7;
                cp_async16(aS + SWZ(r * 128 + c8 * 16), Arow + (size_t)r * K + k0 + c8 * 8);
            }
            #pragma unroll
            for (int i = 0; i < 2; i++) {
                int lin = tid + i * 256;
                int r = lin >> 3, c8 = lin & 7;
                cp_async16(bS + SWZ(r * 128 + c8 * 16), Brow + (size_t)r * K + k0 + c8 * 8);
            }
        }
        cp_commit();
        stg = (stg + 1) == 3 ? 0 : stg + 1;
    }

    // epilogue
    float kmv[2] = {-1e30f, -1e30f};
    const int b0 = row0 / RPB;
    #pragma unroll
    for (int mt = 0; mt < 2; mt++) {
        #pragma unroll
        for (int j = 0; j < 4; j++) {
            #pragma unroll
            for (int half = 0; half < 2; half++) {
                int r = row0 + wm * 32 + mt * 16 + gid + half * 8;
                int cidx = col0 + wn * 32 + j * 8 + tig * 2;
                float v0 = acc[mt][j][half * 2 + 0];
                float v1 = acc[mt][j][half * 2 + 1];
                if (kmaxOut) {
                    int bs = (r / RPB == b0) ? 0 : 1;
                    float m = -1e30f;
                    if (cidx < MF) m = v0;
                    if (cidx + 1 < MF) m = fmaxf(m, v1);
                    kmv[bs] = fmaxf(kmv[bs], m);
                }
                if (bias) { v0 += bias[cidx]; v1 += bias[cidx + 1]; }
                if (act == 1) { v0 = gelu_tanh(v0); v1 = gelu_tanh(v1); }
                if (res) {
                    float2 r2 = *(const float2*)(res + (size_t)r * N + cidx);
                    v0 += r2.x; v1 += r2.y;
                }
                if (Cf) *(float2*)(Cf + (size_t)r * N + cidx) = make_float2(v0, v1);
                if (Cb) *(__nv_bfloat162*)(Cb + (size_t)r * N + cidx) = __floats2bfloat162_rn(v0, v1);
            }
        }
    }
    if (kmaxOut) {
        int h = (row0 + wm * 32 + gid) & 3;
        if (kmv[0] > -1e29f) atomicMax(&smax[h], f2o(kmv[0]));
        if (kmv[1] > -1e29f) atomicMax(&smax[4 + h], f2o(kmv[1]));
        __syncthreads();
        if (tid < 8) {
            int bsel = tid >> 2, hh = tid & 3;
            int bb = b0 + bsel;
            if (smax[tid] != INT_MIN && bb < BB)
                atomicMax(&kmaxOut[bb * HEADS + hh], smax[tid]);
        }
    }
}

// ---------------- batched bf16 HMMA GEMM (128x64 tile, pipelined) ----------------
// Stores guarded by r < mValid AND cidx < nStore.
__global__ void __launch_bounds__(256, 2) btgemm_kernel(
    const __nv_bfloat16* __restrict__ A, size_t aBS, int aClamp,
    const __nv_bfloat16* __restrict__ Bt, size_t bBS,
    float* __restrict__ Cf, __nv_bfloat16* __restrict__ Cb, size_t cBS,
    int ldc, int K, int mValid, int nStore)
{
    extern __shared__ __nv_bfloat16 sm[];
    const uint32_t base = smem_u32(sm);

    const int tid = threadIdx.x;
    const int wid = tid >> 5, lane = tid & 31;
    const int wm = wid & 3, wn = wid >> 2;
    const int row0 = blockIdx.y * 128, col0 = blockIdx.x * 64;
    const int tileid = lane >> 3, rit = lane & 7;
    const int gid = lane >> 2, tig = lane & 3;
    const int bh = blockIdx.z;

    const __nv_bfloat16* Ab = A + (size_t)bh * aBS;
    const __nv_bfloat16* Bb = Bt + (size_t)bh * bBS + (size_t)col0 * K;

    float acc[2][4][4];
    #pragma unroll
    for (int mt = 0; mt < 2; mt++)
        #pragma unroll
        for (int j = 0; j < 4; j++)
            #pragma unroll
            for (int r = 0; r < 4; r++) acc[mt][j][r] = 0.f;

    const int nch = K >> 6;
    #pragma unroll
    for (int s = 0; s < 3; s++) {
        if (s < nch) {
            const int k0 = s << 6;
            const uint32_t aS = base + s * TG_STAGE;
            const uint32_t bS = aS + 16384;
            #pragma unroll
            for (int i = 0; i < 4; i++) {
                int lin = tid + i * 256;
                int r = lin >> 3, c8 = lin & 7;
                int rg = min(row0 + r, aClamp);
                cp_async16(aS + SWZ(r * 128 + c8 * 16), Ab + (size_t)rg * K + k0 + c8 * 8);
            }
            #pragma unroll
            for (int i = 0; i < 2; i++) {
                int lin = tid + i * 256;
                int r = lin >> 3, c8 = lin & 7;
                cp_async16(bS + SWZ(r * 128 + c8 * 16), Bb + (size_t)r * K + k0 + c8 * 8);
            }
        }
        cp_commit();
    }

    int stg = 0;
    for (int c = 0; c < nch; c++) {
        cp_wait2();
        __syncthreads();
        const uint32_t aB = base + stg * TG_STAGE;
        const uint32_t bB = aB + 16384;
        #pragma unroll
        for (int kk = 0; kk < 4; kk++) {
            uint32_t af[2][4];
            #pragma unroll
            for (int mt = 0; mt < 2; mt++) {
                int off = (wm * 32 + mt * 16 + (tileid & 1) * 8 + rit) * 128
                          + kk * 32 + (tileid >> 1) * 16;
                ldmatrix4(af[mt], aB + SWZ(off));
            }
            uint32_t bf[2][4];
            #pragma unroll
            for (int nt = 0; nt < 2; nt++) {
                int off = (wn * 32 + nt * 16 + (tileid & 1) * 8 + rit) * 128
                          + kk * 32 + (tileid >> 1) * 16;
                ldmatrix4(bf[nt], bB + SWZ(off));
            }
            #pragma unroll
            for (int mt = 0; mt < 2; mt++)
                #pragma unroll
                for (int j = 0; j < 4; j++) {
                    int nt = j >> 1, sel = j & 1;
                    mma16816(acc[mt][j], af[mt], bf[nt][sel], bf[nt][2 + sel]);
                }
        }
        __syncthreads();
        if (c + 3 < nch) {
            const int k0 = (c + 3) << 6;
            const uint32_t aS = base + stg * TG_STAGE;
            const uint32_t bS = aS + 16384;
            #pragma unroll
            for (int i = 0; i < 4; i++) {
                int lin = tid + i * 256;
                int r = lin >> 3, c8 = lin & 7;
                int rg = min(row0 + r, aClamp);
                cp_async16(aS + SWZ(r * 128 + c8 * 16), Ab + (size_t)rg * K + k0 + c8 * 8);
            }
            #pragma unroll
            for (int i = 0; i < 2; i++) {
                int lin = tid + i * 256;
                int r = lin >> 3, c8 = lin & 7;
                cp_async16(bS + SWZ(r * 128 + c8 * 16), Bb + (size_t)r * K + k0 + c8 * 8);
            }
        }
        cp_commit();
        stg = (stg + 1) == 3 ? 0 : stg + 1;
    }

    float* Cfb = Cf ? Cf + (size_t)bh * cBS : nullptr;
    __nv_bfloat16* Cbb = Cb ? Cb + (size_t)bh * cBS : nullptr;
    #pragma unroll
    for (int mt = 0; mt < 2; mt++) {
        #pragma unroll
        for (int j = 0; j < 4; j++) {
            #pragma unroll
            for (int half = 0; half < 2; half++) {
                int r = row0 + wm * 32 + mt * 16 + gid + half * 8;
                if (r >= mValid) continue;
                int cidx = col0 + wn * 32 + j * 8 + tig * 2;
                if (cidx >= nStore) continue;
                float v0 = acc[mt][j][half * 2 + 0];
                float v1 = acc[mt][j][half * 2 + 1];
                if (Cfb) *(float2*)(Cfb + (size_t)r * ldc + cidx) = make_float2(v0, v1);
                if (Cbb) *(__nv_bfloat162*)(Cbb + (size_t)r * ldc + cidx) = __floats2bfloat162_rn(v0, v1);
            }
        }
    }
}

// ---------------- prep kernels ----------------
__global__ void f2b_kernel(const float* __restrict__ a, __nv_bfloat16* __restrict__ b, size_t n) {
    size_t i = (size_t)blockIdx.x * blockDim.x + threadIdx.x;
    if (i < n) b[i] = __float2bfloat16(a[i]);
}

__global__ void wtrans_kernel(const float* __restrict__ W, __nv_bfloat16* __restrict__ Wt,
                              int K, int N) {
    __shared__ float t[32][33];
    int k0 = blockIdx.y * 32, n0 = blockIdx.x * 32;
    int tx = threadIdx.x, ty = threadIdx.y;
    #pragma unroll
    for (int i = 0; i < 32; i += 8)
        t[ty + i][tx] = W[(size_t)(k0 + ty + i) * N + n0 + tx];
    __syncthreads();
    #pragma unroll
    for (int i = 0; i < 32; i += 8)
        Wt[(size_t)(n0 + ty + i) * K + k0 + tx] = __float2bfloat16(t[tx][ty + i]);
}

__global__ void projb_kernel(const float* __restrict__ proj, __nv_bfloat16* __restrict__ pTb) {
    int i = blockIdx.x * 256 + threadIdx.x;
    if (i >= MP * 64) return;
    int m = i >> 6, d = i & 63;
    pTb[i] = __float2bfloat16((m < MF) ? proj[m * 64 + d] * NORM : 0.f);
}

// ---------------- layernorm (warp-per-row, 8 rows/block) ----------------
__global__ void __launch_bounds__(256) ln8_bf16_kernel(
    const float* __restrict__ x, const float* __restrict__ g,
    const float* __restrict__ b, __nv_bfloat16* __restrict__ y)
{
    int warp = threadIdx.x >> 5, lane = threadIdx.x & 31;
    int row = blockIdx.x * 8 + warp;
    const float* xr = x + (size_t)row * DIM + lane * 8;
    float4 a0 = *(const float4*)xr;
    float4 a1 = *(const float4*)(xr + 4);
    float v[8] = {a0.x, a0.y, a0.z, a0.w, a1.x, a1.y, a1.z, a1.w};

    float s = ((v[0] + v[1]) + (v[2] + v[3])) + ((v[4] + v[5]) + (v[6] + v[7]));
    #pragma unroll
    for (int o = 16; o; o >>= 1) s += __shfl_xor_sync(0xFFFFFFFFu, s, o);
    float mu = s * (1.0f / DIM);

    float q = 0.f;
    #pragma unroll
    for (int i = 0; i < 8; i++) {
        float d = v[i] - mu;
        v[i] = d;
        q = fmaf(d, d, q);
    }
    #pragma unroll
    for (int o = 16; o; o >>= 1) q += __shfl_xor_sync(0xFFFFFFFFu, q, o);
    float rs = rsqrtf(q * (1.0f / DIM) + LN_EPS);

    float4 g0 = *(const float4*)(g + lane * 8);
    float4 g1 = *(const float4*)(g + lane * 8 + 4);
    float4 b0 = *(const float4*)(b + lane * 8);
    float4 b1 = *(const float4*)(b + lane * 8 + 4);
    float gg[8] = {g0.x, g0.y, g0.z, g0.w, g1.x, g1.y, g1.z, g1.w};
    float bb2[8] = {b0.x, b0.y, b0.z, b0.w, b1.x, b1.y, b1.z, b1.w};

    __nv_bfloat162 o2[4];
    #pragma unroll
    for (int i = 0; i < 4; i++) {
        float r0 = v[2 * i] * rs * gg[2 * i] + bb2[2 * i];
        float r1 = v[2 * i + 1] * rs * gg[2 * i + 1] + bb2[2 * i + 1];
        o2[i] = __floats2bfloat162_rn(r0, r1);
    }
    *(uint4*)(y + (size_t)row * DIM + lane * 8) = *(uint4*)o2;
}

__global__ void ln_f32_kernel(const float* __restrict__ x, const float* __restrict__ g,
                              const float* __restrict__ b, float* __restrict__ y)
{
    int row = blockIdx.x;
    int t = threadIdx.x;
    float v = x[(size_t)row * DIM + t];
    float mu = blockReduceSum256(v) * (1.0f / DIM);
    float d = v - mu;
    float var = blockReduceSum256(d * d) * (1.0f / DIM);
    y[(size_t)row * DIM + t] = d * rsqrtf(var + LN_EPS) * g[t] + b[t];
}

// ---------------- FAVOR+ passes ----------------
__global__ void qexp_kernel(const __nv_bfloat16* __restrict__ qbuf, const float* __restrict__ dd,
                            __nv_bfloat16* __restrict__ qpB)
{
    int w = (blockIdx.x * 256 + threadIdx.x) >> 5;
    int lane = threadIdx.x & 31;
    if (w >= RH) return;
    const __nv_bfloat16* qr = qbuf + (size_t)w * 64;
    float a = __bfloat162float(qr[lane]), b2 = __bfloat162float(qr[lane + 32]);
    float s = a * a + b2 * b2;
    #pragma unroll
    for (int o = 16; o; o >>= 1) s += __shfl_xor_sync(0xFFFFFFFFu, s, o);
    float diag = 0.0625f * s;
    const float* row = dd + (size_t)w * MP;
    float vv[9], mx = -1e30f;
    #pragma unroll
    for (int i = 0; i < 9; i++) {
        int m = lane + 32 * i;
        vv[i] = (m < MF) ? row[m] : -1e30f;
        mx = fmaxf(mx, vv[i]);
    }
    #pragma unroll
    for (int o = 16; o; o >>= 1) mx = fmaxf(mx, __shfl_xor_sync(0xFFFFFFFFu, mx, o));

    int b = w / RPB;
    int rem = w - b * RPB;
    int n = rem >> 2, h = rem & 3;
    __nv_bfloat16* orow = qpB + ((size_t)(b * HEADS + h) * NN + n) * MP;
    #pragma unroll
    for (int i = 0; i < 9; i++) {
        int m = lane + 32 * i;
        if (m < MF) orow[m] = __float2bfloat16(RATIO * (__expf(vv[i] - diag - mx) + KEPS));
        else orow[m] = __float2bfloat16(0.f);
    }
    orow[lane + 288] = __float2bfloat16(0.f);
}

__global__ void kmax_init_kernel(int* __restrict__ kmax) {
    int i = blockIdx.x * blockDim.x + threadIdx.x;
    if (i < BH) kmax[i] = INT_MIN;
}

// kexp + transpose
__global__ void __launch_bounds__(256) kexpT_kernel(
    const __nv_bfloat16* __restrict__ kbuf, const float* __restrict__ dd,
    const int* __restrict__ kmax, __nv_bfloat16* __restrict__ kpT)
{
    __shared__ float s[32][325];
    __shared__ float diag[32];
    int bh = blockIdx.x, b = bh >> 2, h = bh & 3;
    int n0 = blockIdx.y * 32;
    int tid = threadIdx.x;
    int wid = tid >> 5, lane = tid & 31;

    #pragma unroll
    for (int ii = 0; ii < 4; ii++) {
        int n_l = wid * 4 + ii;
        int n_g = n0 + n_l;
        float sum = 0.f;
        if (n_g < NN) {
            const __nv_bfloat16* kr = kbuf + ((size_t)(b * NN + n_g)) * DIM + h * 64;
            float a = __bfloat162float(kr[lane]), b2 = __bfloat162float(kr[lane + 32]);
            sum = a * a + b2 * b2;
        }
        #pragma unroll
        for (int o = 16; o; o >>= 1) sum += __shfl_xor_sync(0xFFFFFFFFu, sum, o);
        if (lane == 0) diag[n_l] = 0.0625f * sum;
    }

    #pragma unroll
    for (int it = 0; it < 4; it++) {
        int n_l = (tid >> 5) + 8 * it;
        int n_g = n0 + n_l;
        const float* row = dd + ((size_t)((b * NN + min(n_g, NN - 1)) * HEADS) + h) * MP;
        bool ok = n_g < NN;
        #pragma unroll
        for (int j = 0; j < 10; j++) {
            int m = lane + 32 * j;
            s[n_l][m] = ok ? row[m] : 0.f;
        }
    }
    __syncthreads();

    float stab = o2f(kmax[bh]);
    int n_g = n0 + lane;
    bool nok = n_g < NN;
    float dg = diag[lane];
    __nv_bfloat16* base = kpT + (size_t)bh * MP * NP + n0 + lane;
    for (int m = wid; m < MP; m += 8) {
        float val = 0.f;
        if (m < MF && nok)
            val = RATIO * (__expf(s[lane][m] - dg - stab) + KEPS);
        base[(size_t)m * NP] = __float2bfloat16(val);
    }
}

// v transpose (bf16 in): vAugT[bh][d][n], d=64 row = ones
__global__ void __launch_bounds__(256) vtrans_kernel(
    const __nv_bfloat16* __restrict__ v, __nv_bfloat16* __restrict__ vT)
{
    __shared__ float t[32][65];
    int bh = blockIdx.x, b = bh >> 2, h = bh & 3;
    int tid = threadIdx.x;
    int lane = tid & 31;
    __nv_bfloat16* vb = vT + (size_t)bh * 128 * NP;

    for (int it = 0; it < 10; it++) {
        int n0 = it * 32;
        int d = tid & 63;
        #pragma unroll
        for (int sub = 0; sub < 8; sub++) {
            int n_l = (tid >> 6) + 4 * sub;
            int n_g = n0 + n_l;
            t[n_l][d] = (n_g < NN) ?
                __bfloat162float(v[((size_t)(b * NN + n_g)) * DIM + h * 64 + d]) : 0.f;
        }
        __syncthreads();
        int dcol = tid >> 5;
        #pragma unroll
        for (int j = 0; j < 8; j++) {
            int d2 = dcol + 8 * j;
            vb[(size_t)d2 * NP + n0 + lane] = __float2bfloat16(t[lane][d2]);
        }
        __syncthreads();
    }
    for (int idx = tid; idx < 64 * NP; idx += 256) {
        int d = 64 + idx / NP, n = idx % NP;
        float val = (d == 64 && n < NN) ? 1.f : 0.f;
        vb[(size_t)d * NP + n] = __float2bfloat16(val);
    }
}

__global__ void divout_kernel(const float* __restrict__ outA, __nv_bfloat16* __restrict__ ob)
{
    int bh = blockIdx.x, b = bh >> 2, h = bh & 3;
    const float* base = outA + (size_t)bh * NN * 128;
    for (int idx = threadIdx.x; idx < NN * 64; idx += 256) {
        int n = idx >> 6, d = idx & 63;
        float num = base[(size_t)n * 128 + d];
        float den = base[(size_t)n * 128 + 64];
        ob[((size_t)(b * NN + n)) * DIM + h * 64 + d] = __float2bfloat16(num / den);
    }
}

// ---------------- pooling & head ----------------
__global__ void pool_kernel(const float* __restrict__ h, float* __restrict__ pooled)
{
    int b = blockIdx.x, c = threadIdx.x;
    const float* p = h + (size_t)b * NN * DIM + c;
    float s0 = 0.f, s1 = 0.f, s2 = 0.f, s3 = 0.f;
    for (int n = 0; n < NN; n += 4) {
        s0 += p[(size_t)(n + 0) * DIM];
        s1 += p[(size_t)(n + 1) * DIM];
        s2 += p[(size_t)(n + 2) * DIM];
        s3 += p[(size_t)(n + 3) * DIM];
    }
    pooled[b * DIM + c] = ((s0 + s1) + (s2 + s3)) * (1.0f / NN);
}

__global__ void head1_kernel(const float* __restrict__ z, const float* __restrict__ w,
                             const float* __restrict__ bias, float* __restrict__ z1)
{
    __shared__ float zs[DIM];
    int b = blockIdx.x, j = threadIdx.x;
    for (int c = j; c < DIM; c += 128) zs[c] = z[b * DIM + c];
    __syncthreads();
    float s0 = 0.f, s1 = 0.f, s2 = 0.f, s3 = 0.f;
    #pragma unroll 1
    for (int c = 0; c < DIM; c += 4) {
        s0 = fmaf(zs[c + 0], w[(c + 0) * 128 + j], s0);
        s1 = fmaf(zs[c + 1], w[(c + 1) * 128 + j], s1);
        s2 = fmaf(zs[c + 2], w[(c + 2) * 128 + j], s2);
        s3 = fmaf(zs[c + 3], w[(c + 3) * 128 + j], s3);
    }
    z1[b * 128 + j] = fmaxf(((s0 + s1) + (s2 + s3)) + bias[j], 0.f);
}

__global__ void head2_kernel(const float* __restrict__ z1, const float* __restrict__ w,
                             const float* __restrict__ bias, float* __restrict__ out)
{
    __shared__ float sh[4];
    int b = blockIdx.x, j = threadIdx.x;
    float s = z1[b * 128 + j] * w[j];
    #pragma unroll
    for (int o = 16; o; o >>= 1) s += __shfl_xor_sync(0xFFFFFFFFu, s, o);
    if ((j & 31) == 0) sh[j >> 5] = s;
    __syncthreads();
    if (j == 0) {
        float t = sh[0] + sh[1] + sh[2] + sh[3] + bias[0];
        out[b] = 1.0f / (1.0f + __expf(-t));
    }
}

// ---------------- host ----------------
template <typename T> static T* symaddr(const void* sym) {
    void* p = nullptr;
    cudaGetSymbolAddress(&p, sym);
    return (T*)p;
}

extern "C" void kernel_launch(void* const* d_in, const int* in_sizes, int n_in,
                              void* d_out, int out_size)
{
    const float* x     = (const float*)d_in[0];
    const float* w_in  = (const float*)d_in[1];
    const float* b_in  = (const float*)d_in[2];
    const float* proj  = (const float*)d_in[3];
    const float* ln1_g = (const float*)d_in[4];
    const float* ln1_b = (const float*)d_in[5];
    const float* wq    = (const float*)d_in[6];
    const float* wk    = (const float*)d_in[7];
    const float* wv    = (const float*)d_in[8];
    const float* wo    = (const float*)d_in[9];
    const float* bo    = (const float*)d_in[10];
    const float* ln2_g = (const float*)d_in[11];
    const float* ln2_b = (const float*)d_in[12];
    const float* w1    = (const float*)d_in[13];
    const float* b1    = (const float*)d_in[14];
    const float* w2    = (const float*)d_in[15];
    const float* b2    = (const float*)d_in[16];
    const float* hln_g = (const float*)d_in[17];
    const float* hln_b = (const float*)d_in[18];
    const float* wh1   = (const float*)d_in[19];
    const float* bh1   = (const float*)d_in[20];
    const float* wh2   = (const float*)d_in[21];
    const float* bh2   = (const float*)d_in[22];
    float* out = (float*)d_out;

    float* h    = symaddr<float>(g_h);
    __nv_bfloat16* yb   = symaddr<__nv_bfloat16>(g_yb);
    __nv_bfloat16* qb   = symaddr<__nv_bfloat16>(g_qb);
    __nv_bfloat16* kb   = symaddr<__nv_bfloat16>(g_kb);
    __nv_bfloat16* vb   = symaddr<__nv_bfloat16>(g_vb);
    __nv_bfloat16* ob   = symaddr<__nv_bfloat16>(g_ob);
    __nv_bfloat16* ffhb = symaddr<__nv_bfloat16>(g_ffhb);
    __nv_bfloat16* xb   = symaddr<__nv_bfloat16>(g_xb);
    float* ddq  = symaddr<float>(g_ddq);
    float* ddk  = symaddr<float>(g_ddk);
    __nv_bfloat16* qpB  = symaddr<__nv_bfloat16>(g_qpB);
    __nv_bfloat16* kpT  = symaddr<__nv_bfloat16>(g_kpT);
    __nv_bfloat16* vT   = symaddr<__nv_bfloat16>(g_vT);
    __nv_bfloat16* ctxT = symaddr<__nv_bfloat16>(g_ctxT);
    float* outA = symaddr<float>(g_outA);
    int*   kmx  = symaddr<int>(g_kmax);
    float* pool = symaddr<float>(g_pool);
    float* z    = symaddr<float>(g_z);
    float* z1   = symaddr<float>(g_z1);
    __nv_bfloat16* pTb  = symaddr<__nv_bfloat16>(g_pTb);
    __nv_bfloat16* wInT = symaddr<__nv_bfloat16>(g_wInT);
    __nv_bfloat16* wqT  = symaddr<__nv_bfloat16>(g_wqT);
    __nv_bfloat16* wkT  = symaddr<__nv_bfloat16>(g_wkT);
    __nv_bfloat16* wvT  = symaddr<__nv_bfloat16>(g_wvT);
    __nv_bfloat16* woT  = symaddr<__nv_bfloat16>(g_woT);
    __nv_bfloat16* w1T  = symaddr<__nv_bfloat16>(g_w1T);
    __nv_bfloat16* w2T  = symaddr<__nv_bfloat16>(g_w2T);

    static bool attr_set = false;
    if (!attr_set) {
        cudaFuncSetAttribute(tgemm_kernel, cudaFuncAttributeMaxDynamicSharedMemorySize, TG_SMEM_BYTES);
        cudaFuncSetAttribute(btgemm_kernel, cudaFuncAttributeMaxDynamicSharedMemorySize, TG_SMEM_BYTES);
        attr_set = true;
    }

    dim3 blk256(256);
    dim3 t256(4, ROWS_TOT / 128);       // N=256
    dim3 t1024(16, ROWS_TOT / 128);     // N=1024
    dim3 tdd(5, RH / 128);              // N=320
    dim3 gCtx(5, 1, BH);
    dim3 gAtt(2, 3, BH);

    // ---- prep ----
    f2b_kernel<<<(int)((ROWS_TOT * (size_t)IN_DIM + 255) / 256), 256>>>(x, xb, (size_t)ROWS_TOT * IN_DIM);
    wtrans_kernel<<<dim3(DIM / 32, IN_DIM / 32), dim3(32, 8)>>>(w_in, wInT, IN_DIM, DIM);
    for (int l = 0; l < 2; l++) {
        wtrans_kernel<<<dim3(DIM / 32, DIM / 32), dim3(32, 8)>>>(wq + (size_t)l * DIM * DIM, wqT + (size_t)l * DIM * DIM, DIM, DIM);
        wtrans_kernel<<<dim3(DIM / 32, DIM / 32), dim3(32, 8)>>>(wk + (size_t)l * DIM * DIM, wkT + (size_t)l * DIM * DIM, DIM, DIM);
        wtrans_kernel<<<dim3(DIM / 32, DIM / 32), dim3(32, 8)>>>(wv + (size_t)l * DIM * DIM, wvT + (size_t)l * DIM * DIM, DIM, DIM);
        wtrans_kernel<<<dim3(DIM / 32, DIM / 32), dim3(32, 8)>>>(wo + (size_t)l * DIM * DIM, woT + (size_t)l * DIM * DIM, DIM, DIM);
        wtrans_kernel<<<dim3(FFH / 32, DIM / 32), dim3(32, 8)>>>(w1 + (size_t)l * DIM * FFH, w1T + (size_t)l * DIM * FFH, DIM, FFH);
        wtrans_kernel<<<dim3(DIM / 32, FFH / 32), dim3(32, 8)>>>(w2 + (size_t)l * FFH * DIM, w2T + (size_t)l * FFH * DIM, FFH, DIM);
    }

    tgemm_kernel<<<t256, blk256, TG_SMEM_BYTES>>>(xb, wInT, b_in, nullptr, h, nullptr,
                                                  ROWS_TOT, DIM, IN_DIM, 0, nullptr);

    for (int l = 0; l < 2; l++) {
        // --- attention ---
        ln8_bf16_kernel<<<ROWS_TOT / 8, 256>>>(h, ln1_g + l * DIM, ln1_b + l * DIM, yb);
        tgemm_kernel<<<t256, blk256, TG_SMEM_BYTES>>>(yb, wqT + (size_t)l * DIM * DIM, nullptr, nullptr, nullptr, qb, ROWS_TOT, DIM, DIM, 0, nullptr);
        tgemm_kernel<<<t256, blk256, TG_SMEM_BYTES>>>(yb, wkT + (size_t)l * DIM * DIM, nullptr, nullptr, nullptr, kb, ROWS_TOT, DIM, DIM, 0, nullptr);
        tgemm_kernel<<<t256, blk256, TG_SMEM_BYTES>>>(yb, wvT + (size_t)l * DIM * DIM, nullptr, nullptr, nullptr, vb, ROWS_TOT, DIM, DIM, 0, nullptr);

        projb_kernel<<<(MP * 64 + 255) / 256, 256>>>(proj + (size_t)l * MF * DH, pTb);
        kmax_init_kernel<<<1, 1024>>>(kmx);
        tgemm_kernel<<<tdd, blk256, TG_SMEM_BYTES>>>(qb, pTb, nullptr, nullptr, ddq, nullptr,
                                                     RH, MP, 64, 0, nullptr);
        tgemm_kernel<<<tdd, blk256, TG_SMEM_BYTES>>>(kb, pTb, nullptr, nullptr, ddk, nullptr,
                                                     RH, MP, 64, 0, kmx);

        qexp_kernel<<<RH / 8, 256>>>(qb, ddq, qpB);
        kexpT_kernel<<<dim3(BH, 10), 256>>>(kb, ddk, kmx, kpT);
        vtrans_kernel<<<BH, 256>>>(vb, vT);

        btgemm_kernel<<<gCtx, blk256, TG_SMEM_BYTES>>>(
            vT, (size_t)128 * NP, 127, kpT, (size_t)MP * NP,
            nullptr, ctxT, (size_t)128 * MP, MP, NP, 128, MP);
        btgemm_kernel<<<gAtt, blk256, TG_SMEM_BYTES>>>(
            qpB, (size_t)NN * MP, NN - 1, ctxT, (size_t)128 * MP,
            outA, nullptr, (size_t)NN * 128, 128, MP, NN, 66);

        divout_kernel<<<BH, 256>>>(outA, ob);

        tgemm_kernel<<<t256, blk256, TG_SMEM_BYTES>>>(ob, woT + (size_t)l * DIM * DIM, bo + l * DIM, h,
                                                      h, nullptr, ROWS_TOT, DIM, DIM, 0, nullptr);

        // --- FFN ---
        ln8_bf16_kernel<<<ROWS_TOT / 8, 256>>>(h, ln2_g + l * DIM, ln2_b + l * DIM, yb);
        tgemm_kernel<<<t1024, blk256, TG_SMEM_BYTES>>>(yb, w1T + (size_t)l * DIM * FFH, b1 + l * FFH, nullptr,
                                                       nullptr, ffhb, ROWS_TOT, FFH, DIM, 1, nullptr);
        tgemm_kernel<<<t256, blk256, TG_SMEM_BYTES>>>(ffhb, w2T + (size_t)l * FFH * DIM, b2 + l * DIM, h,
                                                      h, nullptr, ROWS_TOT, DIM, FFH, 0, nullptr);
    }

    pool_kernel<<<BB, 256>>>(h, pool);
    ln_f32_kernel<<<BB, 256>>>(pool, hln_g, hln_b, z);
    head1_kernel<<<BB, 128>>>(z, wh1, bh1, z1);
    head2_kernel<<<BB, 128>>>(z1, wh2, bh2, out);
}

// round 13
// speedup vs baseline: 1.2568x; 1.0447x over previous
#include <cuda_runtime.h>
#include <cuda_bf16.h>
#include <math.h>
#include <limits.h>
#include <stdint.h>

// ---------------- problem constants ----------------
#define BB 256
#define NN 300
#define IN_DIM 1280
#define DIM 256
#define HEADS 4
#define DH 64
#define MF 266            // NB_FEAT
#define MP 320            // padded feature dim
#define NP 320            // padded sequence dim per head
#define FFH 1024
#define ROWS_TOT (BB*NN)  // 76800
#define RH (ROWS_TOT*HEADS) // 307200
#define BH (BB*HEADS)       // 1024
#define RPB (NN*HEADS)      // rows per batch in dd view = 1200

#define LN_EPS 1e-5f
#define KEPS 1e-4f
#define RATIO 0.061314066f
#define NORM 0.35355339059327373f

// ---------------- scratch ----------------
__device__ float          g_h   [ROWS_TOT*DIM];
__device__ __nv_bfloat16  g_yb  [ROWS_TOT*DIM];
__device__ __nv_bfloat16  g_qb  [ROWS_TOT*DIM];
__device__ __nv_bfloat16  g_kb  [ROWS_TOT*DIM];
__device__ __nv_bfloat16  g_vb  [ROWS_TOT*DIM];
__device__ __nv_bfloat16  g_ob  [ROWS_TOT*DIM];
__device__ __nv_bfloat16  g_ffhb[ROWS_TOT*FFH];
__device__ __nv_bfloat16  g_xb  [ROWS_TOT*IN_DIM];
__device__ __nv_bfloat16  g_qpB [(size_t)BH*NN*MP];
__device__ __nv_bfloat16  g_kpB [(size_t)BH*NN*MP];
__device__ __nv_bfloat16  g_kpT [(size_t)BH*MP*NP];
__device__ __nv_bfloat16  g_vT  [(size_t)BH*128*NP];
__device__ __nv_bfloat16  g_ctxT[(size_t)BH*128*MP];
__device__ float          g_outA[(size_t)BH*NN*128];
__device__ int            g_kmax[BH];
__device__ float          g_pool[BB*DIM];
__device__ float          g_z   [BB*DIM];
__device__ float          g_z1  [BB*128];
__device__ __nv_bfloat16  g_pTb [MP*64];
__device__ __nv_bfloat16  g_wInT[DIM*IN_DIM];
__device__ __nv_bfloat16  g_wqT [2][DIM*DIM];
__device__ __nv_bfloat16  g_wkT [2][DIM*DIM];
__device__ __nv_bfloat16  g_wvT [2][DIM*DIM];
__device__ __nv_bfloat16  g_woT [2][DIM*DIM];
__device__ __nv_bfloat16  g_w1T [2][FFH*DIM];
__device__ __nv_bfloat16  g_w2T [2][DIM*FFH];

// ---------------- helpers ----------------
__device__ __forceinline__ int f2o(float f) {
    int i = __float_as_int(f);
    return i >= 0 ? i : (i ^ 0x7FFFFFFF);
}
__device__ __forceinline__ float o2f(int i) {
    return __int_as_float(i >= 0 ? i : (i ^ 0x7FFFFFFF));
}
__device__ __forceinline__ float tanh_fast(float a) {
    float t = __expf(-2.0f * fabsf(a));
    float r = (1.0f - t) / (1.0f + t);
    return copysignf(r, a);
}
__device__ __forceinline__ float gelu_tanh(float x) {
    float x3 = x * x * x;
    return 0.5f * x * (1.0f + tanh_fast(0.7978845608028654f * (x + 0.044715f * x3)));
}
__device__ __forceinline__ float blockReduceSum256(float v) {
    __shared__ float sh[8];
    __syncthreads();
    int lane = threadIdx.x & 31, w = threadIdx.x >> 5;
    #pragma unroll
    for (int o = 16; o; o >>= 1) v += __shfl_xor_sync(0xFFFFFFFFu, v, o);
    if (lane == 0) sh[w] = v;
    __syncthreads();
    if (threadIdx.x == 0) {
        float s = 0.f;
        #pragma unroll
        for (int i = 0; i < 8; i++) s += sh[i];
        sh[0] = s;
    }
    __syncthreads();
    return sh[0];
}
__device__ __forceinline__ uint32_t smem_u32(const void* p) {
    uint32_t a;
    asm("{ .reg .u64 t; cvta.to.shared.u64 t, %1; cvt.u32.u64 %0, t; }" : "=r"(a) : "l"(p));
    return a;
}

#define SWZ(off) ((off) ^ (((off) >> 3) & 0x70))

__device__ __forceinline__ void ldmatrix4(uint32_t* r, uint32_t addr) {
    asm volatile("ldmatrix.sync.aligned.m8n8.x4.shared.b16 {%0,%1,%2,%3}, [%4];"
        : "=r"(r[0]), "=r"(r[1]), "=r"(r[2]), "=r"(r[3]) : "r"(addr));
}
__device__ __forceinline__ void mma16816(float* c, const uint32_t* a, uint32_t b0, uint32_t b1) {
    asm volatile(
        "mma.sync.aligned.m16n8k16.row.col.f32.bf16.bf16.f32 "
        "{%0,%1,%2,%3}, {%4,%5,%6,%7}, {%8,%9}, {%0,%1,%2,%3};"
        : "+f"(c[0]), "+f"(c[1]), "+f"(c[2]), "+f"(c[3])
        : "r"(a[0]), "r"(a[1]), "r"(a[2]), "r"(a[3]), "r"(b0), "r"(b1));
}
__device__ __forceinline__ void cp_async16(uint32_t smem, const void* g) {
    asm volatile("cp.async.cg.shared.global [%0], [%1], 16;" :: "r"(smem), "l"(g));
}
__device__ __forceinline__ void cp_commit() {
    asm volatile("cp.async.commit_group;" ::: "memory");
}
__device__ __forceinline__ void cp_wait2() {
    asm volatile("cp.async.wait_group 2;" ::: "memory");
}
__device__ __forceinline__ void cp_wait0() {
    asm volatile("cp.async.wait_group 0;" ::: "memory");
}

// stage stride: A 16384 + B 8192 = 24576; 3 stages = 73728
#define TG_STAGE 24576
#define TG_SMEM_BYTES (3*TG_STAGE)

// ---------------- bf16 HMMA GEMM (128x64 tile, 3-stage pipeline) ----------------
// C = act(A[M,K] @ Bt[N,K]^T + bias) (+res). M%128==0, N%64==0, K%64==0.
__global__ void __launch_bounds__(256, 2) tgemm_kernel(
    const __nv_bfloat16* __restrict__ A, const __nv_bfloat16* __restrict__ Bt,
    const float* __restrict__ bias, const float* __restrict__ res,
    float* __restrict__ Cf, __nv_bfloat16* __restrict__ Cb,
    int M, int N, int K, int act, int* __restrict__ kmaxOut)
{
    extern __shared__ __nv_bfloat16 sm[];
    const uint32_t base = smem_u32(sm);
    __shared__ int smax[8];

    const int tid = threadIdx.x;
    const int wid = tid >> 5, lane = tid & 31;
    const int wm = wid & 3, wn = wid >> 2;
    const int row0 = blockIdx.y * 128, col0 = blockIdx.x * 64;
    const int tileid = lane >> 3, rit = lane & 7;
    const int gid = lane >> 2, tig = lane & 3;

    if (kmaxOut && tid < 8) smax[tid] = INT_MIN;

    float acc[2][4][4];
    #pragma unroll
    for (int mt = 0; mt < 2; mt++)
        #pragma unroll
        for (int j = 0; j < 4; j++)
            #pragma unroll
            for (int r = 0; r < 4; r++) acc[mt][j][r] = 0.f;

    const int nch = K >> 6;
    const __nv_bfloat16* Arow = A + (size_t)row0 * K;
    const __nv_bfloat16* Brow = Bt + (size_t)col0 * K;

    #pragma unroll
    for (int s = 0; s < 3; s++) {
        if (s < nch) {
            const int k0 = s << 6;
            const uint32_t aS = base + s * TG_STAGE;
            const uint32_t bS = aS + 16384;
            #pragma unroll
            for (int i = 0; i < 4; i++) {
                int lin = tid + i * 256;
                int r = lin >> 3, c8 = lin & 7;
                cp_async16(aS + SWZ(r * 128 + c8 * 16), Arow + (size_t)r * K + k0 + c8 * 8);
            }
            #pragma unroll
            for (int i = 0; i < 2; i++) {
                int lin = tid + i * 256;
                int r = lin >> 3, c8 = lin & 7;
                cp_async16(bS + SWZ(r * 128 + c8 * 16), Brow + (size_t)r * K + k0 + c8 * 8);
            }
        }
        cp_commit();
    }

    int stg = 0;
    for (int c = 0; c < nch; c++) {
        cp_wait2();
        __syncthreads();
        const uint32_t aB = base + stg * TG_STAGE;
        const uint32_t bB = aB + 16384;
        #pragma unroll
        for (int kk = 0; kk < 4; kk++) {
            uint32_t af[2][4];
            #pragma unroll
            for (int mt = 0; mt < 2; mt++) {
                int off = (wm * 32 + mt * 16 + (tileid & 1) * 8 + rit) * 128
                          + kk * 32 + (tileid >> 1) * 16;
                ldmatrix4(af[mt], aB + SWZ(off));
            }
            uint32_t bf[2][4];
            #pragma unroll
            for (int nt = 0; nt < 2; nt++) {
                int off = (wn * 32 + nt * 16 + (tileid & 1) * 8 + rit) * 128
                          + kk * 32 + (tileid >> 1) * 16;
                ldmatrix4(bf[nt], bB + SWZ(off));
            }
            #pragma unroll
            for (int mt = 0; mt < 2; mt++)
                #pragma unroll
                for (int j = 0; j < 4; j++) {
                    int nt = j >> 1, sel = j & 1;
                    mma16816(acc[mt][j], af[mt], bf[nt][sel], bf[nt][2 + sel]);
                }
        }
        __syncthreads();
        if (c + 3 < nch) {
            const int k0 = (c + 3) << 6;
            const uint32_t aS = base + stg * TG_STAGE;
            const uint32_t bS = aS + 16384;
            #pragma unroll
            for (int i = 0; i < 4; i++) {
                int lin = tid + i * 256;
                int r = lin >> 3, c8 = lin & 7;
                cp_async16(aS + SWZ(r * 128 + c8 * 16), Arow + (size_t)r * K + k0 + c8 * 8);
            }
            #pragma unroll
            for (int i = 0; i < 2; i++) {
                int lin = tid + i * 256;
                int r = lin >> 3, c8 = lin & 7;
                cp_async16(bS + SWZ(r * 128 + c8 * 16), Brow + (size_t)r * K + k0 + c8 * 8);
            }
        }
        cp_commit();
        stg = (stg + 1) == 3 ? 0 : stg + 1;
    }

    // epilogue
    float kmv[2] = {-1e30f, -1e30f};
    const int b0 = row0 / RPB;
    #pragma unroll
    for (int mt = 0; mt < 2; mt++) {
        #pragma unroll
        for (int j = 0; j < 4; j++) {
            #pragma unroll
            for (int half = 0; half < 2; half++) {
                int r = row0 + wm * 32 + mt * 16 + gid + half * 8;
                int cidx = col0 + wn * 32 + j * 8 + tig * 2;
                float v0 = acc[mt][j][half * 2 + 0];
                float v1 = acc[mt][j][half * 2 + 1];
                if (kmaxOut) {
                    int bs = (r / RPB == b0) ? 0 : 1;
                    float m = -1e30f;
                    if (cidx < MF) m = v0;
                    if (cidx + 1 < MF) m = fmaxf(m, v1);
                    kmv[bs] = fmaxf(kmv[bs], m);
                }
                if (bias) { v0 += bias[cidx]; v1 += bias[cidx + 1]; }
                if (act == 1) { v0 = gelu_tanh(v0); v1 = gelu_tanh(v1); }
                if (res) {
                    float2 r2 = *(const float2*)(res + (size_t)r * N + cidx);
                    v0 += r2.x; v1 += r2.y;
                }
                if (Cf) *(float2*)(Cf + (size_t)r * N + cidx) = make_float2(v0, v1);
                if (Cb) *(__nv_bfloat162*)(Cb + (size_t)r * N + cidx) = __floats2bfloat162_rn(v0, v1);
            }
        }
    }
    if (kmaxOut) {
        int h = (row0 + wm * 32 + gid) & 3;
        if (kmv[0] > -1e29f) atomicMax(&smax[h], f2o(kmv[0]));
        if (kmv[1] > -1e29f) atomicMax(&smax[4 + h], f2o(kmv[1]));
        __syncthreads();
        if (tid < 8) {
            int bsel = tid >> 2, hh = tid & 3;
            int bb = b0 + bsel;
            if (smax[tid] != INT_MIN && bb < BB)
                atomicMax(&kmaxOut[bb * HEADS + hh], smax[tid]);
        }
    }
}

// ---------------- batched bf16 HMMA GEMM (128x64 tile, pipelined) ----------------
__global__ void __launch_bounds__(256, 2) btgemm_kernel(
    const __nv_bfloat16* __restrict__ A, size_t aBS, int aClamp,
    const __nv_bfloat16* __restrict__ Bt, size_t bBS,
    float* __restrict__ Cf, __nv_bfloat16* __restrict__ Cb, size_t cBS,
    int ldc, int K, int mValid, int nStore)
{
    extern __shared__ __nv_bfloat16 sm[];
    const uint32_t base = smem_u32(sm);

    const int tid = threadIdx.x;
    const int wid = tid >> 5, lane = tid & 31;
    const int wm = wid & 3, wn = wid >> 2;
    const int row0 = blockIdx.y * 128, col0 = blockIdx.x * 64;
    const int tileid = lane >> 3, rit = lane & 7;
    const int gid = lane >> 2, tig = lane & 3;
    const int bh = blockIdx.z;

    const __nv_bfloat16* Ab = A + (size_t)bh * aBS;
    const __nv_bfloat16* Bb = Bt + (size_t)bh * bBS + (size_t)col0 * K;

    float acc[2][4][4];
    #pragma unroll
    for (int mt = 0; mt < 2; mt++)
        #pragma unroll
        for (int j = 0; j < 4; j++)
            #pragma unroll
            for (int r = 0; r < 4; r++) acc[mt][j][r] = 0.f;

    const int nch = K >> 6;
    #pragma unroll
    for (int s = 0; s < 3; s++) {
        if (s < nch) {
            const int k0 = s << 6;
            const uint32_t aS = base + s * TG_STAGE;
            const uint32_t bS = aS + 16384;
            #pragma unroll
            for (int i = 0; i < 4; i++) {
                int lin = tid + i * 256;
                int r = lin >> 3, c8 = lin & 7;
                int rg = min(row0 + r, aClamp);
                cp_async16(aS + SWZ(r * 128 + c8 * 16), Ab + (size_t)rg * K + k0 + c8 * 8);
            }
            #pragma unroll
            for (int i = 0; i < 2; i++) {
                int lin = tid + i * 256;
                int r = lin >> 3, c8 = lin & 7;
                cp_async16(bS + SWZ(r * 128 + c8 * 16), Bb + (size_t)r * K + k0 + c8 * 8);
            }
        }
        cp_commit();
    }

    int stg = 0;
    for (int c = 0; c < nch; c++) {
        cp_wait2();
        __syncthreads();
        const uint32_t aB = base + stg * TG_STAGE;
        const uint32_t bB = aB + 16384;
        #pragma unroll
        for (int kk = 0; kk < 4; kk++) {
            uint32_t af[2][4];
            #pragma unroll
            for (int mt = 0; mt < 2; mt++) {
                int off = (wm * 32 + mt * 16 + (tileid & 1) * 8 + rit) * 128
                          + kk * 32 + (tileid >> 1) * 16;
                ldmatrix4(af[mt], aB + SWZ(off));
            }
            uint32_t bf[2][4];
            #pragma unroll
            for (int nt = 0; nt < 2; nt++) {
                int off = (wn * 32 + nt * 16 + (tileid & 1) * 8 + rit) * 128
                          + kk * 32 + (tileid >> 1) * 16;
                ldmatrix4(bf[nt], bB + SWZ(off));
            }
            #pragma unroll
            for (int mt = 0; mt < 2; mt++)
                #pragma unroll
                for (int j = 0; j < 4; j++) {
                    int nt = j >> 1, sel = j & 1;
                    mma16816(acc[mt][j], af[mt], bf[nt][sel], bf[nt][2 + sel]);
                }
        }
        __syncthreads();
        if (c + 3 < nch) {
            const int k0 = (c + 3) << 6;
            const uint32_t aS = base + stg * TG_STAGE;
            const uint32_t bS = aS + 16384;
            #pragma unroll
            for (int i = 0; i < 4; i++) {
                int lin = tid + i * 256;
                int r = lin >> 3, c8 = lin & 7;
                int rg = min(row0 + r, aClamp);
                cp_async16(aS + SWZ(r * 128 + c8 * 16), Ab + (size_t)rg * K + k0 + c8 * 8);
            }
            #pragma unroll
            for (int i = 0; i < 2; i++) {
                int lin = tid + i * 256;
                int r = lin >> 3, c8 = lin & 7;
                cp_async16(bS + SWZ(r * 128 + c8 * 16), Bb + (size_t)r * K + k0 + c8 * 8);
            }
        }
        cp_commit();
        stg = (stg + 1) == 3 ? 0 : stg + 1;
    }

    float* Cfb = Cf ? Cf + (size_t)bh * cBS : nullptr;
    __nv_bfloat16* Cbb = Cb ? Cb + (size_t)bh * cBS : nullptr;
    #pragma unroll
    for (int mt = 0; mt < 2; mt++) {
        #pragma unroll
        for (int j = 0; j < 4; j++) {
            #pragma unroll
            for (int half = 0; half < 2; half++) {
                int r = row0 + wm * 32 + mt * 16 + gid + half * 8;
                if (r >= mValid) continue;
                int cidx = col0 + wn * 32 + j * 8 + tig * 2;
                if (cidx >= nStore) continue;
                float v0 = acc[mt][j][half * 2 + 0];
                float v1 = acc[mt][j][half * 2 + 1];
                if (Cfb) *(float2*)(Cfb + (size_t)r * ldc + cidx) = make_float2(v0, v1);
                if (Cbb) *(__nv_bfloat162*)(Cbb + (size_t)r * ldc + cidx) = __floats2bfloat162_rn(v0, v1);
            }
        }
    }
}

// ---------------- fused feature kernel (dd GEMM + exp, no dd buffer) ----------------
// Per CTA: load proj smem once, process 8 tiles of 32 tokens.
// isK=0: per-row max stabilizer; isK=1: global kmax stabilizer.
// out: [BH][NN][MP] bf16 row-major (qpB / kpB).
#define FT_PROJ_BYTES (MP*128)          // 40960
#define FT_ATILE 4096
#define FT_SMEM (FT_PROJ_BYTES + 2*FT_ATILE)   // 49152

__global__ void __launch_bounds__(256, 2) feat_kernel(
    const __nv_bfloat16* __restrict__ src, const __nv_bfloat16* __restrict__ pTb,
    __nv_bfloat16* __restrict__ outp, const int* __restrict__ kmax, int isK)
{
    extern __shared__ __nv_bfloat16 sm[];
    char* smc = (char*)sm;
    const uint32_t projS = smem_u32(sm);
    const uint32_t aS0 = projS + FT_PROJ_BYTES;
    __shared__ int smax[32];
    __shared__ float diag[32];

    const int tid = threadIdx.x;
    const int lane = tid & 31;
    const int wid = tid >> 5;
    const int wm = wid & 1, wn = wid >> 1;        // 2 M-warps x 4 N-warps
    const int tileid = lane >> 3, rit = lane & 7;
    const int gid = lane >> 2, tig = lane & 3;
    const size_t base_tok = (size_t)blockIdx.x * 256;

    // load proj (320 x 64 bf16, SW128)
    for (int i = tid; i < MP * 8; i += 256) {
        int r = i >> 3, c8 = i & 7;
        cp_async16(projS + SWZ(r * 128 + c8 * 16), pTb + (size_t)r * 64 + c8 * 8);
    }
    // load A tile 0
    {
        int r = tid >> 3, c8 = tid & 7;
        cp_async16(aS0 + SWZ(r * 128 + c8 * 16), src + (base_tok + r) * 64 + c8 * 8);
    }
    cp_commit();
    cp_wait0();
    __syncthreads();

    for (int t = 0; t < 8; t++) {
        const int buf = t & 1;
        const uint32_t aB = aS0 + buf * FT_ATILE;
        if (t + 1 < 8) {
            int r = tid >> 3, c8 = tid & 7;
            cp_async16(aS0 + ((t + 1) & 1) * FT_ATILE + SWZ(r * 128 + c8 * 16),
                       src + (base_tok + (t + 1) * 32 + r) * 64 + c8 * 8);
            cp_commit();
        }
        // init smax + diag
        if (tid < 32) smax[tid] = INT_MIN;
        {
            int r = tid >> 3, c8 = tid & 7;
            uint4 d = *(const uint4*)(smc + FT_PROJ_BYTES + buf * FT_ATILE + SWZ(r * 128 + c8 * 16));
            const __nv_bfloat16* pv = (const __nv_bfloat16*)&d;
            float s = 0.f;
            #pragma unroll
            for (int i = 0; i < 8; i++) {
                float f = __bfloat162float(pv[i]);
                s = fmaf(f, f, s);
            }
            #pragma unroll
            for (int o = 4; o; o >>= 1) s += __shfl_xor_sync(0xFFFFFFFFu, s, o);
            if ((lane & 7) == 0) diag[r] = 0.0625f * s;
        }
        __syncthreads();

        // MMA: 32 rows x 320 cols, K=64
        float acc[10][4];
        #pragma unroll
        for (int j = 0; j < 10; j++)
            #pragma unroll
            for (int r = 0; r < 4; r++) acc[j][r] = 0.f;
        #pragma unroll
        for (int kk = 0; kk < 4; kk++) {
            uint32_t af[4];
            {
                int off = (wm * 16 + (tileid & 1) * 8 + rit) * 128
                          + kk * 32 + (tileid >> 1) * 16;
                ldmatrix4(af, aB + SWZ(off));
            }
            uint32_t bf[5][4];
            #pragma unroll
            for (int nt = 0; nt < 5; nt++) {
                int off = (wn * 80 + nt * 16 + (tileid & 1) * 8 + rit) * 128
                          + kk * 32 + (tileid >> 1) * 16;
                ldmatrix4(bf[nt], projS + SWZ(off));
            }
            #pragma unroll
            for (int j = 0; j < 10; j++) {
                int nt = j >> 1, sel = j & 1;
                mma16816(acc[j], af, bf[nt][sel], bf[nt][2 + sel]);
            }
        }

        if (!isK) {
            float mx0 = -1e30f, mx8 = -1e30f;
            #pragma unroll
            for (int j = 0; j < 10; j++) {
                int cb = wn * 80 + j * 8 + tig * 2;
                if (cb < MF)     { mx0 = fmaxf(mx0, acc[j][0]); mx8 = fmaxf(mx8, acc[j][2]); }
                if (cb + 1 < MF) { mx0 = fmaxf(mx0, acc[j][1]); mx8 = fmaxf(mx8, acc[j][3]); }
            }
            #pragma unroll
            for (int o = 2; o; o >>= 1) {
                mx0 = fmaxf(mx0, __shfl_xor_sync(0xFFFFFFFFu, mx0, o));
                mx8 = fmaxf(mx8, __shfl_xor_sync(0xFFFFFFFFu, mx8, o));
            }
            if (tig == 0) {
                atomicMax(&smax[wm * 16 + gid], f2o(mx0));
                atomicMax(&smax[wm * 16 + gid + 8], f2o(mx8));
            }
        }
        __syncthreads();

        // epilogue: exp + store
        {
            int r0l = wm * 16 + gid, r8l = r0l + 8;
            size_t w0 = base_tok + t * 32 + r0l;
            size_t w8 = w0 + 8;
            float dg0 = diag[r0l], dg8 = diag[r8l];
            float st0, st8;
            int b0v = (int)(w0 / RPB), rem0 = (int)(w0 - (size_t)b0v * RPB);
            int b8v = (int)(w8 / RPB), rem8 = (int)(w8 - (size_t)b8v * RPB);
            if (isK) {
                st0 = o2f(kmax[b0v * HEADS + (rem0 & 3)]);
                st8 = o2f(kmax[b8v * HEADS + (rem8 & 3)]);
            } else {
                st0 = o2f(smax[r0l]);
                st8 = o2f(smax[r8l]);
            }
            __nv_bfloat16* p0 = outp + ((size_t)(b0v * HEADS + (rem0 & 3)) * NN + (rem0 >> 2)) * MP;
            __nv_bfloat16* p8 = outp + ((size_t)(b8v * HEADS + (rem8 & 3)) * NN + (rem8 >> 2)) * MP;
            #pragma unroll
            for (int j = 0; j < 10; j++) {
                int cb = wn * 80 + j * 8 + tig * 2;
                float a0 = (cb < MF)     ? RATIO * (__expf(acc[j][0] - dg0 - st0) + KEPS) : 0.f;
                float a1 = (cb + 1 < MF) ? RATIO * (__expf(acc[j][1] - dg0 - st0) + KEPS) : 0.f;
                float c0 = (cb < MF)     ? RATIO * (__expf(acc[j][2] - dg8 - st8) + KEPS) : 0.f;
                float c1 = (cb + 1 < MF) ? RATIO * (__expf(acc[j][3] - dg8 - st8) + KEPS) : 0.f;
                *(__nv_bfloat162*)(p0 + cb) = __floats2bfloat162_rn(a0, a1);
                *(__nv_bfloat162*)(p8 + cb) = __floats2bfloat162_rn(c0, c1);
            }
        }
        if (t + 1 < 8) {
            cp_wait0();
        }
        __syncthreads();
    }
}

// kpB [bh][n][m] -> kpT [bh][m][n] with zero-fill n>=NN
__global__ void ktrans_kernel(const __nv_bfloat16* __restrict__ kpB,
                              __nv_bfloat16* __restrict__ kpT)
{
    __shared__ __nv_bfloat16 s[32][33];
    int bh = blockIdx.z;
    int n0 = blockIdx.x * 32, m0 = blockIdx.y * 32;
    int tx = threadIdx.x, ty = threadIdx.y;    // 32 x 8
    const __nv_bfloat16* src = kpB + (size_t)bh * NN * MP;
    #pragma unroll
    for (int i = 0; i < 32; i += 8) {
        int n = n0 + ty + i;
        s[ty + i][tx] = (n < NN) ? src[(size_t)n * MP + m0 + tx] : __float2bfloat16(0.f);
    }
    __syncthreads();
    __nv_bfloat16* dst = kpT + (size_t)bh * MP * NP;
    #pragma unroll
    for (int i = 0; i < 32; i += 8)
        dst[(size_t)(m0 + ty + i) * NP + n0 + tx] = s[tx][ty + i];
}

// ---------------- prep kernels ----------------
__global__ void f2b_kernel(const float* __restrict__ a, __nv_bfloat16* __restrict__ b, size_t n) {
    size_t i = (size_t)blockIdx.x * blockDim.x + threadIdx.x;
    if (i < n) b[i] = __float2bfloat16(a[i]);
}

__global__ void wtrans_kernel(const float* __restrict__ W, __nv_bfloat16* __restrict__ Wt,
                              int K, int N) {
    __shared__ float t[32][33];
    int k0 = blockIdx.y * 32, n0 = blockIdx.x * 32;
    int tx = threadIdx.x, ty = threadIdx.y;
    #pragma unroll
    for (int i = 0; i < 32; i += 8)
        t[ty + i][tx] = W[(size_t)(k0 + ty + i) * N + n0 + tx];
    __syncthreads();
    #pragma unroll
    for (int i = 0; i < 32; i += 8)
        Wt[(size_t)(n0 + ty + i) * K + k0 + tx] = __float2bfloat16(t[tx][ty + i]);
}

__global__ void projb_kernel(const float* __restrict__ proj, __nv_bfloat16* __restrict__ pTb) {
    int i = blockIdx.x * 256 + threadIdx.x;
    if (i >= MP * 64) return;
    int m = i >> 6, d = i & 63;
    pTb[i] = __float2bfloat16((m < MF) ? proj[m * 64 + d] * NORM : 0.f);
}

// ---------------- layernorm (warp-per-row, 8 rows/block) ----------------
__global__ void __launch_bounds__(256) ln8_bf16_kernel(
    const float* __restrict__ x, const float* __restrict__ g,
    const float* __restrict__ b, __nv_bfloat16* __restrict__ y)
{
    int warp = threadIdx.x >> 5, lane = threadIdx.x & 31;
    int row = blockIdx.x * 8 + warp;
    const float* xr = x + (size_t)row * DIM + lane * 8;
    float4 a0 = *(const float4*)xr;
    float4 a1 = *(const float4*)(xr + 4);
    float v[8] = {a0.x, a0.y, a0.z, a0.w, a1.x, a1.y, a1.z, a1.w};

    float s = ((v[0] + v[1]) + (v[2] + v[3])) + ((v[4] + v[5]) + (v[6] + v[7]));
    #pragma unroll
    for (int o = 16; o; o >>= 1) s += __shfl_xor_sync(0xFFFFFFFFu, s, o);
    float mu = s * (1.0f / DIM);

    float q = 0.f;
    #pragma unroll
    for (int i = 0; i < 8; i++) {
        float d = v[i] - mu;
        v[i] = d;
        q = fmaf(d, d, q);
    }
    #pragma unroll
    for (int o = 16; o; o >>= 1) q += __shfl_xor_sync(0xFFFFFFFFu, q, o);
    float rs = rsqrtf(q * (1.0f / DIM) + LN_EPS);

    float4 g0 = *(const float4*)(g + lane * 8);
    float4 g1 = *(const float4*)(g + lane * 8 + 4);
    float4 b0 = *(const float4*)(b + lane * 8);
    float4 b1 = *(const float4*)(b + lane * 8 + 4);
    float gg[8] = {g0.x, g0.y, g0.z, g0.w, g1.x, g1.y, g1.z, g1.w};
    float bb2[8] = {b0.x, b0.y, b0.z, b0.w, b1.x, b1.y, b1.z, b1.w};

    __nv_bfloat162 o2[4];
    #pragma unroll
    for (int i = 0; i < 4; i++) {
        float r0 = v[2 * i] * rs * gg[2 * i] + bb2[2 * i];
        float r1 = v[2 * i + 1] * rs * gg[2 * i + 1] + bb2[2 * i + 1];
        o2[i] = __floats2bfloat162_rn(r0, r1);
    }
    *(uint4*)(y + (size_t)row * DIM + lane * 8) = *(uint4*)o2;
}

__global__ void ln_f32_kernel(const float* __restrict__ x, const float* __restrict__ g,
                              const float* __restrict__ b, float* __restrict__ y)
{
    int row = blockIdx.x;
    int t = threadIdx.x;
    float v = x[(size_t)row * DIM + t];
    float mu = blockReduceSum256(v) * (1.0f / DIM);
    float d = v - mu;
    float var = blockReduceSum256(d * d) * (1.0f / DIM);
    y[(size_t)row * DIM + t] = d * rsqrtf(var + LN_EPS) * g[t] + b[t];
}

__global__ void kmax_init_kernel(int* __restrict__ kmax) {
    int i = blockIdx.x * blockDim.x + threadIdx.x;
    if (i < BH) kmax[i] = INT_MIN;
}

// v transpose (bf16 in): vAugT[bh][d][n], d=64 row = ones
__global__ void __launch_bounds__(256) vtrans_kernel(
    const __nv_bfloat16* __restrict__ v, __nv_bfloat16* __restrict__ vT)
{
    __shared__ float t[32][65];
    int bh = blockIdx.x, b = bh >> 2, h = bh & 3;
    int tid = threadIdx.x;
    int lane = tid & 31;
    __nv_bfloat16* vb = vT + (size_t)bh * 128 * NP;

    for (int it = 0; it < 10; it++) {
        int n0 = it * 32;
        int d = tid & 63;
        #pragma unroll
        for (int sub = 0; sub < 8; sub++) {
            int n_l = (tid >> 6) + 4 * sub;
            int n_g = n0 + n_l;
            t[n_l][d] = (n_g < NN) ?
                __bfloat162float(v[((size_t)(b * NN + n_g)) * DIM + h * 64 + d]) : 0.f;
        }
        __syncthreads();
        int dcol = tid >> 5;
        #pragma unroll
        for (int j = 0; j < 8; j++) {
            int d2 = dcol + 8 * j;
            vb[(size_t)d2 * NP + n0 + lane] = __float2bfloat16(t[lane][d2]);
        }
        __syncthreads();
    }
    for (int idx = tid; idx < 64 * NP; idx += 256) {
        int d = 64 + idx / NP, n = idx % NP;
        float val = (d == 64 && n < NN) ? 1.f : 0.f;
        vb[(size_t)d * NP + n] = __float2bfloat16(val);
    }
}

__global__ void divout_kernel(const float* __restrict__ outA, __nv_bfloat16* __restrict__ ob)
{
    int bh = blockIdx.x, b = bh >> 2, h = bh & 3;
    const float* base = outA + (size_t)bh * NN * 128;
    for (int idx = threadIdx.x; idx < NN * 64; idx += 256) {
        int n = idx >> 6, d = idx & 63;
        float num = base[(size_t)n * 128 + d];
        float den = base[(size_t)n * 128 + 64];
        ob[((size_t)(b * NN + n)) * DIM + h * 64 + d] = __float2bfloat16(num / den);
    }
}

// ---------------- pooling & head ----------------
__global__ void pool_kernel(const float* __restrict__ h, float* __restrict__ pooled)
{
    int b = blockIdx.x, c = threadIdx.x;
    const float* p = h + (size_t)b * NN * DIM + c;
    float s0 = 0.f, s1 = 0.f, s2 = 0.f, s3 = 0.f;
    for (int n = 0; n < NN; n += 4) {
        s0 += p[(size_t)(n + 0) * DIM];
        s1 += p[(size_t)(n + 1) * DIM];
        s2 += p[(size_t)(n + 2) * DIM];
        s3 += p[(size_t)(n + 3) * DIM];
    }
    pooled[b * DIM + c] = ((s0 + s1) + (s2 + s3)) * (1.0f / NN);
}

__global__ void head1_kernel(const float* __restrict__ z, const float* __restrict__ w,
                             const float* __restrict__ bias, float* __restrict__ z1)
{
    __shared__ float zs[DIM];
    int b = blockIdx.x, j = threadIdx.x;
    for (int c = j; c < DIM; c += 128) zs[c] = z[b * DIM + c];
    __syncthreads();
    float s0 = 0.f, s1 = 0.f, s2 = 0.f, s3 = 0.f;
    #pragma unroll 1
    for (int c = 0; c < DIM; c += 4) {
        s0 = fmaf(zs[c + 0], w[(c + 0) * 128 + j], s0);
        s1 = fmaf(zs[c + 1], w[(c + 1) * 128 + j], s1);
        s2 = fmaf(zs[c + 2], w[(c + 2) * 128 + j], s2);
        s3 = fmaf(zs[c + 3], w[(c + 3) * 128 + j], s3);
    }
    z1[b * 128 + j] = fmaxf(((s0 + s1) + (s2 + s3)) + bias[j], 0.f);
}

__global__ void head2_kernel(const float* __restrict__ z1, const float* __restrict__ w,
                             const float* __restrict__ bias, float* __restrict__ out)
{
    __shared__ float sh[4];
    int b = blockIdx.x, j = threadIdx.x;
    float s = z1[b * 128 + j] * w[j];
    #pragma unroll
    for (int o = 16; o; o >>= 1) s += __shfl_xor_sync(0xFFFFFFFFu, s, o);
    if ((j & 31) == 0) sh[j >> 5] = s;
    __syncthreads();
    if (j == 0) {
        float t = sh[0] + sh[1] + sh[2] + sh[3] + bias[0];
        out[b] = 1.0f / (1.0f + __expf(-t));
    }
}

// ---------------- host ----------------
template <typename T> static T* symaddr(const void* sym) {
    void* p = nullptr;
    cudaGetSymbolAddress(&p, sym);
    return (T*)p;
}

extern "C" void kernel_launch(void* const* d_in, const int* in_sizes, int n_in,
                              void* d_out, int out_size)
{
    const float* x     = (const float*)d_in[0];
    const float* w_in  = (const float*)d_in[1];
    const float* b_in  = (const float*)d_in[2];
    const float* proj  = (const float*)d_in[3];
    const float* ln1_g = (const float*)d_in[4];
    const float* ln1_b = (const float*)d_in[5];
    const float* wq    = (const float*)d_in[6];
    const float* wk    = (const float*)d_in[7];
    const float* wv    = (const float*)d_in[8];
    const float* wo    = (const float*)d_in[9];
    const float* bo    = (const float*)d_in[10];
    const float* ln2_g = (const float*)d_in[11];
    const float* ln2_b = (const float*)d_in[12];
    const float* w1    = (const float*)d_in[13];
    const float* b1    = (const float*)d_in[14];
    const float* w2    = (const float*)d_in[15];
    const float* b2    = (const float*)d_in[16];
    const float* hln_g = (const float*)d_in[17];
    const float* hln_b = (const float*)d_in[18];
    const float* wh1   = (const float*)d_in[19];
    const float* bh1   = (const float*)d_in[20];
    const float* wh2   = (const float*)d_in[21];
    const float* bh2   = (const float*)d_in[22];
    float* out = (float*)d_out;

    float* h    = symaddr<float>(g_h);
    __nv_bfloat16* yb   = symaddr<__nv_bfloat16>(g_yb);
    __nv_bfloat16* qb   = symaddr<__nv_bfloat16>(g_qb);
    __nv_bfloat16* kb   = symaddr<__nv_bfloat16>(g_kb);
    __nv_bfloat16* vb   = symaddr<__nv_bfloat16>(g_vb);
    __nv_bfloat16* ob   = symaddr<__nv_bfloat16>(g_ob);
    __nv_bfloat16* ffhb = symaddr<__nv_bfloat16>(g_ffhb);
    __nv_bfloat16* xb   = symaddr<__nv_bfloat16>(g_xb);
    __nv_bfloat16* qpB  = symaddr<__nv_bfloat16>(g_qpB);
    __nv_bfloat16* kpB  = symaddr<__nv_bfloat16>(g_kpB);
    __nv_bfloat16* kpT  = symaddr<__nv_bfloat16>(g_kpT);
    __nv_bfloat16* vT   = symaddr<__nv_bfloat16>(g_vT);
    __nv_bfloat16* ctxT = symaddr<__nv_bfloat16>(g_ctxT);
    float* outA = symaddr<float>(g_outA);
    int*   kmx  = symaddr<int>(g_kmax);
    float* pool = symaddr<float>(g_pool);
    float* z    = symaddr<float>(g_z);
    float* z1   = symaddr<float>(g_z1);
    __nv_bfloat16* pTb  = symaddr<__nv_bfloat16>(g_pTb);
    __nv_bfloat16* wInT = symaddr<__nv_bfloat16>(g_wInT);
    __nv_bfloat16* wqT  = symaddr<__nv_bfloat16>(g_wqT);
    __nv_bfloat16* wkT  = symaddr<__nv_bfloat16>(g_wkT);
    __nv_bfloat16* wvT  = symaddr<__nv_bfloat16>(g_wvT);
    __nv_bfloat16* woT  = symaddr<__nv_bfloat16>(g_woT);
    __nv_bfloat16* w1T  = symaddr<__nv_bfloat16>(g_w1T);
    __nv_bfloat16* w2T  = symaddr<__nv_bfloat16>(g_w2T);

    static bool attr_set = false;
    if (!attr_set) {
        cudaFuncSetAttribute(tgemm_kernel, cudaFuncAttributeMaxDynamicSharedMemorySize, TG_SMEM_BYTES);
        cudaFuncSetAttribute(btgemm_kernel, cudaFuncAttributeMaxDynamicSharedMemorySize, TG_SMEM_BYTES);
        cudaFuncSetAttribute(feat_kernel, cudaFuncAttributeMaxDynamicSharedMemorySize, FT_SMEM);
        attr_set = true;
    }

    dim3 blk256(256);
    dim3 t256(4, ROWS_TOT / 128);       // N=256
    dim3 t1024(16, ROWS_TOT / 128);     // N=1024
    dim3 tdd(5, RH / 128);              // N=320 (kmax pass)
    dim3 gCtx(5, 1, BH);
    dim3 gAtt(2, 3, BH);
    dim3 gKT(10, 10, BH);

    // ---- prep ----
    f2b_kernel<<<(int)((ROWS_TOT * (size_t)IN_DIM + 255) / 256), 256>>>(x, xb, (size_t)ROWS_TOT * IN_DIM);
    wtrans_kernel<<<dim3(DIM / 32, IN_DIM / 32), dim3(32, 8)>>>(w_in, wInT, IN_DIM, DIM);
    for (int l = 0; l < 2; l++) {
        wtrans_kernel<<<dim3(DIM / 32, DIM / 32), dim3(32, 8)>>>(wq + (size_t)l * DIM * DIM, wqT + (size_t)l * DIM * DIM, DIM, DIM);
        wtrans_kernel<<<dim3(DIM / 32, DIM / 32), dim3(32, 8)>>>(wk + (size_t)l * DIM * DIM, wkT + (size_t)l * DIM * DIM, DIM, DIM);
        wtrans_kernel<<<dim3(DIM / 32, DIM / 32), dim3(32, 8)>>>(wv + (size_t)l * DIM * DIM, wvT + (size_t)l * DIM * DIM, DIM, DIM);
        wtrans_kernel<<<dim3(DIM / 32, DIM / 32), dim3(32, 8)>>>(wo + (size_t)l * DIM * DIM, woT + (size_t)l * DIM * DIM, DIM, DIM);
        wtrans_kernel<<<dim3(FFH / 32, DIM / 32), dim3(32, 8)>>>(w1 + (size_t)l * DIM * FFH, w1T + (size_t)l * DIM * FFH, DIM, FFH);
        wtrans_kernel<<<dim3(DIM / 32, FFH / 32), dim3(32, 8)>>>(w2 + (size_t)l * FFH * DIM, w2T + (size_t)l * FFH * DIM, FFH, DIM);
    }

    tgemm_kernel<<<t256, blk256, TG_SMEM_BYTES>>>(xb, wInT, b_in, nullptr, h, nullptr,
                                                  ROWS_TOT, DIM, IN_DIM, 0, nullptr);

    for (int l = 0; l < 2; l++) {
        // --- attention ---
        ln8_bf16_kernel<<<ROWS_TOT / 8, 256>>>(h, ln1_g + l * DIM, ln1_b + l * DIM, yb);
        tgemm_kernel<<<t256, blk256, TG_SMEM_BYTES>>>(yb, wqT + (size_t)l * DIM * DIM, nullptr, nullptr, nullptr, qb, ROWS_TOT, DIM, DIM, 0, nullptr);
        tgemm_kernel<<<t256, blk256, TG_SMEM_BYTES>>>(yb, wkT + (size_t)l * DIM * DIM, nullptr, nullptr, nullptr, kb, ROWS_TOT, DIM, DIM, 0, nullptr);
        tgemm_kernel<<<t256, blk256, TG_SMEM_BYTES>>>(yb, wvT + (size_t)l * DIM * DIM, nullptr, nullptr, nullptr, vb, ROWS_TOT, DIM, DIM, 0, nullptr);

        projb_kernel<<<(MP * 64 + 255) / 256, 256>>>(proj + (size_t)l * MF * DH, pTb);
        kmax_init_kernel<<<1, 1024>>>(kmx);
        // k global-max pass: compute dd_k, store nothing, only kmax
        tgemm_kernel<<<tdd, blk256, TG_SMEM_BYTES>>>(kb, pTb, nullptr, nullptr, nullptr, nullptr,
                                                     RH, MP, 64, 0, kmx);
        // fused dd+exp feature passes (no dd buffers)
        feat_kernel<<<RH / 256, 256, FT_SMEM>>>(qb, pTb, qpB, nullptr, 0);
        feat_kernel<<<RH / 256, 256, FT_SMEM>>>(kb, pTb, kpB, kmx, 1);
        ktrans_kernel<<<gKT, dim3(32, 8)>>>(kpB, kpT);
        vtrans_kernel<<<BH, 256>>>(vb, vT);

        btgemm_kernel<<<gCtx, blk256, TG_SMEM_BYTES>>>(
            vT, (size_t)128 * NP, 127, kpT, (size_t)MP * NP,
            nullptr, ctxT, (size_t)128 * MP, MP, NP, 128, MP);
        btgemm_kernel<<<gAtt, blk256, TG_SMEM_BYTES>>>(
            qpB, (size_t)NN * MP, NN - 1, ctxT, (size_t)128 * MP,
            outA, nullptr, (size_t)NN * 128, 128, MP, NN, 66);

        divout_kernel<<<BH, 256>>>(outA, ob);

        tgemm_kernel<<<t256, blk256, TG_SMEM_BYTES>>>(ob, woT + (size_t)l * DIM * DIM, bo + l * DIM, h,
                                                      h, nullptr, ROWS_TOT, DIM, DIM, 0, nullptr);

        // --- FFN ---
        ln8_bf16_kernel<<<ROWS_TOT / 8, 256>>>(h, ln2_g + l * DIM, ln2_b + l * DIM, yb);
        tgemm_kernel<<<t1024, blk256, TG_SMEM_BYTES>>>(yb, w1T + (size_t)l * DIM * FFH, b1 + l * FFH, nullptr,
                                                       nullptr, ffhb, ROWS_TOT, FFH, DIM, 1, nullptr);
        tgemm_kernel<<<t256, blk256, TG_SMEM_BYTES>>>(ffhb, w2T + (size_t)l * FFH * DIM, b2 + l * DIM, h,
                                                      h, nullptr, ROWS_TOT, DIM, FFH, 0, nullptr);
    }

    pool_kernel<<<BB, 256>>>(h, pool);
    ln_f32_kernel<<<BB, 256>>>(pool, hln_g, hln_b, z);
    head1_kernel<<<BB, 128>>>(z, wh1, bh1, z1);
    head2_kernel<<<BB, 128>>>(z1, wh2, bh2, out);
}

// round 14
// speedup vs baseline: 1.3603x; 1.0824x over previous
#include <cuda_runtime.h>
#include <cuda_bf16.h>
#include <math.h>
#include <limits.h>
#include <stdint.h>

// ---------------- problem constants ----------------
#define BB 256
#define NN 300
#define IN_DIM 1280
#define DIM 256
#define HEADS 4
#define DH 64
#define MF 266            // NB_FEAT
#define MP 320            // padded feature dim
#define NP 320            // padded sequence dim per head
#define FFH 1024
#define ROWS_TOT (BB*NN)  // 76800
#define RH (ROWS_TOT*HEADS) // 307200
#define BH (BB*HEADS)       // 1024
#define RPB (NN*HEADS)      // rows per batch in dd view = 1200

#define LN_EPS 1e-5f
#define KEPS 1e-4f
#define RATIO 0.061314066f
#define NORM 0.35355339059327373f

// ---------------- scratch ----------------
__device__ float          g_h   [ROWS_TOT*DIM];
__device__ __nv_bfloat16  g_yb  [ROWS_TOT*DIM];
__device__ __nv_bfloat16  g_qb  [ROWS_TOT*DIM];
__device__ __nv_bfloat16  g_kb  [ROWS_TOT*DIM];
__device__ __nv_bfloat16  g_vb  [ROWS_TOT*DIM];
__device__ __nv_bfloat16  g_ob  [ROWS_TOT*DIM];
__device__ __nv_bfloat16  g_ffhb[ROWS_TOT*FFH];
__device__ __nv_bfloat16  g_xb  [ROWS_TOT*IN_DIM];
__device__ __nv_bfloat16  g_qpB [(size_t)BH*NN*MP];
__device__ __nv_bfloat16  g_kpB [(size_t)BH*NN*MP];
__device__ __nv_bfloat16  g_kpT [(size_t)BH*MP*NP];
__device__ __nv_bfloat16  g_vT  [(size_t)BH*128*NP];
__device__ __nv_bfloat16  g_ctxT[(size_t)BH*128*MP];
__device__ float          g_outA[(size_t)BH*NN*128];
__device__ int            g_kmax[BH];
__device__ float          g_pool[BB*DIM];
__device__ float          g_z   [BB*DIM];
__device__ float          g_z1  [BB*128];
__device__ __nv_bfloat16  g_pTb [MP*64];
__device__ __nv_bfloat16  g_wInT[DIM*IN_DIM];
__device__ __nv_bfloat16  g_wqT [2][DIM*DIM];
__device__ __nv_bfloat16  g_wkT [2][DIM*DIM];
__device__ __nv_bfloat16  g_wvT [2][DIM*DIM];
__device__ __nv_bfloat16  g_woT [2][DIM*DIM];
__device__ __nv_bfloat16  g_w1T [2][FFH*DIM];
__device__ __nv_bfloat16  g_w2T [2][DIM*FFH];

// ---------------- helpers ----------------
__device__ __forceinline__ int f2o(float f) {
    int i = __float_as_int(f);
    return i >= 0 ? i : (i ^ 0x7FFFFFFF);
}
__device__ __forceinline__ float o2f(int i) {
    return __int_as_float(i >= 0 ? i : (i ^ 0x7FFFFFFF));
}
__device__ __forceinline__ float tanh_fast(float a) {
    float t = __expf(-2.0f * fabsf(a));
    float r = (1.0f - t) / (1.0f + t);
    return copysignf(r, a);
}
__device__ __forceinline__ float gelu_tanh(float x) {
    float x3 = x * x * x;
    return 0.5f * x * (1.0f + tanh_fast(0.7978845608028654f * (x + 0.044715f * x3)));
}
__device__ __forceinline__ float blockReduceSum256(float v) {
    __shared__ float sh[8];
    __syncthreads();
    int lane = threadIdx.x & 31, w = threadIdx.x >> 5;
    #pragma unroll
    for (int o = 16; o; o >>= 1) v += __shfl_xor_sync(0xFFFFFFFFu, v, o);
    if (lane == 0) sh[w] = v;
    __syncthreads();
    if (threadIdx.x == 0) {
        float s = 0.f;
        #pragma unroll
        for (int i = 0; i < 8; i++) s += sh[i];
        sh[0] = s;
    }
    __syncthreads();
    return sh[0];
}
__device__ __forceinline__ uint32_t smem_u32(const void* p) {
    uint32_t a;
    asm("{ .reg .u64 t; cvta.to.shared.u64 t, %1; cvt.u32.u64 %0, t; }" : "=r"(a) : "l"(p));
    return a;
}

#define SWZ(off) ((off) ^ (((off) >> 3) & 0x70))

__device__ __forceinline__ void ldmatrix4(uint32_t* r, uint32_t addr) {
    asm volatile("ldmatrix.sync.aligned.m8n8.x4.shared.b16 {%0,%1,%2,%3}, [%4];"
        : "=r"(r[0]), "=r"(r[1]), "=r"(r[2]), "=r"(r[3]) : "r"(addr));
}
__device__ __forceinline__ void mma16816(float* c, const uint32_t* a, uint32_t b0, uint32_t b1) {
    asm volatile(
        "mma.sync.aligned.m16n8k16.row.col.f32.bf16.bf16.f32 "
        "{%0,%1,%2,%3}, {%4,%5,%6,%7}, {%8,%9}, {%0,%1,%2,%3};"
        : "+f"(c[0]), "+f"(c[1]), "+f"(c[2]), "+f"(c[3])
        : "r"(a[0]), "r"(a[1]), "r"(a[2]), "r"(a[3]), "r"(b0), "r"(b1));
}
__device__ __forceinline__ void cp_async16(uint32_t smem, const void* g) {
    asm volatile("cp.async.cg.shared.global [%0], [%1], 16;" :: "r"(smem), "l"(g));
}
__device__ __forceinline__ void cp_commit() {
    asm volatile("cp.async.commit_group;" ::: "memory");
}
__device__ __forceinline__ void cp_wait2() {
    asm volatile("cp.async.wait_group 2;" ::: "memory");
}
__device__ __forceinline__ void cp_wait0() {
    asm volatile("cp.async.wait_group 0;" ::: "memory");
}

// stage stride: A 16384 + B 8192 = 24576; 4 stages = 98304
#define TG_STAGE 24576
#define TG_SMEM_BYTES (4*TG_STAGE)

// ---------------- bf16 HMMA GEMM (128x64 tile, 4-stage pipeline, 1 sync/chunk) ----
// C = act(A[M,K] @ Bt[N,K]^T + bias) (+res). M%128==0, N%64==0, K%64==0.
__global__ void __launch_bounds__(256, 2) tgemm_kernel(
    const __nv_bfloat16* __restrict__ A, const __nv_bfloat16* __restrict__ Bt,
    const float* __restrict__ bias, const float* __restrict__ res,
    float* __restrict__ Cf, __nv_bfloat16* __restrict__ Cb,
    int M, int N, int K, int act)
{
    extern __shared__ __nv_bfloat16 sm[];
    const uint32_t base = smem_u32(sm);

    const int tid = threadIdx.x;
    const int wid = tid >> 5, lane = tid & 31;
    const int wm = wid & 3, wn = wid >> 2;
    const int row0 = blockIdx.y * 128, col0 = blockIdx.x * 64;
    const int tileid = lane >> 3, rit = lane & 7;
    const int gid = lane >> 2, tig = lane & 3;

    float acc[2][4][4];
    #pragma unroll
    for (int mt = 0; mt < 2; mt++)
        #pragma unroll
        for (int j = 0; j < 4; j++)
            #pragma unroll
            for (int r = 0; r < 4; r++) acc[mt][j][r] = 0.f;

    const int nch = K >> 6;
    const __nv_bfloat16* Arow = A + (size_t)row0 * K;
    const __nv_bfloat16* Brow = Bt + (size_t)col0 * K;

    #pragma unroll
    for (int s = 0; s < 3; s++) {
        if (s < nch) {
            const int k0 = s << 6;
            const uint32_t aS = base + s * TG_STAGE;
            const uint32_t bS = aS + 16384;
            #pragma unroll
            for (int i = 0; i < 4; i++) {
                int lin = tid + i * 256;
                int r = lin >> 3, c8 = lin & 7;
                cp_async16(aS + SWZ(r * 128 + c8 * 16), Arow + (size_t)r * K + k0 + c8 * 8);
            }
            #pragma unroll
            for (int i = 0; i < 2; i++) {
                int lin = tid + i * 256;
                int r = lin >> 3, c8 = lin & 7;
                cp_async16(bS + SWZ(r * 128 + c8 * 16), Brow + (size_t)r * K + k0 + c8 * 8);
            }
        }
        cp_commit();
    }

    for (int c = 0; c < nch; c++) {
        cp_wait2();
        __syncthreads();
        const int stg = c & 3;
        const uint32_t aB = base + stg * TG_STAGE;
        const uint32_t bB = aB + 16384;
        #pragma unroll
        for (int kk = 0; kk < 4; kk++) {
            uint32_t af[2][4];
            #pragma unroll
            for (int mt = 0; mt < 2; mt++) {
                int off = (wm * 32 + mt * 16 + (tileid & 1) * 8 + rit) * 128
                          + kk * 32 + (tileid >> 1) * 16;
                ldmatrix4(af[mt], aB + SWZ(off));
            }
            uint32_t bf[2][4];
            #pragma unroll
            for (int nt = 0; nt < 2; nt++) {
                int off = (wn * 32 + nt * 16 + (tileid & 1) * 8 + rit) * 128
                          + kk * 32 + (tileid >> 1) * 16;
                ldmatrix4(bf[nt], bB + SWZ(off));
            }
            #pragma unroll
            for (int mt = 0; mt < 2; mt++)
                #pragma unroll
                for (int j = 0; j < 4; j++) {
                    int nt = j >> 1, sel = j & 1;
                    mma16816(acc[mt][j], af[mt], bf[nt][sel], bf[nt][2 + sel]);
                }
        }
        if (c + 3 < nch) {
            const int k0 = (c + 3) << 6;
            const int ns = (c + 3) & 3;
            const uint32_t aS = base + ns * TG_STAGE;
            const uint32_t bS = aS + 16384;
            #pragma unroll
            for (int i = 0; i < 4; i++) {
                int lin = tid + i * 256;
                int r = lin >> 3, c8 = lin & 7;
                cp_async16(aS + SWZ(r * 128 + c8 * 16), Arow + (size_t)r * K + k0 + c8 * 8);
            }
            #pragma unroll
            for (int i = 0; i < 2; i++) {
                int lin = tid + i * 256;
                int r = lin >> 3, c8 = lin & 7;
                cp_async16(bS + SWZ(r * 128 + c8 * 16), Brow + (size_t)r * K + k0 + c8 * 8);
            }
        }
        cp_commit();
    }

    // epilogue
    #pragma unroll
    for (int mt = 0; mt < 2; mt++) {
        #pragma unroll
        for (int j = 0; j < 4; j++) {
            #pragma unroll
            for (int half = 0; half < 2; half++) {
                int r = row0 + wm * 32 + mt * 16 + gid + half * 8;
                int cidx = col0 + wn * 32 + j * 8 + tig * 2;
                float v0 = acc[mt][j][half * 2 + 0];
                float v1 = acc[mt][j][half * 2 + 1];
                if (bias) { v0 += bias[cidx]; v1 += bias[cidx + 1]; }
                if (act == 1) { v0 = gelu_tanh(v0); v1 = gelu_tanh(v1); }
                if (res) {
                    float2 r2 = *(const float2*)(res + (size_t)r * N + cidx);
                    v0 += r2.x; v1 += r2.y;
                }
                if (Cf) *(float2*)(Cf + (size_t)r * N + cidx) = make_float2(v0, v1);
                if (Cb) *(__nv_bfloat162*)(Cb + (size_t)r * N + cidx) = __floats2bfloat162_rn(v0, v1);
            }
        }
    }
}

// ---------------- batched bf16 HMMA GEMM (128x64 tile, 4-stage) ----------------
__global__ void __launch_bounds__(256, 2) btgemm_kernel(
    const __nv_bfloat16* __restrict__ A, size_t aBS, int aClamp,
    const __nv_bfloat16* __restrict__ Bt, size_t bBS,
    float* __restrict__ Cf, __nv_bfloat16* __restrict__ Cb, size_t cBS,
    int ldc, int K, int mValid, int nStore)
{
    extern __shared__ __nv_bfloat16 sm[];
    const uint32_t base = smem_u32(sm);

    const int tid = threadIdx.x;
    const int wid = tid >> 5, lane = tid & 31;
    const int wm = wid & 3, wn = wid >> 2;
    const int row0 = blockIdx.y * 128, col0 = blockIdx.x * 64;
    const int tileid = lane >> 3, rit = lane & 7;
    const int gid = lane >> 2, tig = lane & 3;
    const int bh = blockIdx.z;

    const __nv_bfloat16* Ab = A + (size_t)bh * aBS;
    const __nv_bfloat16* Bb = Bt + (size_t)bh * bBS + (size_t)col0 * K;

    float acc[2][4][4];
    #pragma unroll
    for (int mt = 0; mt < 2; mt++)
        #pragma unroll
        for (int j = 0; j < 4; j++)
            #pragma unroll
            for (int r = 0; r < 4; r++) acc[mt][j][r] = 0.f;

    const int nch = K >> 6;
    #pragma unroll
    for (int s = 0; s < 3; s++) {
        if (s < nch) {
            const int k0 = s << 6;
            const uint32_t aS = base + s * TG_STAGE;
            const uint32_t bS = aS + 16384;
            #pragma unroll
            for (int i = 0; i < 4; i++) {
                int lin = tid + i * 256;
                int r = lin >> 3, c8 = lin & 7;
                int rg = min(row0 + r, aClamp);
                cp_async16(aS + SWZ(r * 128 + c8 * 16), Ab + (size_t)rg * K + k0 + c8 * 8);
            }
            #pragma unroll
            for (int i = 0; i < 2; i++) {
                int lin = tid + i * 256;
                int r = lin >> 3, c8 = lin & 7;
                cp_async16(bS + SWZ(r * 128 + c8 * 16), Bb + (size_t)r * K + k0 + c8 * 8);
            }
        }
        cp_commit();
    }

    for (int c = 0; c < nch; c++) {
        cp_wait2();
        __syncthreads();
        const int stg = c & 3;
        const uint32_t aB = base + stg * TG_STAGE;
        const uint32_t bB = aB + 16384;
        #pragma unroll
        for (int kk = 0; kk < 4; kk++) {
            uint32_t af[2][4];
            #pragma unroll
            for (int mt = 0; mt < 2; mt++) {
                int off = (wm * 32 + mt * 16 + (tileid & 1) * 8 + rit) * 128
                          + kk * 32 + (tileid >> 1) * 16;
                ldmatrix4(af[mt], aB + SWZ(off));
            }
            uint32_t bf[2][4];
            #pragma unroll
            for (int nt = 0; nt < 2; nt++) {
                int off = (wn * 32 + nt * 16 + (tileid & 1) * 8 + rit) * 128
                          + kk * 32 + (tileid >> 1) * 16;
                ldmatrix4(bf[nt], bB + SWZ(off));
            }
            #pragma unroll
            for (int mt = 0; mt < 2; mt++)
                #pragma unroll
                for (int j = 0; j < 4; j++) {
                    int nt = j >> 1, sel = j & 1;
                    mma16816(acc[mt][j], af[mt], bf[nt][sel], bf[nt][2 + sel]);
                }
        }
        if (c + 3 < nch) {
            const int k0 = (c + 3) << 6;
            const int ns = (c + 3) & 3;
            const uint32_t aS = base + ns * TG_STAGE;
            const uint32_t bS = aS + 16384;
            #pragma unroll
            for (int i = 0; i < 4; i++) {
                int lin = tid + i * 256;
                int r = lin >> 3, c8 = lin & 7;
                int rg = min(row0 + r, aClamp);
                cp_async16(aS + SWZ(r * 128 + c8 * 16), Ab + (size_t)rg * K + k0 + c8 * 8);
            }
            #pragma unroll
            for (int i = 0; i < 2; i++) {
                int lin = tid + i * 256;
                int r = lin >> 3, c8 = lin & 7;
                cp_async16(bS + SWZ(r * 128 + c8 * 16), Bb + (size_t)r * K + k0 + c8 * 8);
            }
        }
        cp_commit();
    }

    float* Cfb = Cf ? Cf + (size_t)bh * cBS : nullptr;
    __nv_bfloat16* Cbb = Cb ? Cb + (size_t)bh * cBS : nullptr;
    #pragma unroll
    for (int mt = 0; mt < 2; mt++) {
        #pragma unroll
        for (int j = 0; j < 4; j++) {
            #pragma unroll
            for (int half = 0; half < 2; half++) {
                int r = row0 + wm * 32 + mt * 16 + gid + half * 8;
                if (r >= mValid) continue;
                int cidx = col0 + wn * 32 + j * 8 + tig * 2;
                if (cidx >= nStore) continue;
                float v0 = acc[mt][j][half * 2 + 0];
                float v1 = acc[mt][j][half * 2 + 1];
                if (Cfb) *(float2*)(Cfb + (size_t)r * ldc + cidx) = make_float2(v0, v1);
                if (Cbb) *(__nv_bfloat162*)(Cbb + (size_t)r * ldc + cidx) = __floats2bfloat162_rn(v0, v1);
            }
        }
    }
}

// ---------------- fused feature kernel ----------------
// mode 0: q (per-row max stab, store qpB); mode 1: k (global kmax stab, store kpB);
// mode 2: kmax only (no stores, global atomicMax of raw dd per (b,h)).
#define FT_PROJ_BYTES (MP*128)          // 40960
#define FT_ATILE 4096
#define FT_SMEM (FT_PROJ_BYTES + 2*FT_ATILE)   // 49152

__global__ void __launch_bounds__(256, 2) feat_kernel(
    const __nv_bfloat16* __restrict__ src, const __nv_bfloat16* __restrict__ pTb,
    __nv_bfloat16* __restrict__ outp, int* __restrict__ kmax, int mode)
{
    extern __shared__ __nv_bfloat16 sm[];
    char* smc = (char*)sm;
    const uint32_t projS = smem_u32(sm);
    const uint32_t aS0 = projS + FT_PROJ_BYTES;
    __shared__ int smax[32];
    __shared__ float diag[32];
    __shared__ int gm[8];

    const int tid = threadIdx.x;
    const int lane = tid & 31;
    const int wid = tid >> 5;
    const int wm = wid & 1, wn = wid >> 1;        // 2 M-warps x 4 N-warps
    const int tileid = lane >> 3, rit = lane & 7;
    const int gid = lane >> 2, tig = lane & 3;
    const size_t base_tok = (size_t)blockIdx.x * 256;
    const int baseB = (int)(base_tok / RPB);

    if (tid < 8) gm[tid] = INT_MIN;

    // load proj (320 x 64 bf16, SW128)
    for (int i = tid; i < MP * 8; i += 256) {
        int r = i >> 3, c8 = i & 7;
        cp_async16(projS + SWZ(r * 128 + c8 * 16), pTb + (size_t)r * 64 + c8 * 8);
    }
    // load A tile 0
    {
        int r = tid >> 3, c8 = tid & 7;
        cp_async16(aS0 + SWZ(r * 128 + c8 * 16), src + (base_tok + r) * 64 + c8 * 8);
    }
    cp_commit();
    cp_wait0();
    __syncthreads();

    for (int t = 0; t < 8; t++) {
        const int buf = t & 1;
        const uint32_t aB = aS0 + buf * FT_ATILE;
        if (t + 1 < 8) {
            int r = tid >> 3, c8 = tid & 7;
            cp_async16(aS0 + ((t + 1) & 1) * FT_ATILE + SWZ(r * 128 + c8 * 16),
                       src + (base_tok + (t + 1) * 32 + r) * 64 + c8 * 8);
            cp_commit();
        }
        if (mode != 2) {
            // init smax + diag
            if (tid < 32) smax[tid] = INT_MIN;
            {
                int r = tid >> 3, c8 = tid & 7;
                uint4 d = *(const uint4*)(smc + FT_PROJ_BYTES + buf * FT_ATILE + SWZ(r * 128 + c8 * 16));
                const __nv_bfloat16* pv = (const __nv_bfloat16*)&d;
                float s = 0.f;
                #pragma unroll
                for (int i = 0; i < 8; i++) {
                    float f = __bfloat162float(pv[i]);
                    s = fmaf(f, f, s);
                }
                #pragma unroll
                for (int o = 4; o; o >>= 1) s += __shfl_xor_sync(0xFFFFFFFFu, s, o);
                if ((lane & 7) == 0) diag[r] = 0.0625f * s;
            }
        }
        __syncthreads();

        // MMA: 32 rows x 320 cols, K=64
        float acc[10][4];
        #pragma unroll
        for (int j = 0; j < 10; j++)
            #pragma unroll
            for (int r = 0; r < 4; r++) acc[j][r] = 0.f;
        #pragma unroll
        for (int kk = 0; kk < 4; kk++) {
            uint32_t af[4];
            {
                int off = (wm * 16 + (tileid & 1) * 8 + rit) * 128
                          + kk * 32 + (tileid >> 1) * 16;
                ldmatrix4(af, aB + SWZ(off));
            }
            uint32_t bf[5][4];
            #pragma unroll
            for (int nt = 0; nt < 5; nt++) {
                int off = (wn * 80 + nt * 16 + (tileid & 1) * 8 + rit) * 128
                          + kk * 32 + (tileid >> 1) * 16;
                ldmatrix4(bf[nt], projS + SWZ(off));
            }
            #pragma unroll
            for (int j = 0; j < 10; j++) {
                int nt = j >> 1, sel = j & 1;
                mma16816(acc[j], af, bf[nt][sel], bf[nt][2 + sel]);
            }
        }

        if (mode == 0) {
            float mx0 = -1e30f, mx8 = -1e30f;
            #pragma unroll
            for (int j = 0; j < 10; j++) {
                int cb = wn * 80 + j * 8 + tig * 2;
                if (cb < MF)     { mx0 = fmaxf(mx0, acc[j][0]); mx8 = fmaxf(mx8, acc[j][2]); }
                if (cb + 1 < MF) { mx0 = fmaxf(mx0, acc[j][1]); mx8 = fmaxf(mx8, acc[j][3]); }
            }
            #pragma unroll
            for (int o = 2; o; o >>= 1) {
                mx0 = fmaxf(mx0, __shfl_xor_sync(0xFFFFFFFFu, mx0, o));
                mx8 = fmaxf(mx8, __shfl_xor_sync(0xFFFFFFFFu, mx8, o));
            }
            if (tig == 0) {
                atomicMax(&smax[wm * 16 + gid], f2o(mx0));
                atomicMax(&smax[wm * 16 + gid + 8], f2o(mx8));
            }
        } else if (mode == 2) {
            float mx0 = -1e30f, mx8 = -1e30f;
            #pragma unroll
            for (int j = 0; j < 10; j++) {
                int cb = wn * 80 + j * 8 + tig * 2;
                if (cb < MF)     { mx0 = fmaxf(mx0, acc[j][0]); mx8 = fmaxf(mx8, acc[j][2]); }
                if (cb + 1 < MF) { mx0 = fmaxf(mx0, acc[j][1]); mx8 = fmaxf(mx8, acc[j][3]); }
            }
            #pragma unroll
            for (int o = 2; o; o >>= 1) {
                mx0 = fmaxf(mx0, __shfl_xor_sync(0xFFFFFFFFu, mx0, o));
                mx8 = fmaxf(mx8, __shfl_xor_sync(0xFFFFFFFFu, mx8, o));
            }
            if (tig == 0) {
                int r0l = wm * 16 + gid;
                size_t w0 = base_tok + t * 32 + r0l;
                size_t w8 = w0 + 8;
                int b0v = (int)(w0 / RPB), rem0 = (int)(w0 - (size_t)b0v * RPB);
                int b8v = (int)(w8 / RPB), rem8 = (int)(w8 - (size_t)b8v * RPB);
                atomicMax(&gm[(b0v - baseB) * 4 + (rem0 & 3)], f2o(mx0));
                atomicMax(&gm[(b8v - baseB) * 4 + (rem8 & 3)], f2o(mx8));
            }
        }
        __syncthreads();

        // epilogue: exp + store (modes 0/1 only)
        if (mode != 2) {
            int r0l = wm * 16 + gid, r8l = r0l + 8;
            size_t w0 = base_tok + t * 32 + r0l;
            size_t w8 = w0 + 8;
            float dg0 = diag[r0l], dg8 = diag[r8l];
            float st0, st8;
            int b0v = (int)(w0 / RPB), rem0 = (int)(w0 - (size_t)b0v * RPB);
            int b8v = (int)(w8 / RPB), rem8 = (int)(w8 - (size_t)b8v * RPB);
            if (mode == 1) {
                st0 = o2f(kmax[b0v * HEADS + (rem0 & 3)]);
                st8 = o2f(kmax[b8v * HEADS + (rem8 & 3)]);
            } else {
                st0 = o2f(smax[r0l]);
                st8 = o2f(smax[r8l]);
            }
            __nv_bfloat16* p0 = outp + ((size_t)(b0v * HEADS + (rem0 & 3)) * NN + (rem0 >> 2)) * MP;
            __nv_bfloat16* p8 = outp + ((size_t)(b8v * HEADS + (rem8 & 3)) * NN + (rem8 >> 2)) * MP;
            #pragma unroll
            for (int j = 0; j < 10; j++) {
                int cb = wn * 80 + j * 8 + tig * 2;
                float a0 = (cb < MF)     ? RATIO * (__expf(acc[j][0] - dg0 - st0) + KEPS) : 0.f;
                float a1 = (cb + 1 < MF) ? RATIO * (__expf(acc[j][1] - dg0 - st0) + KEPS) : 0.f;
                float c0 = (cb < MF)     ? RATIO * (__expf(acc[j][2] - dg8 - st8) + KEPS) : 0.f;
                float c1 = (cb + 1 < MF) ? RATIO * (__expf(acc[j][3] - dg8 - st8) + KEPS) : 0.f;
                *(__nv_bfloat162*)(p0 + cb) = __floats2bfloat162_rn(a0, a1);
                *(__nv_bfloat162*)(p8 + cb) = __floats2bfloat162_rn(c0, c1);
            }
        }
        if (t + 1 < 8) {
            cp_wait0();
        }
        __syncthreads();
    }

    if (mode == 2) {
        if (tid < 8) {
            int bb = baseB + (tid >> 2);
            if (gm[tid] != INT_MIN && bb < BB)
                atomicMax(&kmax[bb * HEADS + (tid & 3)], gm[tid]);
        }
    }
}

// kpB [bh][n][m] -> kpT [bh][m][n] with zero-fill n>=NN
__global__ void ktrans_kernel(const __nv_bfloat16* __restrict__ kpB,
                              __nv_bfloat16* __restrict__ kpT)
{
    __shared__ __nv_bfloat16 s[32][33];
    int bh = blockIdx.z;
    int n0 = blockIdx.x * 32, m0 = blockIdx.y * 32;
    int tx = threadIdx.x, ty = threadIdx.y;    // 32 x 8
    const __nv_bfloat16* src = kpB + (size_t)bh * NN * MP;
    #pragma unroll
    for (int i = 0; i < 32; i += 8) {
        int n = n0 + ty + i;
        s[ty + i][tx] = (n < NN) ? src[(size_t)n * MP + m0 + tx] : __float2bfloat16(0.f);
    }
    __syncthreads();
    __nv_bfloat16* dst = kpT + (size_t)bh * MP * NP;
    #pragma unroll
    for (int i = 0; i < 32; i += 8)
        dst[(size_t)(m0 + ty + i) * NP + n0 + tx] = s[tx][ty + i];
}

// ---------------- prep kernels ----------------
__global__ void f2b_kernel(const float* __restrict__ a, __nv_bfloat16* __restrict__ b, size_t n) {
    size_t i = (size_t)blockIdx.x * blockDim.x + threadIdx.x;
    if (i < n) b[i] = __float2bfloat16(a[i]);
}

__global__ void wtrans_kernel(const float* __restrict__ W, __nv_bfloat16* __restrict__ Wt,
                              int K, int N) {
    __shared__ float t[32][33];
    int k0 = blockIdx.y * 32, n0 = blockIdx.x * 32;
    int tx = threadIdx.x, ty = threadIdx.y;
    #pragma unroll
    for (int i = 0; i < 32; i += 8)
        t[ty + i][tx] = W[(size_t)(k0 + ty + i) * N + n0 + tx];
    __syncthreads();
    #pragma unroll
    for (int i = 0; i < 32; i += 8)
        Wt[(size_t)(n0 + ty + i) * K + k0 + tx] = __float2bfloat16(t[tx][ty + i]);
}

__global__ void projb_kernel(const float* __restrict__ proj, __nv_bfloat16* __restrict__ pTb) {
    int i = blockIdx.x * 256 + threadIdx.x;
    if (i >= MP * 64) return;
    int m = i >> 6, d = i & 63;
    pTb[i] = __float2bfloat16((m < MF) ? proj[m * 64 + d] * NORM : 0.f);
}

// ---------------- layernorm (warp-per-row, 8 rows/block) ----------------
__global__ void __launch_bounds__(256) ln8_bf16_kernel(
    const float* __restrict__ x, const float* __restrict__ g,
    const float* __restrict__ b, __nv_bfloat16* __restrict__ y)
{
    int warp = threadIdx.x >> 5, lane = threadIdx.x & 31;
    int row = blockIdx.x * 8 + warp;
    const float* xr = x + (size_t)row * DIM + lane * 8;
    float4 a0 = *(const float4*)xr;
    float4 a1 = *(const float4*)(xr + 4);
    float v[8] = {a0.x, a0.y, a0.z, a0.w, a1.x, a1.y, a1.z, a1.w};

    float s = ((v[0] + v[1]) + (v[2] + v[3])) + ((v[4] + v[5]) + (v[6] + v[7]));
    #pragma unroll
    for (int o = 16; o; o >>= 1) s += __shfl_xor_sync(0xFFFFFFFFu, s, o);
    float mu = s * (1.0f / DIM);

    float q = 0.f;
    #pragma unroll
    for (int i = 0; i < 8; i++) {
        float d = v[i] - mu;
        v[i] = d;
        q = fmaf(d, d, q);
    }
    #pragma unroll
    for (int o = 16; o; o >>= 1) q += __shfl_xor_sync(0xFFFFFFFFu, q, o);
    float rs = rsqrtf(q * (1.0f / DIM) + LN_EPS);

    float4 g0 = *(const float4*)(g + lane * 8);
    float4 g1 = *(const float4*)(g + lane * 8 + 4);
    float4 b0 = *(const float4*)(b + lane * 8);
    float4 b1 = *(const float4*)(b + lane * 8 + 4);
    float gg[8] = {g0.x, g0.y, g0.z, g0.w, g1.x, g1.y, g1.z, g1.w};
    float bb2[8] = {b0.x, b0.y, b0.z, b0.w, b1.x, b1.y, b1.z, b1.w};

    __nv_bfloat162 o2[4];
    #pragma unroll
    for (int i = 0; i < 4; i++) {
        float r0 = v[2 * i] * rs * gg[2 * i] + bb2[2 * i];
        float r1 = v[2 * i + 1] * rs * gg[2 * i + 1] + bb2[2 * i + 1];
        o2[i] = __floats2bfloat162_rn(r0, r1);
    }
    *(uint4*)(y + (size_t)row * DIM + lane * 8) = *(uint4*)o2;
}

__global__ void ln_f32_kernel(const float* __restrict__ x, const float* __restrict__ g,
                              const float* __restrict__ b, float* __restrict__ y)
{
    int row = blockIdx.x;
    int t = threadIdx.x;
    float v = x[(size_t)row * DIM + t];
    float mu = blockReduceSum256(v) * (1.0f / DIM);
    float d = v - mu;
    float var = blockReduceSum256(d * d) * (1.0f / DIM);
    y[(size_t)row * DIM + t] = d * rsqrtf(var + LN_EPS) * g[t] + b[t];
}

__global__ void kmax_init_kernel(int* __restrict__ kmax) {
    int i = blockIdx.x * blockDim.x + threadIdx.x;
    if (i < BH) kmax[i] = INT_MIN;
}

// v transpose (bf16 in): vAugT[bh][d][n], d=64 row = ones
__global__ void __launch_bounds__(256) vtrans_kernel(
    const __nv_bfloat16* __restrict__ v, __nv_bfloat16* __restrict__ vT)
{
    __shared__ float t[32][65];
    int bh = blockIdx.x, b = bh >> 2, h = bh & 3;
    int tid = threadIdx.x;
    int lane = tid & 31;
    __nv_bfloat16* vb = vT + (size_t)bh * 128 * NP;

    for (int it = 0; it < 10; it++) {
        int n0 = it * 32;
        int d = tid & 63;
        #pragma unroll
        for (int sub = 0; sub < 8; sub++) {
            int n_l = (tid >> 6) + 4 * sub;
            int n_g = n0 + n_l;
            t[n_l][d] = (n_g < NN) ?
                __bfloat162float(v[((size_t)(b * NN + n_g)) * DIM + h * 64 + d]) : 0.f;
        }
        __syncthreads();
        int dcol = tid >> 5;
        #pragma unroll
        for (int j = 0; j < 8; j++) {
            int d2 = dcol + 8 * j;
            vb[(size_t)d2 * NP + n0 + lane] = __float2bfloat16(t[lane][d2]);
        }
        __syncthreads();
    }
    for (int idx = tid; idx < 64 * NP; idx += 256) {
        int d = 64 + idx / NP, n = idx % NP;
        float val = (d == 64 && n < NN) ? 1.f : 0.f;
        vb[(size_t)d * NP + n] = __float2bfloat16(val);
    }
}

__global__ void divout_kernel(const float* __restrict__ outA, __nv_bfloat16* __restrict__ ob)
{
    int bh = blockIdx.x, b = bh >> 2, h = bh & 3;
    const float* base = outA + (size_t)bh * NN * 128;
    for (int idx = threadIdx.x; idx < NN * 64; idx += 256) {
        int n = idx >> 6, d = idx & 63;
        float num = base[(size_t)n * 128 + d];
        float den = base[(size_t)n * 128 + 64];
        ob[((size_t)(b * NN + n)) * DIM + h * 64 + d] = __float2bfloat16(num / den);
    }
}

// ---------------- pooling & head ----------------
__global__ void pool_kernel(const float* __restrict__ h, float* __restrict__ pooled)
{
    int b = blockIdx.x, c = threadIdx.x;
    const float* p = h + (size_t)b * NN * DIM + c;
    float s0 = 0.f, s1 = 0.f, s2 = 0.f, s3 = 0.f;
    for (int n = 0; n < NN; n += 4) {
        s0 += p[(size_t)(n + 0) * DIM];
        s1 += p[(size_t)(n + 1) * DIM];
        s2 += p[(size_t)(n + 2) * DIM];
        s3 += p[(size_t)(n + 3) * DIM];
    }
    pooled[b * DIM + c] = ((s0 + s1) + (s2 + s3)) * (1.0f / NN);
}

__global__ void head1_kernel(const float* __restrict__ z, const float* __restrict__ w,
                             const float* __restrict__ bias, float* __restrict__ z1)
{
    __shared__ float zs[DIM];
    int b = blockIdx.x, j = threadIdx.x;
    for (int c = j; c < DIM; c += 128) zs[c] = z[b * DIM + c];
    __syncthreads();
    float s0 = 0.f, s1 = 0.f, s2 = 0.f, s3 = 0.f;
    #pragma unroll 1
    for (int c = 0; c < DIM; c += 4) {
        s0 = fmaf(zs[c + 0], w[(c + 0) * 128 + j], s0);
        s1 = fmaf(zs[c + 1], w[(c + 1) * 128 + j], s1);
        s2 = fmaf(zs[c + 2], w[(c + 2) * 128 + j], s2);
        s3 = fmaf(zs[c + 3], w[(c + 3) * 128 + j], s3);
    }
    z1[b * 128 + j] = fmaxf(((s0 + s1) + (s2 + s3)) + bias[j], 0.f);
}

__global__ void head2_kernel(const float* __restrict__ z1, const float* __restrict__ w,
                             const float* __restrict__ bias, float* __restrict__ out)
{
    __shared__ float sh[4];
    int b = blockIdx.x, j = threadIdx.x;
    float s = z1[b * 128 + j] * w[j];
    #pragma unroll
    for (int o = 16; o; o >>= 1) s += __shfl_xor_sync(0xFFFFFFFFu, s, o);
    if ((j & 31) == 0) sh[j >> 5] = s;
    __syncthreads();
    if (j == 0) {
        float t = sh[0] + sh[1] + sh[2] + sh[3] + bias[0];
        out[b] = 1.0f / (1.0f + __expf(-t));
    }
}

// ---------------- host ----------------
template <typename T> static T* symaddr(const void* sym) {
    void* p = nullptr;
    cudaGetSymbolAddress(&p, sym);
    return (T*)p;
}

extern "C" void kernel_launch(void* const* d_in, const int* in_sizes, int n_in,
                              void* d_out, int out_size)
{
    const float* x     = (const float*)d_in[0];
    const float* w_in  = (const float*)d_in[1];
    const float* b_in  = (const float*)d_in[2];
    const float* proj  = (const float*)d_in[3];
    const float* ln1_g = (const float*)d_in[4];
    const float* ln1_b = (const float*)d_in[5];
    const float* wq    = (const float*)d_in[6];
    const float* wk    = (const float*)d_in[7];
    const float* wv    = (const float*)d_in[8];
    const float* wo    = (const float*)d_in[9];
    const float* bo    = (const float*)d_in[10];
    const float* ln2_g = (const float*)d_in[11];
    const float* ln2_b = (const float*)d_in[12];
    const float* w1    = (const float*)d_in[13];
    const float* b1    = (const float*)d_in[14];
    const float* w2    = (const float*)d_in[15];
    const float* b2    = (const float*)d_in[16];
    const float* hln_g = (const float*)d_in[17];
    const float* hln_b = (const float*)d_in[18];
    const float* wh1   = (const float*)d_in[19];
    const float* bh1   = (const float*)d_in[20];
    const float* wh2   = (const float*)d_in[21];
    const float* bh2   = (const float*)d_in[22];
    float* out = (float*)d_out;

    float* h    = symaddr<float>(g_h);
    __nv_bfloat16* yb   = symaddr<__nv_bfloat16>(g_yb);
    __nv_bfloat16* qb   = symaddr<__nv_bfloat16>(g_qb);
    __nv_bfloat16* kb   = symaddr<__nv_bfloat16>(g_kb);
    __nv_bfloat16* vb   = symaddr<__nv_bfloat16>(g_vb);
    __nv_bfloat16* ob   = symaddr<__nv_bfloat16>(g_ob);
    __nv_bfloat16* ffhb = symaddr<__nv_bfloat16>(g_ffhb);
    __nv_bfloat16* xb   = symaddr<__nv_bfloat16>(g_xb);
    __nv_bfloat16* qpB  = symaddr<__nv_bfloat16>(g_qpB);
    __nv_bfloat16* kpB  = symaddr<__nv_bfloat16>(g_kpB);
    __nv_bfloat16* kpT  = symaddr<__nv_bfloat16>(g_kpT);
    __nv_bfloat16* vT   = symaddr<__nv_bfloat16>(g_vT);
    __nv_bfloat16* ctxT = symaddr<__nv_bfloat16>(g_ctxT);
    float* outA = symaddr<float>(g_outA);
    int*   kmx  = symaddr<int>(g_kmax);
    float* pool = symaddr<float>(g_pool);
    float* z    = symaddr<float>(g_z);
    float* z1   = symaddr<float>(g_z1);
    __nv_bfloat16* pTb  = symaddr<__nv_bfloat16>(g_pTb);
    __nv_bfloat16* wInT = symaddr<__nv_bfloat16>(g_wInT);
    __nv_bfloat16* wqT  = symaddr<__nv_bfloat16>(g_wqT);
    __nv_bfloat16* wkT  = symaddr<__nv_bfloat16>(g_wkT);
    __nv_bfloat16* wvT  = symaddr<__nv_bfloat16>(g_wvT);
    __nv_bfloat16* woT  = symaddr<__nv_bfloat16>(g_woT);
    __nv_bfloat16* w1T  = symaddr<__nv_bfloat16>(g_w1T);
    __nv_bfloat16* w2T  = symaddr<__nv_bfloat16>(g_w2T);

    static bool attr_set = false;
    if (!attr_set) {
        cudaFuncSetAttribute(tgemm_kernel, cudaFuncAttributeMaxDynamicSharedMemorySize, TG_SMEM_BYTES);
        cudaFuncSetAttribute(btgemm_kernel, cudaFuncAttributeMaxDynamicSharedMemorySize, TG_SMEM_BYTES);
        cudaFuncSetAttribute(feat_kernel, cudaFuncAttributeMaxDynamicSharedMemorySize, FT_SMEM);
        attr_set = true;
    }

    dim3 blk256(256);
    dim3 t256(4, ROWS_TOT / 128);       // N=256
    dim3 t1024(16, ROWS_TOT / 128);     // N=1024
    dim3 gCtx(5, 1, BH);
    dim3 gAtt(2, 3, BH);
    dim3 gKT(10, 10, BH);

    // ---- prep ----
    f2b_kernel<<<(int)((ROWS_TOT * (size_t)IN_DIM + 255) / 256), 256>>>(x, xb, (size_t)ROWS_TOT * IN_DIM);
    wtrans_kernel<<<dim3(DIM / 32, IN_DIM / 32), dim3(32, 8)>>>(w_in, wInT, IN_DIM, DIM);
    for (int l = 0; l < 2; l++) {
        wtrans_kernel<<<dim3(DIM / 32, DIM / 32), dim3(32, 8)>>>(wq + (size_t)l * DIM * DIM, wqT + (size_t)l * DIM * DIM, DIM, DIM);
        wtrans_kernel<<<dim3(DIM / 32, DIM / 32), dim3(32, 8)>>>(wk + (size_t)l * DIM * DIM, wkT + (size_t)l * DIM * DIM, DIM, DIM);
        wtrans_kernel<<<dim3(DIM / 32, DIM / 32), dim3(32, 8)>>>(wv + (size_t)l * DIM * DIM, wvT + (size_t)l * DIM * DIM, DIM, DIM);
        wtrans_kernel<<<dim3(DIM / 32, DIM / 32), dim3(32, 8)>>>(wo + (size_t)l * DIM * DIM, woT + (size_t)l * DIM * DIM, DIM, DIM);
        wtrans_kernel<<<dim3(FFH / 32, DIM / 32), dim3(32, 8)>>>(w1 + (size_t)l * DIM * FFH, w1T + (size_t)l * DIM * FFH, DIM, FFH);
        wtrans_kernel<<<dim3(DIM / 32, FFH / 32), dim3(32, 8)>>>(w2 + (size_t)l * FFH * DIM, w2T + (size_t)l * FFH * DIM, FFH, DIM);
    }

    tgemm_kernel<<<t256, blk256, TG_SMEM_BYTES>>>(xb, wInT, b_in, nullptr, h, nullptr,
                                                  ROWS_TOT, DIM, IN_DIM, 0);

    for (int l = 0; l < 2; l++) {
        // --- attention ---
        ln8_bf16_kernel<<<ROWS_TOT / 8, 256>>>(h, ln1_g + l * DIM, ln1_b + l * DIM, yb);
        tgemm_kernel<<<t256, blk256, TG_SMEM_BYTES>>>(yb, wqT + (size_t)l * DIM * DIM, nullptr, nullptr, nullptr, qb, ROWS_TOT, DIM, DIM, 0);
        tgemm_kernel<<<t256, blk256, TG_SMEM_BYTES>>>(yb, wkT + (size_t)l * DIM * DIM, nullptr, nullptr, nullptr, kb, ROWS_TOT, DIM, DIM, 0);
        tgemm_kernel<<<t256, blk256, TG_SMEM_BYTES>>>(yb, wvT + (size_t)l * DIM * DIM, nullptr, nullptr, nullptr, vb, ROWS_TOT, DIM, DIM, 0);

        projb_kernel<<<(MP * 64 + 255) / 256, 256>>>(proj + (size_t)l * MF * DH, pTb);
        kmax_init_kernel<<<1, 1024>>>(kmx);
        // kmax via fused feat kernel (no stores)
        feat_kernel<<<RH / 256, 256, FT_SMEM>>>(kb, pTb, nullptr, kmx, 2);
        // fused dd+exp feature passes
        feat_kernel<<<RH / 256, 256, FT_SMEM>>>(qb, pTb, qpB, nullptr, 0);
        feat_kernel<<<RH / 256, 256, FT_SMEM>>>(kb, pTb, kpB, kmx, 1);
        ktrans_kernel<<<gKT, dim3(32, 8)>>>(kpB, kpT);
        vtrans_kernel<<<BH, 256>>>(vb, vT);

        btgemm_kernel<<<gCtx, blk256, TG_SMEM_BYTES>>>(
            vT, (size_t)128 * NP, 127, kpT, (size_t)MP * NP,
            nullptr, ctxT, (size_t)128 * MP, MP, NP, 128, MP);
        btgemm_kernel<<<gAtt, blk256, TG_SMEM_BYTES>>>(
            qpB, (size_t)NN * MP, NN - 1, ctxT, (size_t)128 * MP,
            outA, nullptr, (size_t)NN * 128, 128, MP, NN, 66);

        divout_kernel<<<BH, 256>>>(outA, ob);

        tgemm_kernel<<<t256, blk256, TG_SMEM_BYTES>>>(ob, woT + (size_t)l * DIM * DIM, bo + l * DIM, h,
                                                      h, nullptr, ROWS_TOT, DIM, DIM, 0);

        // --- FFN ---
        ln8_bf16_kernel<<<ROWS_TOT / 8, 256>>>(h, ln2_g + l * DIM, ln2_b + l * DIM, yb);
        tgemm_kernel<<<t1024, blk256, TG_SMEM_BYTES>>>(yb, w1T + (size_t)l * DIM * FFH, b1 + l * FFH, nullptr,
                                                       nullptr, ffhb, ROWS_TOT, FFH, DIM, 1);
        tgemm_kernel<<<t256, blk256, TG_SMEM_BYTES>>>(ffhb, w2T + (size_t)l * FFH * DIM, b2 + l * DIM, h,
                                                      h, nullptr, ROWS_TOT, DIM, FFH, 0);
    }

    pool_kernel<<<BB, 256>>>(h, pool);
    ln_f32_kernel<<<BB, 256>>>(pool, hln_g, hln_b, z);
    head1_kernel<<<BB, 128>>>(z, wh1, bh1, z1);
    head2_kernel<<<BB, 128>>>(z1, wh2, bh2, out);
}

// round 16
// speedup vs baseline: 1.3661x; 1.0043x over previous
#include <cuda_runtime.h>
#include <cuda_bf16.h>
#include <math.h>
#include <limits.h>
#include <stdint.h>

// ---------------- problem constants ----------------
#define BB 256
#define NN 300
#define IN_DIM 1280
#define DIM 256
#define HEADS 4
#define DH 64
#define MF 266            // NB_FEAT
#define MP 320            // padded feature dim
#define NP 320            // padded sequence dim per head
#define FFH 1024
#define ROWS_TOT (BB*NN)  // 76800
#define RH (ROWS_TOT*HEADS) // 307200
#define BH (BB*HEADS)       // 1024
#define RPB (NN*HEADS)      // rows per batch in dd view = 1200

#define LN_EPS 1e-5f
#define KEPS 1e-4f
#define RATIO 0.061314066f
#define NORM 0.35355339059327373f

// ---------------- scratch ----------------
__device__ float          g_h   [ROWS_TOT*DIM];
__device__ __nv_bfloat16  g_yb  [ROWS_TOT*DIM];
__device__ __nv_bfloat16  g_qkvb[(size_t)ROWS_TOT*768];
__device__ __nv_bfloat16  g_ob  [ROWS_TOT*DIM];
__device__ __nv_bfloat16  g_ffhb[ROWS_TOT*FFH];
__device__ __nv_bfloat16  g_xb  [ROWS_TOT*IN_DIM];
__device__ __nv_bfloat16  g_qpB [(size_t)BH*NN*MP];
__device__ __nv_bfloat16  g_kpB [(size_t)BH*NN*MP];
__device__ __nv_bfloat16  g_kpT [(size_t)BH*MP*NP];
__device__ __nv_bfloat16  g_vT  [(size_t)BH*128*NP];
__device__ __nv_bfloat16  g_ctxT[(size_t)BH*128*MP];
__device__ float          g_outA[(size_t)BH*NN*64];
__device__ int            g_kmax[BH];
__device__ float          g_pool[BB*DIM];
__device__ float          g_z   [BB*DIM];
__device__ float          g_z1  [BB*128];
__device__ __nv_bfloat16  g_pTb [MP*64];
__device__ __nv_bfloat16  g_wInT[DIM*IN_DIM];
__device__ __nv_bfloat16  g_wqkvT[2][3*DIM*DIM];
__device__ __nv_bfloat16  g_woT [2][DIM*DIM];
__device__ __nv_bfloat16  g_w1T [2][FFH*DIM];
__device__ __nv_bfloat16  g_w2T [2][DIM*FFH];

// ---------------- helpers ----------------
__device__ __forceinline__ int f2o(float f) {
    int i = __float_as_int(f);
    return i >= 0 ? i : (i ^ 0x7FFFFFFF);
}
__device__ __forceinline__ float o2f(int i) {
    return __int_as_float(i >= 0 ? i : (i ^ 0x7FFFFFFF));
}
__device__ __forceinline__ float tanh_fast(float a) {
    float t = __expf(-2.0f * fabsf(a));
    float r = (1.0f - t) / (1.0f + t);
    return copysignf(r, a);
}
__device__ __forceinline__ float gelu_tanh(float x) {
    float x3 = x * x * x;
    return 0.5f * x * (1.0f + tanh_fast(0.7978845608028654f * (x + 0.044715f * x3)));
}
__device__ __forceinline__ float blockReduceSum256(float v) {
    __shared__ float sh[8];
    __syncthreads();
    int lane = threadIdx.x & 31, w = threadIdx.x >> 5;
    #pragma unroll
    for (int o = 16; o; o >>= 1) v += __shfl_xor_sync(0xFFFFFFFFu, v, o);
    if (lane == 0) sh[w] = v;
    __syncthreads();
    if (threadIdx.x == 0) {
        float s = 0.f;
        #pragma unroll
        for (int i = 0; i < 8; i++) s += sh[i];
        sh[0] = s;
    }
    __syncthreads();
    return sh[0];
}
__device__ __forceinline__ uint32_t smem_u32(const void* p) {
    uint32_t a;
    asm("{ .reg .u64 t; cvta.to.shared.u64 t, %1; cvt.u32.u64 %0, t; }" : "=r"(a) : "l"(p));
    return a;
}

#define SWZ(off) ((off) ^ (((off) >> 3) & 0x70))

__device__ __forceinline__ void ldmatrix4(uint32_t* r, uint32_t addr) {
    asm volatile("ldmatrix.sync.aligned.m8n8.x4.shared.b16 {%0,%1,%2,%3}, [%4];"
        : "=r"(r[0]), "=r"(r[1]), "=r"(r[2]), "=r"(r[3]) : "r"(addr));
}
__device__ __forceinline__ void mma16816(float* c, const uint32_t* a, uint32_t b0, uint32_t b1) {
    asm volatile(
        "mma.sync.aligned.m16n8k16.row.col.f32.bf16.bf16.f32 "
        "{%0,%1,%2,%3}, {%4,%5,%6,%7}, {%8,%9}, {%0,%1,%2,%3};"
        : "+f"(c[0]), "+f"(c[1]), "+f"(c[2]), "+f"(c[3])
        : "r"(a[0]), "r"(a[1]), "r"(a[2]), "r"(a[3]), "r"(b0), "r"(b1));
}
__device__ __forceinline__ void cp_async16(uint32_t smem, const void* g) {
    asm volatile("cp.async.cg.shared.global [%0], [%1], 16;" :: "r"(smem), "l"(g));
}
__device__ __forceinline__ void cp_commit() {
    asm volatile("cp.async.commit_group;" ::: "memory");
}
__device__ __forceinline__ void cp_wait2() {
    asm volatile("cp.async.wait_group 2;" ::: "memory");
}
__device__ __forceinline__ void cp_wait0() {
    asm volatile("cp.async.wait_group 0;" ::: "memory");
}

// stage stride: A 16384 + B 8192 = 24576; 4 stages = 98304
#define TG_STAGE 24576
#define TG_SMEM_BYTES (4*TG_STAGE)

// ---------------- bf16 HMMA GEMM (128x64 tile, 4-stage pipeline, 1 sync/chunk) ----
__global__ void __launch_bounds__(256, 2) tgemm_kernel(
    const __nv_bfloat16* __restrict__ A, const __nv_bfloat16* __restrict__ Bt,
    const float* __restrict__ bias, const float* __restrict__ res,
    float* __restrict__ Cf, __nv_bfloat16* __restrict__ Cb,
    int M, int N, int K, int act)
{
    extern __shared__ __nv_bfloat16 sm[];
    const uint32_t base = smem_u32(sm);

    const int tid = threadIdx.x;
    const int wid = tid >> 5, lane = tid & 31;
    const int wm = wid & 3, wn = wid >> 2;
    const int row0 = blockIdx.y * 128, col0 = blockIdx.x * 64;
    const int tileid = lane >> 3, rit = lane & 7;
    const int gid = lane >> 2, tig = lane & 3;

    float acc[2][4][4];
    #pragma unroll
    for (int mt = 0; mt < 2; mt++)
        #pragma unroll
        for (int j = 0; j < 4; j++)
            #pragma unroll
            for (int r = 0; r < 4; r++) acc[mt][j][r] = 0.f;

    const int nch = K >> 6;
    const __nv_bfloat16* Arow = A + (size_t)row0 * K;
    const __nv_bfloat16* Brow = Bt + (size_t)col0 * K;

    #pragma unroll
    for (int s = 0; s < 3; s++) {
        if (s < nch) {
            const int k0 = s << 6;
            const uint32_t aS = base + s * TG_STAGE;
            const uint32_t bS = aS + 16384;
            #pragma unroll
            for (int i = 0; i < 4; i++) {
                int lin = tid + i * 256;
                int r = lin >> 3, c8 = lin & 7;
                cp_async16(aS + SWZ(r * 128 + c8 * 16), Arow + (size_t)r * K + k0 + c8 * 8);
            }
            #pragma unroll
            for (int i = 0; i < 2; i++) {
                int lin = tid + i * 256;
                int r = lin >> 3, c8 = lin & 7;
                cp_async16(bS + SWZ(r * 128 + c8 * 16), Brow + (size_t)r * K + k0 + c8 * 8);
            }
        }
        cp_commit();
    }

    for (int c = 0; c < nch; c++) {
        cp_wait2();
        __syncthreads();
        const int stg = c & 3;
        const uint32_t aB = base + stg * TG_STAGE;
        const uint32_t bB = aB + 16384;
        #pragma unroll
        for (int kk = 0; kk < 4; kk++) {
            uint32_t af[2][4];
            #pragma unroll
            for (int mt = 0; mt < 2; mt++) {
                int off = (wm * 32 + mt * 16 + (tileid & 1) * 8 + rit) * 128
                          + kk * 32 + (tileid >> 1) * 16;
                ldmatrix4(af[mt], aB + SWZ(off));
            }
            uint32_t bf[2][4];
            #pragma unroll
            for (int nt = 0; nt < 2; nt++) {
                int off = (wn * 32 + nt * 16 + (tileid & 1) * 8 + rit) * 128
                          + kk * 32 + (tileid >> 1) * 16;
                ldmatrix4(bf[nt], bB + SWZ(off));
            }
            #pragma unroll
            for (int mt = 0; mt < 2; mt++)
                #pragma unroll
                for (int j = 0; j < 4; j++) {
                    int nt = j >> 1, sel = j & 1;
                    mma16816(acc[mt][j], af[mt], bf[nt][sel], bf[nt][2 + sel]);
                }
        }
        if (c + 3 < nch) {
            const int k0 = (c + 3) << 6;
            const int ns = (c + 3) & 3;
            const uint32_t aS = base + ns * TG_STAGE;
            const uint32_t bS = aS + 16384;
            #pragma unroll
            for (int i = 0; i < 4; i++) {
                int lin = tid + i * 256;
                int r = lin >> 3, c8 = lin & 7;
                cp_async16(aS + SWZ(r * 128 + c8 * 16), Arow + (size_t)r * K + k0 + c8 * 8);
            }
            #pragma unroll
            for (int i = 0; i < 2; i++) {
                int lin = tid + i * 256;
                int r = lin >> 3, c8 = lin & 7;
                cp_async16(bS + SWZ(r * 128 + c8 * 16), Brow + (size_t)r * K + k0 + c8 * 8);
            }
        }
        cp_commit();
    }

    #pragma unroll
    for (int mt = 0; mt < 2; mt++) {
        #pragma unroll
        for (int j = 0; j < 4; j++) {
            #pragma unroll
            for (int half = 0; half < 2; half++) {
                int r = row0 + wm * 32 + mt * 16 + gid + half * 8;
                int cidx = col0 + wn * 32 + j * 8 + tig * 2;
                float v0 = acc[mt][j][half * 2 + 0];
                float v1 = acc[mt][j][half * 2 + 1];
                if (bias) { v0 += bias[cidx]; v1 += bias[cidx + 1]; }
                if (act == 1) { v0 = gelu_tanh(v0); v1 = gelu_tanh(v1); }
                if (res) {
                    float2 r2 = *(const float2*)(res + (size_t)r * N + cidx);
                    v0 += r2.x; v1 += r2.y;
                }
                if (Cf) *(float2*)(Cf + (size_t)r * N + cidx) = make_float2(v0, v1);
                if (Cb) *(__nv_bfloat162*)(Cb + (size_t)r * N + cidx) = __floats2bfloat162_rn(v0, v1);
            }
        }
    }
}

// ---------------- batched bf16 HMMA GEMM (128x64 tile, 4-stage) ----------------
__global__ void __launch_bounds__(256, 2) btgemm_kernel(
    const __nv_bfloat16* __restrict__ A, size_t aBS, int aClamp,
    const __nv_bfloat16* __restrict__ Bt, size_t bBS,
    float* __restrict__ Cf, __nv_bfloat16* __restrict__ Cb, size_t cBS,
    int ldc, int K, int mValid, int nStore)
{
    extern __shared__ __nv_bfloat16 sm[];
    const uint32_t base = smem_u32(sm);

    const int tid = threadIdx.x;
    const int wid = tid >> 5, lane = tid & 31;
    const int wm = wid & 3, wn = wid >> 2;
    const int row0 = blockIdx.y * 128, col0 = blockIdx.x * 64;
    const int tileid = lane >> 3, rit = lane & 7;
    const int gid = lane >> 2, tig = lane & 3;
    const int bh = blockIdx.z;

    const __nv_bfloat16* Ab = A + (size_t)bh * aBS;
    const __nv_bfloat16* Bb = Bt + (size_t)bh * bBS + (size_t)col0 * K;

    float acc[2][4][4];
    #pragma unroll
    for (int mt = 0; mt < 2; mt++)
        #pragma unroll
        for (int j = 0; j < 4; j++)
            #pragma unroll
            for (int r = 0; r < 4; r++) acc[mt][j][r] = 0.f;

    const int nch = K >> 6;
    #pragma unroll
    for (int s = 0; s < 3; s++) {
        if (s < nch) {
            const int k0 = s << 6;
            const uint32_t aS = base + s * TG_STAGE;
            const uint32_t bS = aS + 16384;
            #pragma unroll
            for (int i = 0; i < 4; i++) {
                int lin = tid + i * 256;
                int r = lin >> 3, c8 = lin & 7;
                int rg = min(row0 + r, aClamp);
                cp_async16(aS + SWZ(r * 128 + c8 * 16), Ab + (size_t)rg * K + k0 + c8 * 8);
            }
            #pragma unroll
            for (int i = 0; i < 2; i++) {
                int lin = tid + i * 256;
                int r = lin >> 3, c8 = lin & 7;
                cp_async16(bS + SWZ(r * 128 + c8 * 16), Bb + (size_t)r * K + k0 + c8 * 8);
            }
        }
        cp_commit();
    }

    for (int c = 0; c < nch; c++) {
        cp_wait2();
        __syncthreads();
        const int stg = c & 3;
        const uint32_t aB = base + stg * TG_STAGE;
        const uint32_t bB = aB + 16384;
        #pragma unroll
        for (int kk = 0; kk < 4; kk++) {
            uint32_t af[2][4];
            #pragma unroll
            for (int mt = 0; mt < 2; mt++) {
                int off = (wm * 32 + mt * 16 + (tileid & 1) * 8 + rit) * 128
                          + kk * 32 + (tileid >> 1) * 16;
                ldmatrix4(af[mt], aB + SWZ(off));
            }
            uint32_t bf[2][4];
            #pragma unroll
            for (int nt = 0; nt < 2; nt++) {
                int off = (wn * 32 + nt * 16 + (tileid & 1) * 8 + rit) * 128
                          + kk * 32 + (tileid >> 1) * 16;
                ldmatrix4(bf[nt], bB + SWZ(off));
            }
            #pragma unroll
            for (int mt = 0; mt < 2; mt++)
                #pragma unroll
                for (int j = 0; j < 4; j++) {
                    int nt = j >> 1, sel = j & 1;
                    mma16816(acc[mt][j], af[mt], bf[nt][sel], bf[nt][2 + sel]);
                }
        }
        if (c + 3 < nch) {
            const int k0 = (c + 3) << 6;
            const int ns = (c + 3) & 3;
            const uint32_t aS = base + ns * TG_STAGE;
            const uint32_t bS = aS + 16384;
            #pragma unroll
            for (int i = 0; i < 4; i++) {
                int lin = tid + i * 256;
                int r = lin >> 3, c8 = lin & 7;
                int rg = min(row0 + r, aClamp);
                cp_async16(aS + SWZ(r * 128 + c8 * 16), Ab + (size_t)rg * K + k0 + c8 * 8);
            }
            #pragma unroll
            for (int i = 0; i < 2; i++) {
                int lin = tid + i * 256;
                int r = lin >> 3, c8 = lin & 7;
                cp_async16(bS + SWZ(r * 128 + c8 * 16), Bb + (size_t)r * K + k0 + c8 * 8);
            }
        }
        cp_commit();
    }

    float* Cfb = Cf ? Cf + (size_t)bh * cBS : nullptr;
    __nv_bfloat16* Cbb = Cb ? Cb + (size_t)bh * cBS : nullptr;
    #pragma unroll
    for (int mt = 0; mt < 2; mt++) {
        #pragma unroll
        for (int j = 0; j < 4; j++) {
            #pragma unroll
            for (int half = 0; half < 2; half++) {
                int r = row0 + wm * 32 + mt * 16 + gid + half * 8;
                if (r >= mValid) continue;
                int cidx = col0 + wn * 32 + j * 8 + tig * 2;
                if (cidx >= nStore) continue;
                float v0 = acc[mt][j][half * 2 + 0];
                float v1 = acc[mt][j][half * 2 + 1];
                if (Cfb) *(float2*)(Cfb + (size_t)r * ldc + cidx) = make_float2(v0, v1);
                if (Cbb) *(__nv_bfloat162*)(Cbb + (size_t)r * ldc + cidx) = __floats2bfloat162_rn(v0, v1);
            }
        }
    }
}

// ---------------- fused feature kernel ----------------
// src is qkv buffer [ROWS][768]; token w reads at (w>>2)*768 + (w&3)*64 + qkvOff.
// mode 0: q (per-row max stab); mode 1: k (global kmax stab); mode 2: kmax only.
#define FT_PROJ_BYTES (MP*128)          // 40960
#define FT_ATILE 4096
#define FT_SMEM (FT_PROJ_BYTES + 2*FT_ATILE)   // 49152

__global__ void __launch_bounds__(256, 2) feat_kernel(
    const __nv_bfloat16* __restrict__ src, int qkvOff,
    const __nv_bfloat16* __restrict__ pTb,
    __nv_bfloat16* __restrict__ outp, int* __restrict__ kmax, int mode)
{
    extern __shared__ __nv_bfloat16 sm[];
    char* smc = (char*)sm;
    const uint32_t projS = smem_u32(sm);
    const uint32_t aS0 = projS + FT_PROJ_BYTES;
    __shared__ int smax[32];
    __shared__ float diag[32];
    __shared__ int gm[8];

    const int tid = threadIdx.x;
    const int lane = tid & 31;
    const int wid = tid >> 5;
    const int wm = wid & 1, wn = wid >> 1;        // 2 M-warps x 4 N-warps
    const int tileid = lane >> 3, rit = lane & 7;
    const int gid = lane >> 2, tig = lane & 3;
    const size_t base_tok = (size_t)blockIdx.x * 256;
    const int baseB = (int)(base_tok / RPB);

    if (tid < 8) gm[tid] = INT_MIN;

    // load proj (320 x 64 bf16, SW128)
    for (int i = tid; i < MP * 8; i += 256) {
        int r = i >> 3, c8 = i & 7;
        cp_async16(projS + SWZ(r * 128 + c8 * 16), pTb + (size_t)r * 64 + c8 * 8);
    }
    // load A tile 0
    {
        int r = tid >> 3, c8 = tid & 7;
        size_t w = base_tok + r;
        cp_async16(aS0 + SWZ(r * 128 + c8 * 16),
                   src + (w >> 2) * 768 + (w & 3) * 64 + qkvOff + c8 * 8);
    }
    cp_commit();
    cp_wait0();
    __syncthreads();

    for (int t = 0; t < 8; t++) {
        const int buf = t & 1;
        const uint32_t aB = aS0 + buf * FT_ATILE;
        if (t + 1 < 8) {
            int r = tid >> 3, c8 = tid & 7;
            size_t w = base_tok + (t + 1) * 32 + r;
            cp_async16(aS0 + ((t + 1) & 1) * FT_ATILE + SWZ(r * 128 + c8 * 16),
                       src + (w >> 2) * 768 + (w & 3) * 64 + qkvOff + c8 * 8);
            cp_commit();
        }
        if (mode != 2) {
            if (tid < 32) smax[tid] = INT_MIN;
            {
                int r = tid >> 3, c8 = tid & 7;
                uint4 d = *(const uint4*)(smc + FT_PROJ_BYTES + buf * FT_ATILE + SWZ(r * 128 + c8 * 16));
                const __nv_bfloat16* pv = (const __nv_bfloat16*)&d;
                float s = 0.f;
                #pragma unroll
                for (int i = 0; i < 8; i++) {
                    float f = __bfloat162float(pv[i]);
                    s = fmaf(f, f, s);
                }
                #pragma unroll
                for (int o = 4; o; o >>= 1) s += __shfl_xor_sync(0xFFFFFFFFu, s, o);
                if ((lane & 7) == 0) diag[r] = 0.0625f * s;
            }
        }
        __syncthreads();

        float acc[10][4];
        #pragma unroll
        for (int j = 0; j < 10; j++)
            #pragma unroll
            for (int r = 0; r < 4; r++) acc[j][r] = 0.f;
        #pragma unroll
        for (int kk = 0; kk < 4; kk++) {
            uint32_t af[4];
            {
                int off = (wm * 16 + (tileid & 1) * 8 + rit) * 128
                          + kk * 32 + (tileid >> 1) * 16;
                ldmatrix4(af, aB + SWZ(off));
            }
            uint32_t bf[5][4];
            #pragma unroll
            for (int nt = 0; nt < 5; nt++) {
                int off = (wn * 80 + nt * 16 + (tileid & 1) * 8 + rit) * 128
                          + kk * 32 + (tileid >> 1) * 16;
                ldmatrix4(bf[nt], projS + SWZ(off));
            }
            #pragma unroll
            for (int j = 0; j < 10; j++) {
                int nt = j >> 1, sel = j & 1;
                mma16816(acc[j], af, bf[nt][sel], bf[nt][2 + sel]);
            }
        }

        if (mode != 1) {
            float mx0 = -1e30f, mx8 = -1e30f;
            #pragma unroll
            for (int j = 0; j < 10; j++) {
                int cb = wn * 80 + j * 8 + tig * 2;
                if (cb < MF)     { mx0 = fmaxf(mx0, acc[j][0]); mx8 = fmaxf(mx8, acc[j][2]); }
                if (cb + 1 < MF) { mx0 = fmaxf(mx0, acc[j][1]); mx8 = fmaxf(mx8, acc[j][3]); }
            }
            #pragma unroll
            for (int o = 2; o; o >>= 1) {
                mx0 = fmaxf(mx0, __shfl_xor_sync(0xFFFFFFFFu, mx0, o));
                mx8 = fmaxf(mx8, __shfl_xor_sync(0xFFFFFFFFu, mx8, o));
            }
            if (tig == 0) {
                if (mode == 0) {
                    atomicMax(&smax[wm * 16 + gid], f2o(mx0));
                    atomicMax(&smax[wm * 16 + gid + 8], f2o(mx8));
                } else {
                    int r0l = wm * 16 + gid;
                    size_t w0 = base_tok + t * 32 + r0l;
                    size_t w8 = w0 + 8;
                    int b0v = (int)(w0 / RPB), rem0 = (int)(w0 - (size_t)b0v * RPB);
                    int b8v = (int)(w8 / RPB), rem8 = (int)(w8 - (size_t)b8v * RPB);
                    atomicMax(&gm[(b0v - baseB) * 4 + (rem0 & 3)], f2o(mx0));
                    atomicMax(&gm[(b8v - baseB) * 4 + (rem8 & 3)], f2o(mx8));
                }
            }
        }
        __syncthreads();

        if (mode != 2) {
            int r0l = wm * 16 + gid, r8l = r0l + 8;
            size_t w0 = base_tok + t * 32 + r0l;
            size_t w8 = w0 + 8;
            float dg0 = diag[r0l], dg8 = diag[r8l];
            float st0, st8;
            int b0v = (int)(w0 / RPB), rem0 = (int)(w0 - (size_t)b0v * RPB);
            int b8v = (int)(w8 / RPB), rem8 = (int)(w8 - (size_t)b8v * RPB);
            if (mode == 1) {
                st0 = o2f(kmax[b0v * HEADS + (rem0 & 3)]);
                st8 = o2f(kmax[b8v * HEADS + (rem8 & 3)]);
            } else {
                st0 = o2f(smax[r0l]);
                st8 = o2f(smax[r8l]);
            }
            __nv_bfloat16* p0 = outp + ((size_t)(b0v * HEADS + (rem0 & 3)) * NN + (rem0 >> 2)) * MP;
            __nv_bfloat16* p8 = outp + ((size_t)(b8v * HEADS + (rem8 & 3)) * NN + (rem8 >> 2)) * MP;
            #pragma unroll
            for (int j = 0; j < 10; j++) {
                int cb = wn * 80 + j * 8 + tig * 2;
                float a0 = (cb < MF)     ? RATIO * (__expf(acc[j][0] - dg0 - st0) + KEPS) : 0.f;
                float a1 = (cb + 1 < MF) ? RATIO * (__expf(acc[j][1] - dg0 - st0) + KEPS) : 0.f;
                float c0 = (cb < MF)     ? RATIO * (__expf(acc[j][2] - dg8 - st8) + KEPS) : 0.f;
                float c1 = (cb + 1 < MF) ? RATIO * (__expf(acc[j][3] - dg8 - st8) + KEPS) : 0.f;
                *(__nv_bfloat162*)(p0 + cb) = __floats2bfloat162_rn(a0, a1);
                *(__nv_bfloat162*)(p8 + cb) = __floats2bfloat162_rn(c0, c1);
            }
        }
        if (t + 1 < 8) {
            cp_wait0();
        }
        __syncthreads();
    }

    if (mode == 2) {
        if (tid < 8) {
            int bb = baseB + (tid >> 2);
            if (gm[tid] != INT_MIN && bb < BB)
                atomicMax(&kmax[bb * HEADS + (tid & 3)], gm[tid]);
        }
    }
}

// kpB [bh][n][m] -> kpT [bh][m][n] with zero-fill n>=NN
__global__ void ktrans_kernel(const __nv_bfloat16* __restrict__ kpB,
                              __nv_bfloat16* __restrict__ kpT)
{
    __shared__ __nv_bfloat16 s[32][33];
    int bh = blockIdx.z;
    int n0 = blockIdx.x * 32, m0 = blockIdx.y * 32;
    int tx = threadIdx.x, ty = threadIdx.y;    // 32 x 8
    const __nv_bfloat16* src = kpB + (size_t)bh * NN * MP;
    #pragma unroll
    for (int i = 0; i < 32; i += 8) {
        int n = n0 + ty + i;
        s[ty + i][tx] = (n < NN) ? src[(size_t)n * MP + m0 + tx] : __float2bfloat16(0.f);
    }
    __syncthreads();
    __nv_bfloat16* dst = kpT + (size_t)bh * MP * NP;
    #pragma unroll
    for (int i = 0; i < 32; i += 8)
        dst[(size_t)(m0 + ty + i) * NP + n0 + tx] = s[tx][ty + i];
}

// ---------------- prep kernels ----------------
__global__ void f2b_kernel(const float* __restrict__ a, __nv_bfloat16* __restrict__ b, size_t n) {
    size_t i = (size_t)blockIdx.x * blockDim.x + threadIdx.x;
    if (i < n) b[i] = __float2bfloat16(a[i]);
}

// generic transpose with layer batching over grid.z
__global__ void wtrans_kernel(const float* __restrict__ W, __nv_bfloat16* __restrict__ Wt,
                              int K, int N, size_t sStride, size_t dStride) {
    __shared__ float t[32][33];
    const float* Ws = W + blockIdx.z * sStride;
    __nv_bfloat16* Wd = Wt + blockIdx.z * dStride;
    int k0 = blockIdx.y * 32, n0 = blockIdx.x * 32;
    int tx = threadIdx.x, ty = threadIdx.y;
    #pragma unroll
    for (int i = 0; i < 32; i += 8)
        t[ty + i][tx] = Ws[(size_t)(k0 + ty + i) * N + n0 + tx];
    __syncthreads();
    #pragma unroll
    for (int i = 0; i < 32; i += 8)
        Wd[(size_t)(n0 + ty + i) * K + k0 + tx] = __float2bfloat16(t[tx][ty + i]);
}

// batched DIMxDIM transposes: z = l*4 + widx; widx 0..2 -> wqkvT, 3 -> woT
__global__ void wtrans8_kernel(const float* __restrict__ wq, const float* __restrict__ wk,
                               const float* __restrict__ wv, const float* __restrict__ wo,
                               __nv_bfloat16* __restrict__ wqkvT, __nv_bfloat16* __restrict__ woT) {
    __shared__ float t[32][33];
    int z = blockIdx.z;
    int l = z >> 2, widx = z & 3;
    const float* srcs[4] = {wq, wk, wv, wo};
    const float* Ws = srcs[widx] + (size_t)l * DIM * DIM;
    __nv_bfloat16* Wd = (widx < 3)
        ? wqkvT + (size_t)l * 3 * DIM * DIM + (size_t)widx * DIM * DIM
        : woT + (size_t)l * DIM * DIM;
    int k0 = blockIdx.y * 32, n0 = blockIdx.x * 32;
    int tx = threadIdx.x, ty = threadIdx.y;
    #pragma unroll
    for (int i = 0; i < 32; i += 8)
        t[ty + i][tx] = Ws[(size_t)(k0 + ty + i) * DIM + n0 + tx];
    __syncthreads();
    #pragma unroll
    for (int i = 0; i < 32; i += 8)
        Wd[(size_t)(n0 + ty + i) * DIM + k0 + tx] = __float2bfloat16(t[tx][ty + i]);
}

__global__ void projb_kernel(const float* __restrict__ proj, __nv_bfloat16* __restrict__ pTb) {
    int i = blockIdx.x * 256 + threadIdx.x;
    if (i >= MP * 64) return;
    int m = i >> 6, d = i & 63;
    pTb[i] = __float2bfloat16((m < MF) ? proj[m * 64 + d] * NORM : 0.f);
}

// ---------------- layernorm (warp-per-row, 8 rows/block) ----------------
__global__ void __launch_bounds__(256) ln8_bf16_kernel(
    const float* __restrict__ x, const float* __restrict__ g,
    const float* __restrict__ b, __nv_bfloat16* __restrict__ y)
{
    int warp = threadIdx.x >> 5, lane = threadIdx.x & 31;
    int row = blockIdx.x * 8 + warp;
    const float* xr = x + (size_t)row * DIM + lane * 8;
    float4 a0 = *(const float4*)xr;
    float4 a1 = *(const float4*)(xr + 4);
    float v[8] = {a0.x, a0.y, a0.z, a0.w, a1.x, a1.y, a1.z, a1.w};

    float s = ((v[0] + v[1]) + (v[2] + v[3])) + ((v[4] + v[5]) + (v[6] + v[7]));
    #pragma unroll
    for (int o = 16; o; o >>= 1) s += __shfl_xor_sync(0xFFFFFFFFu, s, o);
    float mu = s * (1.0f / DIM);

    float q = 0.f;
    #pragma unroll
    for (int i = 0; i < 8; i++) {
        float d = v[i] - mu;
        v[i] = d;
        q = fmaf(d, d, q);
    }
    #pragma unroll
    for (int o = 16; o; o >>= 1) q += __shfl_xor_sync(0xFFFFFFFFu, q, o);
    float rs = rsqrtf(q * (1.0f / DIM) + LN_EPS);

    float4 g0 = *(const float4*)(g + lane * 8);
    float4 g1 = *(const float4*)(g + lane * 8 + 4);
    float4 b0 = *(const float4*)(b + lane * 8);
    float4 b1 = *(const float4*)(b + lane * 8 + 4);
    float gg[8] = {g0.x, g0.y, g0.z, g0.w, g1.x, g1.y, g1.z, g1.w};
    float bb2[8] = {b0.x, b0.y, b0.z, b0.w, b1.x, b1.y, b1.z, b1.w};

    __nv_bfloat162 o2[4];
    #pragma unroll
    for (int i = 0; i < 4; i++) {
        float r0 = v[2 * i] * rs * gg[2 * i] + bb2[2 * i];
        float r1 = v[2 * i + 1] * rs * gg[2 * i + 1] + bb2[2 * i + 1];
        o2[i] = __floats2bfloat162_rn(r0, r1);
    }
    *(uint4*)(y + (size_t)row * DIM + lane * 8) = *(uint4*)o2;
}

__global__ void ln_f32_kernel(const float* __restrict__ x, const float* __restrict__ g,
                              const float* __restrict__ b, float* __restrict__ y)
{
    int row = blockIdx.x;
    int t = threadIdx.x;
    float v = x[(size_t)row * DIM + t];
    float mu = blockReduceSum256(v) * (1.0f / DIM);
    float d = v - mu;
    float var = blockReduceSum256(d * d) * (1.0f / DIM);
    y[(size_t)row * DIM + t] = d * rsqrtf(var + LN_EPS) * g[t] + b[t];
}

__global__ void kmax_init_kernel(int* __restrict__ kmax) {
    int i = blockIdx.x * blockDim.x + threadIdx.x;
    if (i < BH) kmax[i] = INT_MIN;
}

// v transpose from qkv buffer (stride 768, offset 512): vAugT[bh][d][n], d=64 = ones
__global__ void __launch_bounds__(256) vtrans_kernel(
    const __nv_bfloat16* __restrict__ v, __nv_bfloat16* __restrict__ vT)
{
    __shared__ float t[32][65];
    int bh = blockIdx.x, b = bh >> 2, h = bh & 3;
    int tid = threadIdx.x;
    int lane = tid & 31;
    __nv_bfloat16* vb = vT + (size_t)bh * 128 * NP;

    for (int it = 0; it < 10; it++) {
        int n0 = it * 32;
        int d = tid & 63;
        #pragma unroll
        for (int sub = 0; sub < 8; sub++) {
            int n_l = (tid >> 6) + 4 * sub;
            int n_g = n0 + n_l;
            t[n_l][d] = (n_g < NN) ?
                __bfloat162float(v[((size_t)(b * NN + n_g)) * 768 + h * 64 + d]) : 0.f;
        }
        __syncthreads();
        int dcol = tid >> 5;
        #pragma unroll
        for (int j = 0; j < 8; j++) {
            int d2 = dcol + 8 * j;
            vb[(size_t)d2 * NP + n0 + lane] = __float2bfloat16(t[lane][d2]);
        }
        __syncthreads();
    }
    for (int idx = tid; idx < 64 * NP; idx += 256) {
        int d = 64 + idx / NP, n = idx % NP;
        float val = (d == 64 && n < NN) ? 1.f : 0.f;
        vb[(size_t)d * NP + n] = __float2bfloat16(val);
    }
}

// divide: den recomputed from ctxT row 64 (== ksum) dot qp row; numerator from outA[NN][64]
__global__ void __launch_bounds__(256) divout_kernel(
    const float* __restrict__ outA, const __nv_bfloat16* __restrict__ ctxT,
    const __nv_bfloat16* __restrict__ qpB, __nv_bfloat16* __restrict__ ob)
{
    __shared__ float ks[MP];
    __shared__ float den[NN];
    int bh = blockIdx.x, b = bh >> 2, h = bh & 3;
    int tid = threadIdx.x;
    int wid = tid >> 5, lane = tid & 31;
    const __nv_bfloat16* kr = ctxT + (size_t)bh * 128 * MP + (size_t)64 * MP;
    for (int m = tid; m < MP; m += 256) ks[m] = __bfloat162float(kr[m]);
    __syncthreads();
    const __nv_bfloat16* qbase = qpB + (size_t)bh * NN * MP;
    for (int n = wid; n < NN; n += 8) {
        const __nv_bfloat16* q = qbase + (size_t)n * MP;
        float s = 0.f;
        #pragma unroll
        for (int i = 0; i < 10; i++) {
            int m = lane + 32 * i;
            s = fmaf(__bfloat162float(q[m]), ks[m], s);
        }
        #pragma unroll
        for (int o = 16; o; o >>= 1) s += __shfl_xor_sync(0xFFFFFFFFu, s, o);
        if (lane == 0) den[n] = s;
    }
    __syncthreads();
    const float* base = outA + (size_t)bh * NN * 64;
    for (int idx = tid; idx < NN * 64; idx += 256) {
        int n = idx >> 6, d = idx & 63;
        ob[((size_t)(b * NN + n)) * DIM + h * 64 + d] =
            __float2bfloat16(base[idx] / den[n]);
    }
}

// ---------------- pooling & head ----------------
__global__ void pool_kernel(const float* __restrict__ h, float* __restrict__ pooled)
{
    int b = blockIdx.x, c = threadIdx.x;
    const float* p = h + (size_t)b * NN * DIM + c;
    float s0 = 0.f, s1 = 0.f, s2 = 0.f, s3 = 0.f;
    for (int n = 0; n < NN; n += 4) {
        s0 += p[(size_t)(n + 0) * DIM];
        s1 += p[(size_t)(n + 1) * DIM];
        s2 += p[(size_t)(n + 2) * DIM];
        s3 += p[(size_t)(n + 3) * DIM];
    }
    pooled[b * DIM + c] = ((s0 + s1) + (s2 + s3)) * (1.0f / NN);
}

__global__ void head1_kernel(const float* __restrict__ z, const float* __restrict__ w,
                             const float* __restrict__ bias, float* __restrict__ z1)
{
    __shared__ float zs[DIM];
    int b = blockIdx.x, j = threadIdx.x;
    for (int c = j; c < DIM; c += 128) zs[c] = z[b * DIM + c];
    __syncthreads();
    float s0 = 0.f, s1 = 0.f, s2 = 0.f, s3 = 0.f;
    #pragma unroll 1
    for (int c = 0; c < DIM; c += 4) {
        s0 = fmaf(zs[c + 0], w[(c + 0) * 128 + j], s0);
        s1 = fmaf(zs[c + 1], w[(c + 1) * 128 + j], s1);
        s2 = fmaf(zs[c + 2], w[(c + 2) * 128 + j], s2);
        s3 = fmaf(zs[c + 3], w[(c + 3) * 128 + j], s3);
    }
    z1[b * 128 + j] = fmaxf(((s0 + s1) + (s2 + s3)) + bias[j], 0.f);
}

__global__ void head2_kernel(const float* __restrict__ z1, const float* __restrict__ w,
                             const float* __restrict__ bias, float* __restrict__ out)
{
    __shared__ float sh[4];
    int b = blockIdx.x, j = threadIdx.x;
    float s = z1[b * 128 + j] * w[j];
    #pragma unroll
    for (int o = 16; o; o >>= 1) s += __shfl_xor_sync(0xFFFFFFFFu, s, o);
    if ((j & 31) == 0) sh[j >> 5] = s;
    __syncthreads();
    if (j == 0) {
        float t = sh[0] + sh[1] + sh[2] + sh[3] + bias[0];
        out[b] = 1.0f / (1.0f + __expf(-t));
    }
}

// ---------------- host ----------------
template <typename T> static T* symaddr(const void* sym) {
    void* p = nullptr;
    cudaGetSymbolAddress(&p, sym);
    return (T*)p;
}

extern "C" void kernel_launch(void* const* d_in, const int* in_sizes, int n_in,
                              void* d_out, int out_size)
{
    const float* x     = (const float*)d_in[0];
    const float* w_in  = (const float*)d_in[1];
    const float* b_in  = (const float*)d_in[2];
    const float* proj  = (const float*)d_in[3];
    const float* ln1_g = (const float*)d_in[4];
    const float* ln1_b = (const float*)d_in[5];
    const float* wq    = (const float*)d_in[6];
    const float* wk    = (const float*)d_in[7];
    const float* wv    = (const float*)d_in[8];
    const float* wo    = (const float*)d_in[9];
    const float* bo    = (const float*)d_in[10];
    const float* ln2_g = (const float*)d_in[11];
    const float* ln2_b = (const float*)d_in[12];
    const float* w1    = (const float*)d_in[13];
    const float* b1    = (const float*)d_in[14];
    const float* w2    = (const float*)d_in[15];
    const float* b2    = (const float*)d_in[16];
    const float* hln_g = (const float*)d_in[17];
    const float* hln_b = (const float*)d_in[18];
    const float* wh1   = (const float*)d_in[19];
    const float* bh1   = (const float*)d_in[20];
    const float* wh2   = (const float*)d_in[21];
    const float* bh2   = (const float*)d_in[22];
    float* out = (float*)d_out;

    float* h    = symaddr<float>(g_h);
    __nv_bfloat16* yb   = symaddr<__nv_bfloat16>(g_yb);
    __nv_bfloat16* qkvb = symaddr<__nv_bfloat16>(g_qkvb);
    __nv_bfloat16* ob   = symaddr<__nv_bfloat16>(g_ob);
    __nv_bfloat16* ffhb = symaddr<__nv_bfloat16>(g_ffhb);
    __nv_bfloat16* xb   = symaddr<__nv_bfloat16>(g_xb);
    __nv_bfloat16* qpB  = symaddr<__nv_bfloat16>(g_qpB);
    __nv_bfloat16* kpB  = symaddr<__nv_bfloat16>(g_kpB);
    __nv_bfloat16* kpT  = symaddr<__nv_bfloat16>(g_kpT);
    __nv_bfloat16* vT   = symaddr<__nv_bfloat16>(g_vT);
    __nv_bfloat16* ctxT = symaddr<__nv_bfloat16>(g_ctxT);
    float* outA = symaddr<float>(g_outA);
    int*   kmx  = symaddr<int>(g_kmax);
    float* pool = symaddr<float>(g_pool);
    float* z    = symaddr<float>(g_z);
    float* z1   = symaddr<float>(g_z1);
    __nv_bfloat16* pTb   = symaddr<__nv_bfloat16>(g_pTb);
    __nv_bfloat16* wInT  = symaddr<__nv_bfloat16>(g_wInT);
    __nv_bfloat16* wqkvT = symaddr<__nv_bfloat16>(g_wqkvT);
    __nv_bfloat16* woT   = symaddr<__nv_bfloat16>(g_woT);
    __nv_bfloat16* w1T   = symaddr<__nv_bfloat16>(g_w1T);
    __nv_bfloat16* w2T   = symaddr<__nv_bfloat16>(g_w2T);

    static bool attr_set = false;
    if (!attr_set) {
        cudaFuncSetAttribute(tgemm_kernel, cudaFuncAttributeMaxDynamicSharedMemorySize, TG_SMEM_BYTES);
        cudaFuncSetAttribute(btgemm_kernel, cudaFuncAttributeMaxDynamicSharedMemorySize, TG_SMEM_BYTES);
        cudaFuncSetAttribute(feat_kernel, cudaFuncAttributeMaxDynamicSharedMemorySize, FT_SMEM);
        attr_set = true;
    }

    dim3 blk256(256);
    dim3 t256(4, ROWS_TOT / 128);       // N=256
    dim3 t768(12, ROWS_TOT / 128);      // N=768 fused QKV (contiguous out)
    dim3 t1024(16, ROWS_TOT / 128);     // N=1024
    dim3 gCtx(5, 1, BH);
    dim3 gAtt(1, 3, BH);                // numerator only
    dim3 gKT(10, 10, BH);

    // ---- prep (4 transpose launches + f2b) ----
    f2b_kernel<<<(int)((ROWS_TOT * (size_t)IN_DIM + 255) / 256), 256>>>(x, xb, (size_t)ROWS_TOT * IN_DIM);
    wtrans_kernel<<<dim3(DIM / 32, IN_DIM / 32, 1), dim3(32, 8)>>>(w_in, wInT, IN_DIM, DIM, 0, 0);
    wtrans8_kernel<<<dim3(DIM / 32, DIM / 32, 8), dim3(32, 8)>>>(wq, wk, wv, wo, wqkvT, woT);
    wtrans_kernel<<<dim3(FFH / 32, DIM / 32, 2), dim3(32, 8)>>>(w1, w1T, DIM, FFH,
                                                                (size_t)DIM * FFH, (size_t)DIM * FFH);
    wtrans_kernel<<<dim3(DIM / 32, FFH / 32, 2), dim3(32, 8)>>>(w2, w2T, FFH, DIM,
                                                                (size_t)FFH * DIM, (size_t)FFH * DIM);

    tgemm_kernel<<<t256, blk256, TG_SMEM_BYTES>>>(xb, wInT, b_in, nullptr, h, nullptr,
                                                  ROWS_TOT, DIM, IN_DIM, 0);

    for (int l = 0; l < 2; l++) {
        // --- attention ---
        ln8_bf16_kernel<<<ROWS_TOT / 8, 256>>>(h, ln1_g + l * DIM, ln1_b + l * DIM, yb);
        tgemm_kernel<<<t768, blk256, TG_SMEM_BYTES>>>(yb, wqkvT + (size_t)l * 3 * DIM * DIM,
                                                      nullptr, nullptr, nullptr, qkvb,
                                                      ROWS_TOT, 768, DIM, 0);

        projb_kernel<<<(MP * 64 + 255) / 256, 256>>>(proj + (size_t)l * MF * DH, pTb);
        kmax_init_kernel<<<1, 1024>>>(kmx);
        feat_kernel<<<RH / 256, 256, FT_SMEM>>>(qkvb, 256, pTb, nullptr, kmx, 2);
        feat_kernel<<<RH / 256, 256, FT_SMEM>>>(qkvb, 0, pTb, qpB, nullptr, 0);
        feat_kernel<<<RH / 256, 256, FT_SMEM>>>(qkvb, 256, pTb, kpB, kmx, 1);
        ktrans_kernel<<<gKT, dim3(32, 8)>>>(kpB, kpT);
        vtrans_kernel<<<BH, 256>>>(qkvb + 512, vT);

        btgemm_kernel<<<gCtx, blk256, TG_SMEM_BYTES>>>(
            vT, (size_t)128 * NP, 127, kpT, (size_t)MP * NP,
            nullptr, ctxT, (size_t)128 * MP, MP, NP, 128, MP);
        btgemm_kernel<<<gAtt, blk256, TG_SMEM_BYTES>>>(
            qpB, (size_t)NN * MP, NN - 1, ctxT, (size_t)128 * MP,
            outA, nullptr, (size_t)NN * 64, 64, MP, NN, 64);

        divout_kernel<<<BH, 256>>>(outA, ctxT, qpB, ob);

        tgemm_kernel<<<t256, blk256, TG_SMEM_BYTES>>>(ob, woT + (size_t)l * DIM * DIM, bo + l * DIM, h,
                                                      h, nullptr, ROWS_TOT, DIM, DIM, 0);

        // --- FFN ---
        ln8_bf16_kernel<<<ROWS_TOT / 8, 256>>>(h, ln2_g + l * DIM, ln2_b + l * DIM, yb);
        tgemm_kernel<<<t1024, blk256, TG_SMEM_BYTES>>>(yb, w1T + (size_t)l * DIM * FFH, b1 + l * FFH, nullptr,
                                                       nullptr, ffhb, ROWS_TOT, FFH, DIM, 1);
        tgemm_kernel<<<t256, blk256, TG_SMEM_BYTES>>>(ffhb, w2T + (size_t)l * FFH * DIM, b2 + l * DIM, h,
                                                      h, nullptr, ROWS_TOT, DIM, FFH, 0);
    }

    pool_kernel<<<BB, 256>>>(h, pool);
    ln_f32_kernel<<<BB, 256>>>(pool, hln_g, hln_b, z);
    head1_kernel<<<BB, 128>>>(z, wh1, bh1, z1);
    head2_kernel<<<BB, 128>>>(z1, wh2, bh2, out);
}